// round 10
// baseline (speedup 1.0000x reference)
#include <cuda_runtime.h>
#include <cuda_bf16.h>
#include <cstdint>

// ---------------- problem constants ----------------
#define Bq      4
#define Sq      2048
#define Tq      (Bq * Sq)      // 8192 tokens
#define Dd      384
#define QKd     48
#define Ed      768
#define Hd      1632           // 2*QK + 2*E
#define NBq     8
#define VOCABq  100

// ---------------- scratch (static device globals; no cudaMalloc) -----------
__device__ float g_x[Tq * Dd];                        // residual stream
__device__ float g_xn[Tq * Dd];                       // final-LN output (fp32)
__device__ float g_h[(size_t)Tq * Hd];                // expand GEMM out (fp32)
__device__ float g_v[Tq * Dd];                        // V fp32 (pre-transpose)
__device__ float g_p[(size_t)Bq * Sq * Sq];           // raw scores fp32

#define AL16 __align__(16)
__device__ AL16 __nv_bfloat16 g_xnh[Tq * Dd],  g_xnl[Tq * Dd];
__device__ AL16 __nv_bfloat16 g_cath[(size_t)Tq * Ed], g_catl[(size_t)Tq * Ed];
__device__ AL16 __nv_bfloat16 g_vth[(size_t)Bq * Dd * Sq], g_vtl[(size_t)Bq * Dd * Sq];
__device__ AL16 __nv_bfloat16 g_ph[(size_t)Bq * Sq * Sq],  g_pl[(size_t)Bq * Sq * Sq];
__device__ AL16 __nv_bfloat16 g_qh[Tq * 64], g_ql[Tq * 64];   // qh padded K=64
__device__ AL16 __nv_bfloat16 g_kh[Tq * 64], g_kl[Tq * 64];   // kh padded K=64
__device__ AL16 __nv_bfloat16 g_ewh[NBq * Hd * Dd], g_ewl[NBq * Hd * Dd];
__device__ AL16 __nv_bfloat16 g_pwh[NBq * Dd * Ed], g_pwl[NBq * Dd * Ed];

// ================= low-level helpers =================
__device__ __forceinline__ uint32_t s2u(const void* p) {
    uint32_t a;
    asm("{ .reg .u64 t; cvta.to.shared.u64 t, %1; cvt.u32.u64 %0, t; }" : "=r"(a) : "l"(p));
    return a;
}
__device__ __forceinline__ void cpa16(uint32_t dst, const void* src, uint32_t sz) {
    asm volatile("cp.async.cg.shared.global [%0], [%1], 16, %2;"
                 :: "r"(dst), "l"(src), "r"(sz) : "memory");
}
__device__ __forceinline__ void cpa_commit() {
    asm volatile("cp.async.commit_group;" ::: "memory");
}
template <int NN>
__device__ __forceinline__ void cpa_wait() {
    asm volatile("cp.async.wait_group %0;" :: "n"(NN) : "memory");
}
__device__ __forceinline__ uint32_t swz(uint32_t off) { return off ^ ((off >> 3) & 0x70); }

__device__ __forceinline__ void ldm_x4(uint32_t addr, uint32_t* r) {
    asm volatile("ldmatrix.sync.aligned.m8n8.x4.shared.b16 {%0,%1,%2,%3}, [%4];"
                 : "=r"(r[0]), "=r"(r[1]), "=r"(r[2]), "=r"(r[3]) : "r"(addr));
}
__device__ __forceinline__ void mma16816(float* c, const uint32_t* a, const uint32_t* b) {
    asm volatile("mma.sync.aligned.m16n8k16.row.col.f32.bf16.bf16.f32 "
                 "{%0,%1,%2,%3}, {%4,%5,%6,%7}, {%8,%9}, {%0,%1,%2,%3};"
                 : "+f"(c[0]), "+f"(c[1]), "+f"(c[2]), "+f"(c[3])
                 : "r"(a[0]), "r"(a[1]), "r"(a[2]), "r"(a[3]), "r"(b[0]), "r"(b[1]));
}
__device__ __forceinline__ void split1(float v, __nv_bfloat16& h, __nv_bfloat16& l) {
    h = __float2bfloat16_rn(v);
    l = __float2bfloat16_rn(v - __bfloat162float(h));
}

// ================= bf16 HMMA GEMM: C = A(MxK) * B(NxK)^T, 3-term split =====
// Inputs pre-split (hi/lo bf16, K-contiguous). 128(M)x256(N) CTA tile, BK=64,
// 8 warps (2Mx4N, warp tile 64x64), cp.async 2-stage, reg accumulators.
// K multiple of 64 at all call sites. causal: 0=none, 1=skip upper tiles,
// 2=cap K at bm+128 (P@V). For causal!=0 the M-tile order is flipped so the
// largest-K CTAs launch first (wave balance).
// OUTM: 0 = fp32 store, 1 = fp32 add, 2 = bf16 hi/lo pair store.
#define ATILE   16384                   // 128 rows x 64 bf16 x 2B
#define BTILE   32768                   // 256 rows x 64 bf16 x 2B
#define STAGE_B (2 * ATILE + 2 * BTILE) // 96 KB
#define SHM_BF  (2 * STAGE_B + 128)

template <int OUTM>
__global__ void __launch_bounds__(256, 1)
gemm_bf(const __nv_bfloat16* __restrict__ Ah_, const __nv_bfloat16* __restrict__ Al_,
        int lda, long long sA,
        const __nv_bfloat16* __restrict__ Bh_, const __nv_bfloat16* __restrict__ Bl_,
        int ldb, long long sB,
        float* __restrict__ Cf,
        __nv_bfloat16* __restrict__ Ch, __nv_bfloat16* __restrict__ Cl,
        int ldc, long long sC, int N, int K, int causal) {
    int my = (causal != 0) ? (gridDim.y - 1 - blockIdx.y) : blockIdx.y;
    int bm = my * 128;
    int bn = blockIdx.x * 256;
    if (causal == 1 && bn >= bm + 128) return;
    int Keff = (causal == 2) ? ((bm + 128 < K) ? bm + 128 : K) : K;
    int nch = Keff >> 6;

    const __nv_bfloat16* Ah = Ah_ + (long long)blockIdx.z * sA;
    const __nv_bfloat16* Al = Al_ + (long long)blockIdx.z * sA;
    const __nv_bfloat16* Bh = Bh_ + (long long)blockIdx.z * sB;
    const __nv_bfloat16* Bl = Bl_ + (long long)blockIdx.z * sB;

    extern __shared__ char dsm[];
    uint32_t base = (s2u(dsm) + 127u) & ~127u;

    int tid = threadIdx.x;
    int wid = tid >> 5, lane = tid & 31;
    int m0w = (wid >> 2) * 64;      // 2 warps in M
    int n0w = (wid & 3) * 64;       // 4 warps in N

    float acc[4][8][4];
#pragma unroll
    for (int i = 0; i < 4; i++)
#pragma unroll
        for (int j = 0; j < 8; j++)
#pragma unroll
            for (int e = 0; e < 4; e++) acc[i][j][e] = 0.0f;

    uint32_t a_row  = (uint32_t)(lane & 15);
    uint32_t a_colb = (uint32_t)((lane >> 4) * 16);
    uint32_t b_row  = (uint32_t)(((lane >> 4) << 3) + (lane & 7));
    uint32_t b_colb = (uint32_t)(((lane >> 3) & 1) * 16);

    auto load_chunk = [&](int ch, int bsel) {
        int k0 = ch << 6;
        uint32_t tb = base + (uint32_t)bsel * STAGE_B;
        // A: 1024 16B-units (hi + lo), 4 per thread each
#pragma unroll
        for (int i = 0; i < 4; i++) {
            int uid = tid + i * 256;
            int row = uid >> 3, u = uid & 7;
            uint32_t soff = swz((uint32_t)row * 128u + (uint32_t)u * 16u);
            size_t aoff = (size_t)(bm + row) * lda + k0 + u * 8;
            cpa16(tb + soff,         Ah + aoff, 16u);
            cpa16(tb + ATILE + soff, Al + aoff, 16u);
        }
        // B: 2048 16B-units (hi + lo), 8 per thread each
        uint32_t tBh = tb + 2 * ATILE, tBl = tBh + BTILE;
#pragma unroll
        for (int i = 0; i < 8; i++) {
            int uid = tid + i * 256;
            int row = uid >> 3, u = uid & 7;
            uint32_t soff = swz((uint32_t)row * 128u + (uint32_t)u * 16u);
            uint32_t bsz = ((bn + row) < N) ? 16u : 0u;
            size_t boff = (size_t)(bn + row) * ldb + k0 + u * 8;
            cpa16(tBh + soff, Bh + boff, bsz);
            cpa16(tBl + soff, Bl + boff, bsz);
        }
    };

    auto compute = [&](int bsel) {
        uint32_t tb  = base + (uint32_t)bsel * STAGE_B;
        uint32_t tAh = tb, tAl = tb + ATILE;
        uint32_t tBh = tb + 2 * ATILE, tBl = tBh + BTILE;
#pragma unroll
        for (int ks = 0; ks < 4; ks++) {
            uint32_t kbyte = (uint32_t)ks * 32u;
            uint32_t afrag[4][4], bhfrag[4][4], blfrag[4][4];
#pragma unroll
            for (int mt = 0; mt < 4; mt++) {
                uint32_t rr = (uint32_t)(m0w + mt * 16) + a_row;
                ldm_x4(tAh + swz(rr * 128u + kbyte + a_colb), afrag[mt]);
            }
#pragma unroll
            for (int bt = 0; bt < 4; bt++) {
                uint32_t rr = (uint32_t)(n0w + bt * 16) + b_row;
                uint32_t off = swz(rr * 128u + kbyte + b_colb);
                ldm_x4(tBh + off, bhfrag[bt]);
                ldm_x4(tBl + off, blfrag[bt]);
            }
            // term 1: Ahi*Bhi
#pragma unroll
            for (int mt = 0; mt < 4; mt++)
#pragma unroll
                for (int nt = 0; nt < 8; nt++)
                    mma16816(acc[mt][nt], afrag[mt], &bhfrag[nt >> 1][(nt & 1) * 2]);
            // term 2: Ahi*Blo
#pragma unroll
            for (int mt = 0; mt < 4; mt++)
#pragma unroll
                for (int nt = 0; nt < 8; nt++)
                    mma16816(acc[mt][nt], afrag[mt], &blfrag[nt >> 1][(nt & 1) * 2]);
            // term 3: Alo*Bhi (reload A frags as lo)
#pragma unroll
            for (int mt = 0; mt < 4; mt++) {
                uint32_t rr = (uint32_t)(m0w + mt * 16) + a_row;
                ldm_x4(tAl + swz(rr * 128u + kbyte + a_colb), afrag[mt]);
            }
#pragma unroll
            for (int mt = 0; mt < 4; mt++)
#pragma unroll
                for (int nt = 0; nt < 8; nt++)
                    mma16816(acc[mt][nt], afrag[mt], &bhfrag[nt >> 1][(nt & 1) * 2]);
        }
    };

    load_chunk(0, 0);
    cpa_commit();
    for (int ch = 0; ch < nch; ch++) {
        if (ch + 1 < nch) {
            load_chunk(ch + 1, (ch + 1) & 1);
            cpa_commit();
            cpa_wait<1>();
        } else {
            cpa_wait<0>();
        }
        __syncthreads();
        compute(ch & 1);
        __syncthreads();
    }

    // ---------------- epilogue ----------------
    float* CfB = (OUTM != 2) ? Cf + (long long)blockIdx.z * sC : nullptr;
    __nv_bfloat16* ChB = (OUTM == 2) ? Ch + (long long)blockIdx.z * sC : nullptr;
    __nv_bfloat16* ClB = (OUTM == 2) ? Cl + (long long)blockIdx.z * sC : nullptr;
#pragma unroll
    for (int mt = 0; mt < 4; mt++) {
        int row0 = bm + m0w + mt * 16 + (lane >> 2);
#pragma unroll
        for (int nt = 0; nt < 8; nt++) {
            int col = bn + n0w + nt * 8 + (lane & 3) * 2;
            float* c = acc[mt][nt];
#pragma unroll
            for (int half = 0; half < 2; half++) {
                int row = row0 + half * 8;
                float v0 = c[half * 2], v1 = c[half * 2 + 1];
                if (OUTM == 2) {
                    if (col + 1 < N) {
                        __nv_bfloat16 h0, l0, h1, l1;
                        split1(v0, h0, l0); split1(v1, h1, l1);
                        __nv_bfloat162 hv; hv.x = h0; hv.y = h1;
                        __nv_bfloat162 lv; lv.x = l0; lv.y = l1;
                        *reinterpret_cast<__nv_bfloat162*>(ChB + (size_t)row * ldc + col) = hv;
                        *reinterpret_cast<__nv_bfloat162*>(ClB + (size_t)row * ldc + col) = lv;
                    }
                } else {
                    float* Crow = CfB + (size_t)row * ldc;
                    if (col + 1 < N) {
                        float2 cv;
                        if (OUTM == 1) {
                            cv = *reinterpret_cast<float2*>(Crow + col);
                            cv.x += v0; cv.y += v1;
                        } else cv = make_float2(v0, v1);
                        *reinterpret_cast<float2*>(Crow + col) = cv;
                    } else if (col < N) {
                        Crow[col] = (OUTM == 1) ? (Crow[col] + v0) : v0;
                    }
                }
            }
        }
    }
}

template <int OUTM>
static inline void gemm_bf_launch(const __nv_bfloat16* Ah, const __nv_bfloat16* Al,
                                  int lda, long long sA,
                                  const __nv_bfloat16* Bh, const __nv_bfloat16* Bl,
                                  int ldb, long long sB,
                                  float* Cf, __nv_bfloat16* Ch, __nv_bfloat16* Cl,
                                  int ldc, long long sC,
                                  int M, int N, int K, int batch, int causal) {
    dim3 grid((N + 255) / 256, M / 128, batch);
    cudaFuncSetAttribute(gemm_bf<OUTM>, cudaFuncAttributeMaxDynamicSharedMemorySize, SHM_BF);
    gemm_bf<OUTM><<<grid, 256, SHM_BF>>>(Ah, Al, lda, sA, Bh, Bl, ldb, sB,
                                         Cf, Ch, Cl, ldc, sC, N, K, causal);
}

// ---------------- reductions ----------------
__device__ __forceinline__ float warp_sum(float v) {
#pragma unroll
    for (int o = 16; o; o >>= 1) v += __shfl_xor_sync(0xffffffffu, v, o);
    return v;
}
__device__ __forceinline__ float warp_max(float v) {
#pragma unroll
    for (int o = 16; o; o >>= 1) v = fmaxf(v, __shfl_xor_sync(0xffffffffu, v, o));
    return v;
}

// ---------------- weight split: fp32 -> bf16 hi/lo ----------------
__global__ void split_w_kernel(const float4* __restrict__ src,
                               __nv_bfloat162* __restrict__ h2,
                               __nv_bfloat162* __restrict__ l2, int n4) {
    int i = blockIdx.x * 256 + threadIdx.x;
    if (i >= n4) return;
    float4 x = src[i];
    __nv_bfloat162 ha = __floats2bfloat162_rn(x.x, x.y);
    __nv_bfloat162 hb = __floats2bfloat162_rn(x.z, x.w);
    __nv_bfloat162 la = __floats2bfloat162_rn(x.x - __bfloat162float(ha.x),
                                              x.y - __bfloat162float(ha.y));
    __nv_bfloat162 lb = __floats2bfloat162_rn(x.z - __bfloat162float(hb.x),
                                              x.w - __bfloat162float(hb.y));
    h2[2 * i] = ha; h2[2 * i + 1] = hb;
    l2[2 * i] = la; l2[2 * i + 1] = lb;
}

// ---------------- embed (sin/cos) + LayerNorm (fp32 out) ----------------
__global__ void embed_ln_kernel(const int* __restrict__ q,
                                const float* __restrict__ freqs,
                                const float* __restrict__ g,
                                const float* __restrict__ b,
                                float* __restrict__ y) {
    int t = blockIdx.x;
    int tid = threadIdx.x;
    float qv = (float)q[t];
    float v[3];
#pragma unroll
    for (int k = 0; k < 3; k++) {
        int d = tid + k * 128;
        if (d < Dd / 2) v[k] = sinf(qv * freqs[d]);
        else            v[k] = cosf(qv * freqs[d - Dd / 2]);
    }
    float s = v[0] + v[1] + v[2];
    float sq = v[0]*v[0] + v[1]*v[1] + v[2]*v[2];
    s = warp_sum(s); sq = warp_sum(sq);
    __shared__ float shs[4], shq[4], mr[2];
    if ((tid & 31) == 0) { shs[tid >> 5] = s; shq[tid >> 5] = sq; }
    __syncthreads();
    if (tid == 0) {
        float ts = shs[0]+shs[1]+shs[2]+shs[3], tq = shq[0]+shq[1]+shq[2]+shq[3];
        float mean = ts * (1.0f / Dd);
        float var  = tq * (1.0f / Dd) - mean * mean;
        mr[0] = mean; mr[1] = rsqrtf(var + 1e-5f);
    }
    __syncthreads();
    float mean = mr[0], rstd = mr[1];
    float* yr = y + (size_t)t * Dd;
#pragma unroll
    for (int k = 0; k < 3; k++) {
        int d = tid + k * 128;
        yr[d] = (v[k] - mean) * rstd * g[d] + b[d];
    }
}

// ---------------- LayerNorm, fp32 out (final LN) ----------------
__global__ void ln_kernel(const float* __restrict__ x, float* __restrict__ y,
                          const float* __restrict__ g, const float* __restrict__ b) {
    int t = blockIdx.x;
    int tid = threadIdx.x;
    const float* xr = x + (size_t)t * Dd;
    float v0 = xr[tid], v1 = xr[tid + 128], v2 = xr[tid + 256];
    float s  = v0 + v1 + v2;
    float sq = v0*v0 + v1*v1 + v2*v2;
    s = warp_sum(s); sq = warp_sum(sq);
    __shared__ float shs[4], shq[4], mr[2];
    if ((tid & 31) == 0) { shs[tid >> 5] = s; shq[tid >> 5] = sq; }
    __syncthreads();
    if (tid == 0) {
        float ts = shs[0]+shs[1]+shs[2]+shs[3], tq = shq[0]+shq[1]+shq[2]+shq[3];
        float mean = ts * (1.0f / Dd);
        float var  = tq * (1.0f / Dd) - mean * mean;
        mr[0] = mean; mr[1] = rsqrtf(var + 1e-5f);
    }
    __syncthreads();
    float mean = mr[0], rstd = mr[1];
    float* yr = y + (size_t)t * Dd;
    yr[tid]       = (v0 - mean) * rstd * g[tid]       + b[tid];
    yr[tid + 128] = (v1 - mean) * rstd * g[tid + 128] + b[tid + 128];
    yr[tid + 256] = (v2 - mean) * rstd * g[tid + 256] + b[tid + 256];
}

// ---------------- LayerNorm, bf16 hi/lo out (per-block LN) ----------------
__global__ void ln_bf16_kernel(const float* __restrict__ x,
                               __nv_bfloat16* __restrict__ yh,
                               __nv_bfloat16* __restrict__ yl,
                               const float* __restrict__ g,
                               const float* __restrict__ b) {
    int t = blockIdx.x;
    int tid = threadIdx.x;
    const float* xr = x + (size_t)t * Dd;
    float v0 = xr[tid], v1 = xr[tid + 128], v2 = xr[tid + 256];
    float s  = v0 + v1 + v2;
    float sq = v0*v0 + v1*v1 + v2*v2;
    s = warp_sum(s); sq = warp_sum(sq);
    __shared__ float shs[4], shq[4], mr[2];
    if ((tid & 31) == 0) { shs[tid >> 5] = s; shq[tid >> 5] = sq; }
    __syncthreads();
    if (tid == 0) {
        float ts = shs[0]+shs[1]+shs[2]+shs[3], tq = shq[0]+shq[1]+shq[2]+shq[3];
        float mean = ts * (1.0f / Dd);
        float var  = tq * (1.0f / Dd) - mean * mean;
        mr[0] = mean; mr[1] = rsqrtf(var + 1e-5f);
    }
    __syncthreads();
    float mean = mr[0], rstd = mr[1];
    size_t rb = (size_t)t * Dd;
#pragma unroll
    for (int k = 0; k < 3; k++) {
        int d = tid + k * 128;
        float vv = (k == 0 ? v0 : (k == 1 ? v1 : v2));
        float y = (vv - mean) * rstd * g[d] + b[d];
        __nv_bfloat16 hh, ll;
        split1(y, hh, ll);
        yh[rb + d] = hh; yl[rb + d] = ll;
    }
}

// ---------------- fused geglu + qk split ----------------
// 256 threads: tid<192 -> geglu (loc->cat hi/lo, val->V fp32);
// tid>=192 -> qh/kh split padded to K=64.
__global__ void geglu_qk_kernel(const float* __restrict__ h,
                                __nv_bfloat16* __restrict__ cath,
                                __nv_bfloat16* __restrict__ catl,
                                float* __restrict__ v,
                                __nv_bfloat16* __restrict__ qh, __nv_bfloat16* __restrict__ ql,
                                __nv_bfloat16* __restrict__ kh, __nv_bfloat16* __restrict__ kl) {
    int t = blockIdx.x;
    int tid = threadIdx.x;
    const float* hr = h + (size_t)t * Hd;
    if (tid < 192) {
        int j4 = tid;
        float4 lin = *reinterpret_cast<const float4*>(hr + 2 * QKd + j4 * 4);
        float4 pg  = *reinterpret_cast<const float4*>(hr + 2 * QKd + Ed + j4 * 4);
        float4 r;
        r.x = lin.x * 0.5f * pg.x * (1.0f + erff(pg.x * 0.70710678118654752f));
        r.y = lin.y * 0.5f * pg.y * (1.0f + erff(pg.y * 0.70710678118654752f));
        r.z = lin.z * 0.5f * pg.z * (1.0f + erff(pg.z * 0.70710678118654752f));
        r.w = lin.w * 0.5f * pg.w * (1.0f + erff(pg.w * 0.70710678118654752f));
        if (j4 < 96) {
            __nv_bfloat162 ha = __floats2bfloat162_rn(r.x, r.y);
            __nv_bfloat162 hb = __floats2bfloat162_rn(r.z, r.w);
            __nv_bfloat162 la = __floats2bfloat162_rn(r.x - __bfloat162float(ha.x),
                                                      r.y - __bfloat162float(ha.y));
            __nv_bfloat162 lb = __floats2bfloat162_rn(r.z - __bfloat162float(hb.x),
                                                      r.w - __bfloat162float(hb.y));
            __nv_bfloat162* ch = reinterpret_cast<__nv_bfloat162*>(cath + (size_t)t * Ed + j4 * 4);
            __nv_bfloat162* cl = reinterpret_cast<__nv_bfloat162*>(catl + (size_t)t * Ed + j4 * 4);
            ch[0] = ha; ch[1] = hb; cl[0] = la; cl[1] = lb;
        } else {
            *reinterpret_cast<float4*>(v + (size_t)t * Dd + (j4 - 96) * 4) = r;
        }
    } else {
        int u = tid - 192;          // 0..63
        int which = u >> 5;         // 0: q, 1: k
        int d0 = (u & 31) * 2;      // 0..62
        float a = (d0     < QKd) ? hr[which * QKd + d0]     : 0.0f;
        float b = (d0 + 1 < QKd) ? hr[which * QKd + d0 + 1] : 0.0f;
        __nv_bfloat162 hv = __floats2bfloat162_rn(a, b);
        __nv_bfloat162 lv = __floats2bfloat162_rn(a - __bfloat162float(hv.x),
                                                  b - __bfloat162float(hv.y));
        size_t idx = (size_t)t * 64 + d0;
        if (which == 0) {
            *reinterpret_cast<__nv_bfloat162*>(qh + idx) = hv;
            *reinterpret_cast<__nv_bfloat162*>(ql + idx) = lv;
        } else {
            *reinterpret_cast<__nv_bfloat162*>(kh + idx) = hv;
            *reinterpret_cast<__nv_bfloat162*>(kl + idx) = lv;
        }
    }
}

// ---------------- V transpose: fp32 [Sq x Dd] -> bf16 hi/lo [Dd x Sq] ------
__global__ void transpose_v(const float* __restrict__ v,
                            __nv_bfloat16* __restrict__ vth,
                            __nv_bfloat16* __restrict__ vtl) {
    __shared__ float tile[32][33];
    int b = blockIdx.z;
    int s0 = blockIdx.x * 32, d0 = blockIdx.y * 32;
    int x = threadIdx.x, y = threadIdx.y;
    const float* src = v + (size_t)b * Sq * Dd;
    size_t dstb = (size_t)b * Dd * Sq;
#pragma unroll
    for (int i = 0; i < 32; i += 8)
        tile[y + i][x] = src[(size_t)(s0 + y + i) * Dd + d0 + x];
    __syncthreads();
#pragma unroll
    for (int i = 0; i < 32; i += 8) {
        float val = tile[x][y + i];
        __nv_bfloat16 hh, ll;
        split1(val, hh, ll);
        size_t idx = dstb + (size_t)(d0 + y + i) * Sq + s0 + x;
        vth[idx] = hh; vtl[idx] = ll;
    }
}

// ---------------- causal softmax: fp32 scores -> bf16 hi/lo probs ----------
__global__ void softmax_kernel(const float* __restrict__ p,
                               __nv_bfloat16* __restrict__ ph,
                               __nv_bfloat16* __restrict__ pl) {
    int i = blockIdx.x;
    int b = blockIdx.y;
    size_t off = ((size_t)b * Sq + i) * Sq;
    const float* row = p + off;
    int L = i + 1;
    int zend = ((i >> 7) + 1) << 7;
    int tid = threadIdx.x;   // 256
    const float scale = 0.14433756729740643f;
    __shared__ float sh[8];

    float m = -3.0e38f;
    float rv[8];
#pragma unroll
    for (int k = 0; k < 8; k++) {
        int j = tid + k * 256;
        rv[k] = (j < L) ? row[j] : -3.0e38f;
        m = fmaxf(m, rv[k]);
    }
    m = warp_max(m);
    if ((tid & 31) == 0) sh[tid >> 5] = m;
    __syncthreads();
    float mm = sh[0];
#pragma unroll
    for (int k = 1; k < 8; k++) mm = fmaxf(mm, sh[k]);
    __syncthreads();

    float sum = 0.0f;
#pragma unroll
    for (int k = 0; k < 8; k++) {
        int j = tid + k * 256;
        if (j < L) { rv[k] = __expf((rv[k] - mm) * scale); sum += rv[k]; }
    }
    sum = warp_sum(sum);
    if ((tid & 31) == 0) sh[tid >> 5] = sum;
    __syncthreads();
    float tot = sh[0];
#pragma unroll
    for (int k = 1; k < 8; k++) tot += sh[k];
    float inv = 1.0f / tot;

#pragma unroll
    for (int k = 0; k < 8; k++) {
        int j = tid + k * 256;
        if (j < zend) {
            float e = (j < L) ? rv[k] * inv : 0.0f;
            __nv_bfloat16 hh, ll;
            split1(e, hh, ll);
            ph[off + j] = hh; pl[off + j] = ll;
        }
    }
}

// ---------------- SIMT SGEMM (logits only): C = A(MxK) * B(NxK)^T ----------
__global__ void __launch_bounds__(256, 2)
gemm_simt(const float* __restrict__ A, int lda,
          const float* __restrict__ B, int ldb,
          float* __restrict__ C, int ldc, int N, int K) {
    int bm = blockIdx.y * 128;
    int bn = blockIdx.x * 128;

    __shared__ float As[8][128];
    __shared__ float Bs[8][128];
    int tid = threadIdx.x;
    int tx = tid & 15, ty = tid >> 4;
    float acc[8][8] = {};

    int lrow = tid >> 1;
    int lkk  = (tid & 1) * 4;
    const float* Ap = A + (size_t)(bm + lrow) * lda + lkk;
    bool bvalid = (bn + lrow) < N;
    const float* Bp = B + (size_t)(bn + lrow) * ldb + lkk;

    for (int k0 = 0; k0 < K; k0 += 8) {
        float4 av = *reinterpret_cast<const float4*>(Ap + k0);
        float4 bv = bvalid ? *reinterpret_cast<const float4*>(Bp + k0)
                           : make_float4(0.f, 0.f, 0.f, 0.f);
        As[lkk+0][lrow]=av.x; As[lkk+1][lrow]=av.y; As[lkk+2][lrow]=av.z; As[lkk+3][lrow]=av.w;
        Bs[lkk+0][lrow]=bv.x; Bs[lkk+1][lrow]=bv.y; Bs[lkk+2][lrow]=bv.z; Bs[lkk+3][lrow]=bv.w;
        __syncthreads();
#pragma unroll
        for (int kk = 0; kk < 8; kk++) {
            float a[8], b[8];
            *reinterpret_cast<float4*>(&a[0]) = *reinterpret_cast<const float4*>(&As[kk][ty*8]);
            *reinterpret_cast<float4*>(&a[4]) = *reinterpret_cast<const float4*>(&As[kk][ty*8+4]);
            *reinterpret_cast<float4*>(&b[0]) = *reinterpret_cast<const float4*>(&Bs[kk][tx*8]);
            *reinterpret_cast<float4*>(&b[4]) = *reinterpret_cast<const float4*>(&Bs[kk][tx*8+4]);
#pragma unroll
            for (int i = 0; i < 8; i++)
#pragma unroll
                for (int j = 0; j < 8; j++)
                    acc[i][j] += a[i] * b[j];
        }
        __syncthreads();
    }
#pragma unroll
    for (int i = 0; i < 8; i++) {
        float* Crow = C + (size_t)(bm + ty * 8 + i) * ldc;
#pragma unroll
        for (int j = 0; j < 8; j++) {
            int n = bn + tx * 8 + j;
            if (n < N) Crow[n] = acc[i][j];
        }
    }
}

// ---------------- driver ----------------
extern "C" void kernel_launch(void* const* d_in, const int* in_sizes, int n_in,
                              void* d_out, int out_size) {
    const int*   q      = (const int*)  d_in[0];
    const float* freqs  = (const float*)d_in[1];
    const float* exp_w  = (const float*)d_in[2];   // (8, 1632, 384)
    const float* proj_w = (const float*)d_in[3];   // (8, 384, 768)
    const float* blk_g  = (const float*)d_in[4];
    const float* blk_b  = (const float*)d_in[5];
    const float* ln_g   = (const float*)d_in[6];
    const float* ln_b   = (const float*)d_in[7];
    const float* out_w  = (const float*)d_in[8];   // (100, 384)
    float* out = (float*)d_out;

    float *x, *xn, *h, *v, *p;
    __nv_bfloat16 *xnh, *xnl, *cath, *catl, *vth, *vtl, *ph, *pl;
    __nv_bfloat16 *qh, *ql, *kh, *kl, *ewh, *ewl, *pwh, *pwl;
    cudaGetSymbolAddress((void**)&x,    g_x);
    cudaGetSymbolAddress((void**)&xn,   g_xn);
    cudaGetSymbolAddress((void**)&h,    g_h);
    cudaGetSymbolAddress((void**)&v,    g_v);
    cudaGetSymbolAddress((void**)&p,    g_p);
    cudaGetSymbolAddress((void**)&xnh,  g_xnh);  cudaGetSymbolAddress((void**)&xnl,  g_xnl);
    cudaGetSymbolAddress((void**)&cath, g_cath); cudaGetSymbolAddress((void**)&catl, g_catl);
    cudaGetSymbolAddress((void**)&vth,  g_vth);  cudaGetSymbolAddress((void**)&vtl,  g_vtl);
    cudaGetSymbolAddress((void**)&ph,   g_ph);   cudaGetSymbolAddress((void**)&pl,   g_pl);
    cudaGetSymbolAddress((void**)&qh,   g_qh);   cudaGetSymbolAddress((void**)&ql,   g_ql);
    cudaGetSymbolAddress((void**)&kh,   g_kh);   cudaGetSymbolAddress((void**)&kl,   g_kl);
    cudaGetSymbolAddress((void**)&ewh,  g_ewh);  cudaGetSymbolAddress((void**)&ewl,  g_ewl);
    cudaGetSymbolAddress((void**)&pwh,  g_pwh);  cudaGetSymbolAddress((void**)&pwl,  g_pwl);

    // pre-split weights (once per launch)
    {
        int n4e = NBq * Hd * Dd / 4;
        int n4p = NBq * Dd * Ed / 4;
        split_w_kernel<<<(n4e + 255) / 256, 256>>>(
            (const float4*)exp_w, (__nv_bfloat162*)ewh, (__nv_bfloat162*)ewl, n4e);
        split_w_kernel<<<(n4p + 255) / 256, 256>>>(
            (const float4*)proj_w, (__nv_bfloat162*)pwh, (__nv_bfloat162*)pwl, n4p);
    }

    embed_ln_kernel<<<Tq, 128>>>(q, freqs, ln_g, ln_b, x);

    for (int blk = 0; blk < NBq; blk++) {
        ln_bf16_kernel<<<Tq, 128>>>(x, xnh, xnl, blk_g + blk * Dd, blk_b + blk * Dd);

        // h = xn @ exp_w[blk]^T   (8192 x 1632, K=384) -> fp32
        gemm_bf_launch<0>(xnh, xnl, Dd, 0,
                          ewh + (size_t)blk * Hd * Dd, ewl + (size_t)blk * Hd * Dd, Dd, 0,
                          h, nullptr, nullptr, Hd, 0,
                          Tq, Hd, Dd, 1, 0);

        geglu_qk_kernel<<<Tq, 256>>>(h, cath, catl, v, qh, ql, kh, kl);

        // scores: qh @ kh^T per batch (K padded to 64), causal tile-skip
        gemm_bf_launch<0>(qh, ql, 64, (long long)Sq * 64,
                          kh, kl, 64, (long long)Sq * 64,
                          p, nullptr, nullptr, Sq, (long long)Sq * Sq,
                          Sq, Sq, 64, Bq, 1);

        softmax_kernel<<<dim3(Sq, Bq), 256>>>(p, ph, pl);

        transpose_v<<<dim3(Sq / 32, Dd / 32, Bq), dim3(32, 8)>>>(v, vth, vtl);

        // attn = P @ V -> cat[:, 384:768] as bf16 hi/lo; K capped causally
        gemm_bf_launch<2>(ph, pl, Sq, (long long)Sq * Sq,
                          vth, vtl, Sq, (long long)Dd * Sq,
                          nullptr, cath + Dd, catl + Dd, Ed, (long long)Sq * Ed,
                          Sq, Dd, Sq, Bq, 2);

        // x += cat @ proj_w[blk]^T
        gemm_bf_launch<1>(cath, catl, Ed, 0,
                          pwh + (size_t)blk * Dd * Ed, pwl + (size_t)blk * Dd * Ed, Ed, 0,
                          x, nullptr, nullptr, Dd, 0,
                          Tq, Dd, Ed, 1, 0);
    }

    ln_kernel<<<Tq, 128>>>(x, xn, ln_g, ln_b);
    gemm_simt<<<dim3(1, Tq / 128), 256>>>(xn, Dd, out_w, Dd, out, VOCABq, VOCABq, Dd);
}

// round 11
// speedup vs baseline: 1.2387x; 1.2387x over previous
#include <cuda_runtime.h>
#include <cuda_bf16.h>
#include <cstdint>

// ---------------- problem constants ----------------
#define Bq      4
#define Sq      2048
#define Tq      (Bq * Sq)      // 8192 tokens
#define Dd      384
#define QKd     48
#define Ed      768
#define Hd      1632           // 2*QK + 2*E
#define NBq     8
#define VOCABq  100

// ---------------- scratch (static device globals; no cudaMalloc) -----------
__device__ float g_x[Tq * Dd];                        // residual stream
__device__ float g_xn[Tq * Dd];                       // final-LN output (fp32)
__device__ float g_h[(size_t)Tq * Hd];                // expand GEMM out (fp32)
__device__ float g_v[Tq * Dd];                        // V fp32 (pre-transpose)
__device__ float g_p[(size_t)Bq * Sq * Sq];           // raw scores fp32

#define AL16 __align__(16)
__device__ AL16 __nv_bfloat16 g_xnh[Tq * Dd],  g_xnl[Tq * Dd];
__device__ AL16 __nv_bfloat16 g_cath[(size_t)Tq * Ed], g_catl[(size_t)Tq * Ed];
__device__ AL16 __nv_bfloat16 g_vth[(size_t)Bq * Dd * Sq], g_vtl[(size_t)Bq * Dd * Sq];
__device__ AL16 __nv_bfloat16 g_ph[(size_t)Bq * Sq * Sq],  g_pl[(size_t)Bq * Sq * Sq];
__device__ AL16 __nv_bfloat16 g_qh[Tq * 64], g_ql[Tq * 64];   // qh padded K=64
__device__ AL16 __nv_bfloat16 g_kh[Tq * 64], g_kl[Tq * 64];   // kh padded K=64
__device__ AL16 __nv_bfloat16 g_ewh[NBq * Hd * Dd], g_ewl[NBq * Hd * Dd];
__device__ AL16 __nv_bfloat16 g_pwh[NBq * Dd * Ed], g_pwl[NBq * Dd * Ed];

// ================= low-level helpers =================
__device__ __forceinline__ uint32_t s2u(const void* p) {
    uint32_t a;
    asm("{ .reg .u64 t; cvta.to.shared.u64 t, %1; cvt.u32.u64 %0, t; }" : "=r"(a) : "l"(p));
    return a;
}
__device__ __forceinline__ void cpa16(uint32_t dst, const void* src, uint32_t sz) {
    asm volatile("cp.async.cg.shared.global [%0], [%1], 16, %2;"
                 :: "r"(dst), "l"(src), "r"(sz) : "memory");
}
__device__ __forceinline__ void cpa_commit() {
    asm volatile("cp.async.commit_group;" ::: "memory");
}
template <int NN>
__device__ __forceinline__ void cpa_wait() {
    asm volatile("cp.async.wait_group %0;" :: "n"(NN) : "memory");
}
__device__ __forceinline__ uint32_t swz(uint32_t off) { return off ^ ((off >> 3) & 0x70); }

__device__ __forceinline__ void ldm_x4(uint32_t addr, uint32_t* r) {
    asm volatile("ldmatrix.sync.aligned.m8n8.x4.shared.b16 {%0,%1,%2,%3}, [%4];"
                 : "=r"(r[0]), "=r"(r[1]), "=r"(r[2]), "=r"(r[3]) : "r"(addr));
}
__device__ __forceinline__ void mma16816(float* c, const uint32_t* a, const uint32_t* b) {
    asm volatile("mma.sync.aligned.m16n8k16.row.col.f32.bf16.bf16.f32 "
                 "{%0,%1,%2,%3}, {%4,%5,%6,%7}, {%8,%9}, {%0,%1,%2,%3};"
                 : "+f"(c[0]), "+f"(c[1]), "+f"(c[2]), "+f"(c[3])
                 : "r"(a[0]), "r"(a[1]), "r"(a[2]), "r"(a[3]), "r"(b[0]), "r"(b[1]));
}
__device__ __forceinline__ void split1(float v, __nv_bfloat16& h, __nv_bfloat16& l) {
    h = __float2bfloat16_rn(v);
    l = __float2bfloat16_rn(v - __bfloat162float(h));
}

// ================= bf16 HMMA GEMM: C = A(MxK) * B(NxK)^T, 3-term split =====
// Inputs pre-split (hi/lo bf16, K-contiguous). 128x128 CTA tile, BK=64,
// 8 warps (2Mx4N, warp tile 64x32), cp.async 3-stage pipeline, reg acc.
// K multiple of 64 at all call sites. causal: 0=none, 1=skip bn>bm,
// 2=cap K at bm+128 (P@V). For causal!=0 the M-tile order is flipped so the
// largest-K CTAs launch first (wave balance).
// OUTM: 0 = fp32 store, 1 = fp32 add, 2 = bf16 hi/lo pair store.
#define BTILE   16384                   // 128 rows x 64 bf16 x 2B
#define STAGE_B (4 * BTILE)             // Ah, Al, Bh, Bl = 64 KB
#define NSTAGE  3
#define SHM_BF  (NSTAGE * STAGE_B + 128)

template <int OUTM>
__global__ void __launch_bounds__(256, 1)
gemm_bf(const __nv_bfloat16* __restrict__ Ah_, const __nv_bfloat16* __restrict__ Al_,
        int lda, long long sA,
        const __nv_bfloat16* __restrict__ Bh_, const __nv_bfloat16* __restrict__ Bl_,
        int ldb, long long sB,
        float* __restrict__ Cf,
        __nv_bfloat16* __restrict__ Ch, __nv_bfloat16* __restrict__ Cl,
        int ldc, long long sC, int N, int K, int causal) {
    int my = (causal != 0) ? ((int)gridDim.y - 1 - (int)blockIdx.y) : (int)blockIdx.y;
    int bm = my * 128;
    int bn = blockIdx.x * 128;
    if (causal == 1 && bn > bm) return;
    int Keff = (causal == 2) ? ((bm + 128 < K) ? bm + 128 : K) : K;
    int nch = Keff >> 6;

    const __nv_bfloat16* Ah = Ah_ + (long long)blockIdx.z * sA;
    const __nv_bfloat16* Al = Al_ + (long long)blockIdx.z * sA;
    const __nv_bfloat16* Bh = Bh_ + (long long)blockIdx.z * sB;
    const __nv_bfloat16* Bl = Bl_ + (long long)blockIdx.z * sB;

    extern __shared__ char dsm[];
    uint32_t base = (s2u(dsm) + 127u) & ~127u;

    int tid = threadIdx.x;
    int wid = tid >> 5, lane = tid & 31;
    int m0w = (wid >> 2) * 64;      // 2 warps in M
    int n0w = (wid & 3) * 32;       // 4 warps in N

    // loader lanes: 1024 16B-units per tile; thread covers rows lrow+{0,32,64,96}
    int lrow = tid >> 3;       // 0..31
    int lu   = tid & 7;        // 0..7

    float acc[4][4][4];
#pragma unroll
    for (int i = 0; i < 4; i++)
#pragma unroll
        for (int j = 0; j < 4; j++)
#pragma unroll
            for (int e = 0; e < 4; e++) acc[i][j][e] = 0.0f;

    uint32_t a_row  = (uint32_t)(lane & 15);
    uint32_t a_colb = (uint32_t)((lane >> 4) * 16);
    uint32_t b_row  = (uint32_t)(((lane >> 4) << 3) + (lane & 7));
    uint32_t b_colb = (uint32_t)(((lane >> 3) & 1) * 16);

    auto load_chunk = [&](int ch, int bsel) {
        int k0 = ch << 6;
        uint32_t tb = base + (uint32_t)bsel * STAGE_B;
#pragma unroll
        for (int i = 0; i < 4; i++) {
            int row = lrow + i * 32;
            uint32_t soff = swz((uint32_t)row * 128u + (uint32_t)lu * 16u);
            size_t aoff = (size_t)(bm + row) * lda + k0 + lu * 8;
            cpa16(tb + soff,             Ah + aoff, 16u);
            cpa16(tb + BTILE + soff,     Al + aoff, 16u);
            uint32_t bsz = ((bn + row) < N) ? 16u : 0u;
            size_t boff = (size_t)(bn + row) * ldb + k0 + lu * 8;
            cpa16(tb + 2 * BTILE + soff, Bh + boff, bsz);
            cpa16(tb + 3 * BTILE + soff, Bl + boff, bsz);
        }
    };

    auto compute = [&](int bsel) {
        uint32_t tb  = base + (uint32_t)bsel * STAGE_B;
        uint32_t tAh = tb, tAl = tb + BTILE, tBh = tb + 2 * BTILE, tBl = tb + 3 * BTILE;
#pragma unroll
        for (int ks = 0; ks < 4; ks++) {
            uint32_t kbyte = (uint32_t)ks * 32u;
            uint32_t afrag[4][4], bhfrag[2][4], blfrag[2][4];
#pragma unroll
            for (int mt = 0; mt < 4; mt++) {
                uint32_t rr = (uint32_t)(m0w + mt * 16) + a_row;
                ldm_x4(tAh + swz(rr * 128u + kbyte + a_colb), afrag[mt]);
            }
#pragma unroll
            for (int bt = 0; bt < 2; bt++) {
                uint32_t rr = (uint32_t)(n0w + bt * 16) + b_row;
                uint32_t off = swz(rr * 128u + kbyte + b_colb);
                ldm_x4(tBh + off, bhfrag[bt]);
                ldm_x4(tBl + off, blfrag[bt]);
            }
            // term 1: Ahi*Bhi
#pragma unroll
            for (int mt = 0; mt < 4; mt++)
#pragma unroll
                for (int nt = 0; nt < 4; nt++)
                    mma16816(acc[mt][nt], afrag[mt], &bhfrag[nt >> 1][(nt & 1) * 2]);
            // term 2: Ahi*Blo
#pragma unroll
            for (int mt = 0; mt < 4; mt++)
#pragma unroll
                for (int nt = 0; nt < 4; nt++)
                    mma16816(acc[mt][nt], afrag[mt], &blfrag[nt >> 1][(nt & 1) * 2]);
            // term 3: Alo*Bhi (reload A frags as lo)
#pragma unroll
            for (int mt = 0; mt < 4; mt++) {
                uint32_t rr = (uint32_t)(m0w + mt * 16) + a_row;
                ldm_x4(tAl + swz(rr * 128u + kbyte + a_colb), afrag[mt]);
            }
#pragma unroll
            for (int mt = 0; mt < 4; mt++)
#pragma unroll
                for (int nt = 0; nt < 4; nt++)
                    mma16816(acc[mt][nt], afrag[mt], &bhfrag[nt >> 1][(nt & 1) * 2]);
        }
    };

    // 3-stage pipeline: up to 2 chunks in flight ahead of compute
    int issued = 0;
    if (issued < nch) { load_chunk(issued, issued % NSTAGE); cpa_commit(); issued++; }
    if (issued < nch) { load_chunk(issued, issued % NSTAGE); cpa_commit(); issued++; }
    for (int ch = 0; ch < nch; ch++) {
        if (issued < nch) { load_chunk(issued, issued % NSTAGE); cpa_commit(); issued++; }
        int pending = issued - ch - 1;
        if (pending >= 2)      cpa_wait<2>();
        else if (pending == 1) cpa_wait<1>();
        else                   cpa_wait<0>();
        __syncthreads();
        compute(ch % NSTAGE);
        __syncthreads();
    }

    // ---------------- epilogue ----------------
    float* CfB = (OUTM != 2) ? Cf + (long long)blockIdx.z * sC : nullptr;
    __nv_bfloat16* ChB = (OUTM == 2) ? Ch + (long long)blockIdx.z * sC : nullptr;
    __nv_bfloat16* ClB = (OUTM == 2) ? Cl + (long long)blockIdx.z * sC : nullptr;
#pragma unroll
    for (int mt = 0; mt < 4; mt++) {
        int row0 = bm + m0w + mt * 16 + (lane >> 2);
#pragma unroll
        for (int nt = 0; nt < 4; nt++) {
            int col = bn + n0w + nt * 8 + (lane & 3) * 2;
            float* c = acc[mt][nt];
#pragma unroll
            for (int half = 0; half < 2; half++) {
                int row = row0 + half * 8;
                float v0 = c[half * 2], v1 = c[half * 2 + 1];
                if (OUTM == 2) {
                    if (col + 1 < N) {
                        __nv_bfloat16 h0, l0, h1, l1;
                        split1(v0, h0, l0); split1(v1, h1, l1);
                        __nv_bfloat162 hv; hv.x = h0; hv.y = h1;
                        __nv_bfloat162 lv; lv.x = l0; lv.y = l1;
                        *reinterpret_cast<__nv_bfloat162*>(ChB + (size_t)row * ldc + col) = hv;
                        *reinterpret_cast<__nv_bfloat162*>(ClB + (size_t)row * ldc + col) = lv;
                    }
                } else {
                    float* Crow = CfB + (size_t)row * ldc;
                    if (col + 1 < N) {
                        float2 cv;
                        if (OUTM == 1) {
                            cv = *reinterpret_cast<float2*>(Crow + col);
                            cv.x += v0; cv.y += v1;
                        } else cv = make_float2(v0, v1);
                        *reinterpret_cast<float2*>(Crow + col) = cv;
                    } else if (col < N) {
                        Crow[col] = (OUTM == 1) ? (Crow[col] + v0) : v0;
                    }
                }
            }
        }
    }
}

template <int OUTM>
static inline void gemm_bf_launch(const __nv_bfloat16* Ah, const __nv_bfloat16* Al,
                                  int lda, long long sA,
                                  const __nv_bfloat16* Bh, const __nv_bfloat16* Bl,
                                  int ldb, long long sB,
                                  float* Cf, __nv_bfloat16* Ch, __nv_bfloat16* Cl,
                                  int ldc, long long sC,
                                  int M, int N, int K, int batch, int causal) {
    dim3 grid((N + 127) / 128, M / 128, batch);
    cudaFuncSetAttribute(gemm_bf<OUTM>, cudaFuncAttributeMaxDynamicSharedMemorySize, SHM_BF);
    gemm_bf<OUTM><<<grid, 256, SHM_BF>>>(Ah, Al, lda, sA, Bh, Bl, ldb, sB,
                                         Cf, Ch, Cl, ldc, sC, N, K, causal);
}

// ---------------- reductions ----------------
__device__ __forceinline__ float warp_sum(float v) {
#pragma unroll
    for (int o = 16; o; o >>= 1) v += __shfl_xor_sync(0xffffffffu, v, o);
    return v;
}
__device__ __forceinline__ float warp_max(float v) {
#pragma unroll
    for (int o = 16; o; o >>= 1) v = fmaxf(v, __shfl_xor_sync(0xffffffffu, v, o));
    return v;
}

// ---------------- weight split: fp32 -> bf16 hi/lo ----------------
__global__ void split_w_kernel(const float4* __restrict__ src,
                               __nv_bfloat162* __restrict__ h2,
                               __nv_bfloat162* __restrict__ l2, int n4) {
    int i = blockIdx.x * 256 + threadIdx.x;
    if (i >= n4) return;
    float4 x = src[i];
    __nv_bfloat162 ha = __floats2bfloat162_rn(x.x, x.y);
    __nv_bfloat162 hb = __floats2bfloat162_rn(x.z, x.w);
    __nv_bfloat162 la = __floats2bfloat162_rn(x.x - __bfloat162float(ha.x),
                                              x.y - __bfloat162float(ha.y));
    __nv_bfloat162 lb = __floats2bfloat162_rn(x.z - __bfloat162float(hb.x),
                                              x.w - __bfloat162float(hb.y));
    h2[2 * i] = ha; h2[2 * i + 1] = hb;
    l2[2 * i] = la; l2[2 * i + 1] = lb;
}

// ---------------- embed (sin/cos) + LayerNorm (fp32 out) ----------------
__global__ void embed_ln_kernel(const int* __restrict__ q,
                                const float* __restrict__ freqs,
                                const float* __restrict__ g,
                                const float* __restrict__ b,
                                float* __restrict__ y) {
    int t = blockIdx.x;
    int tid = threadIdx.x;
    float qv = (float)q[t];
    float v[3];
#pragma unroll
    for (int k = 0; k < 3; k++) {
        int d = tid + k * 128;
        if (d < Dd / 2) v[k] = sinf(qv * freqs[d]);
        else            v[k] = cosf(qv * freqs[d - Dd / 2]);
    }
    float s = v[0] + v[1] + v[2];
    float sq = v[0]*v[0] + v[1]*v[1] + v[2]*v[2];
    s = warp_sum(s); sq = warp_sum(sq);
    __shared__ float shs[4], shq[4], mr[2];
    if ((tid & 31) == 0) { shs[tid >> 5] = s; shq[tid >> 5] = sq; }
    __syncthreads();
    if (tid == 0) {
        float ts = shs[0]+shs[1]+shs[2]+shs[3], tq = shq[0]+shq[1]+shq[2]+shq[3];
        float mean = ts * (1.0f / Dd);
        float var  = tq * (1.0f / Dd) - mean * mean;
        mr[0] = mean; mr[1] = rsqrtf(var + 1e-5f);
    }
    __syncthreads();
    float mean = mr[0], rstd = mr[1];
    float* yr = y + (size_t)t * Dd;
#pragma unroll
    for (int k = 0; k < 3; k++) {
        int d = tid + k * 128;
        yr[d] = (v[k] - mean) * rstd * g[d] + b[d];
    }
}

// ---------------- LayerNorm, fp32 out (final LN) ----------------
__global__ void ln_kernel(const float* __restrict__ x, float* __restrict__ y,
                          const float* __restrict__ g, const float* __restrict__ b) {
    int t = blockIdx.x;
    int tid = threadIdx.x;
    const float* xr = x + (size_t)t * Dd;
    float v0 = xr[tid], v1 = xr[tid + 128], v2 = xr[tid + 256];
    float s  = v0 + v1 + v2;
    float sq = v0*v0 + v1*v1 + v2*v2;
    s = warp_sum(s); sq = warp_sum(sq);
    __shared__ float shs[4], shq[4], mr[2];
    if ((tid & 31) == 0) { shs[tid >> 5] = s; shq[tid >> 5] = sq; }
    __syncthreads();
    if (tid == 0) {
        float ts = shs[0]+shs[1]+shs[2]+shs[3], tq = shq[0]+shq[1]+shq[2]+shq[3];
        float mean = ts * (1.0f / Dd);
        float var  = tq * (1.0f / Dd) - mean * mean;
        mr[0] = mean; mr[1] = rsqrtf(var + 1e-5f);
    }
    __syncthreads();
    float mean = mr[0], rstd = mr[1];
    float* yr = y + (size_t)t * Dd;
    yr[tid]       = (v0 - mean) * rstd * g[tid]       + b[tid];
    yr[tid + 128] = (v1 - mean) * rstd * g[tid + 128] + b[tid + 128];
    yr[tid + 256] = (v2 - mean) * rstd * g[tid + 256] + b[tid + 256];
}

// ---------------- LayerNorm, bf16 hi/lo out (per-block LN) ----------------
__global__ void ln_bf16_kernel(const float* __restrict__ x,
                               __nv_bfloat16* __restrict__ yh,
                               __nv_bfloat16* __restrict__ yl,
                               const float* __restrict__ g,
                               const float* __restrict__ b) {
    int t = blockIdx.x;
    int tid = threadIdx.x;
    const float* xr = x + (size_t)t * Dd;
    float v0 = xr[tid], v1 = xr[tid + 128], v2 = xr[tid + 256];
    float s  = v0 + v1 + v2;
    float sq = v0*v0 + v1*v1 + v2*v2;
    s = warp_sum(s); sq = warp_sum(sq);
    __shared__ float shs[4], shq[4], mr[2];
    if ((tid & 31) == 0) { shs[tid >> 5] = s; shq[tid >> 5] = sq; }
    __syncthreads();
    if (tid == 0) {
        float ts = shs[0]+shs[1]+shs[2]+shs[3], tq = shq[0]+shq[1]+shq[2]+shq[3];
        float mean = ts * (1.0f / Dd);
        float var  = tq * (1.0f / Dd) - mean * mean;
        mr[0] = mean; mr[1] = rsqrtf(var + 1e-5f);
    }
    __syncthreads();
    float mean = mr[0], rstd = mr[1];
    size_t rb = (size_t)t * Dd;
#pragma unroll
    for (int k = 0; k < 3; k++) {
        int d = tid + k * 128;
        float vv = (k == 0 ? v0 : (k == 1 ? v1 : v2));
        float y = (vv - mean) * rstd * g[d] + b[d];
        __nv_bfloat16 hh, ll;
        split1(y, hh, ll);
        yh[rb + d] = hh; yl[rb + d] = ll;
    }
}

// ---------------- fused geglu + qk split ----------------
__global__ void geglu_qk_kernel(const float* __restrict__ h,
                                __nv_bfloat16* __restrict__ cath,
                                __nv_bfloat16* __restrict__ catl,
                                float* __restrict__ v,
                                __nv_bfloat16* __restrict__ qh, __nv_bfloat16* __restrict__ ql,
                                __nv_bfloat16* __restrict__ kh, __nv_bfloat16* __restrict__ kl) {
    int t = blockIdx.x;
    int tid = threadIdx.x;
    const float* hr = h + (size_t)t * Hd;
    if (tid < 192) {
        int j4 = tid;
        float4 lin = *reinterpret_cast<const float4*>(hr + 2 * QKd + j4 * 4);
        float4 pg  = *reinterpret_cast<const float4*>(hr + 2 * QKd + Ed + j4 * 4);
        float4 r;
        r.x = lin.x * 0.5f * pg.x * (1.0f + erff(pg.x * 0.70710678118654752f));
        r.y = lin.y * 0.5f * pg.y * (1.0f + erff(pg.y * 0.70710678118654752f));
        r.z = lin.z * 0.5f * pg.z * (1.0f + erff(pg.z * 0.70710678118654752f));
        r.w = lin.w * 0.5f * pg.w * (1.0f + erff(pg.w * 0.70710678118654752f));
        if (j4 < 96) {
            __nv_bfloat162 ha = __floats2bfloat162_rn(r.x, r.y);
            __nv_bfloat162 hb = __floats2bfloat162_rn(r.z, r.w);
            __nv_bfloat162 la = __floats2bfloat162_rn(r.x - __bfloat162float(ha.x),
                                                      r.y - __bfloat162float(ha.y));
            __nv_bfloat162 lb = __floats2bfloat162_rn(r.z - __bfloat162float(hb.x),
                                                      r.w - __bfloat162float(hb.y));
            __nv_bfloat162* ch = reinterpret_cast<__nv_bfloat162*>(cath + (size_t)t * Ed + j4 * 4);
            __nv_bfloat162* cl = reinterpret_cast<__nv_bfloat162*>(catl + (size_t)t * Ed + j4 * 4);
            ch[0] = ha; ch[1] = hb; cl[0] = la; cl[1] = lb;
        } else {
            *reinterpret_cast<float4*>(v + (size_t)t * Dd + (j4 - 96) * 4) = r;
        }
    } else {
        int u = tid - 192;          // 0..63
        int which = u >> 5;         // 0: q, 1: k
        int d0 = (u & 31) * 2;      // 0..62
        float a = (d0     < QKd) ? hr[which * QKd + d0]     : 0.0f;
        float b = (d0 + 1 < QKd) ? hr[which * QKd + d0 + 1] : 0.0f;
        __nv_bfloat162 hv = __floats2bfloat162_rn(a, b);
        __nv_bfloat162 lv = __floats2bfloat162_rn(a - __bfloat162float(hv.x),
                                                  b - __bfloat162float(hv.y));
        size_t idx = (size_t)t * 64 + d0;
        if (which == 0) {
            *reinterpret_cast<__nv_bfloat162*>(qh + idx) = hv;
            *reinterpret_cast<__nv_bfloat162*>(ql + idx) = lv;
        } else {
            *reinterpret_cast<__nv_bfloat162*>(kh + idx) = hv;
            *reinterpret_cast<__nv_bfloat162*>(kl + idx) = lv;
        }
    }
}

// ---------------- V transpose: fp32 [Sq x Dd] -> bf16 hi/lo [Dd x Sq] ------
__global__ void transpose_v(const float* __restrict__ v,
                            __nv_bfloat16* __restrict__ vth,
                            __nv_bfloat16* __restrict__ vtl) {
    __shared__ float tile[32][33];
    int b = blockIdx.z;
    int s0 = blockIdx.x * 32, d0 = blockIdx.y * 32;
    int x = threadIdx.x, y = threadIdx.y;
    const float* src = v + (size_t)b * Sq * Dd;
    size_t dstb = (size_t)b * Dd * Sq;
#pragma unroll
    for (int i = 0; i < 32; i += 8)
        tile[y + i][x] = src[(size_t)(s0 + y + i) * Dd + d0 + x];
    __syncthreads();
#pragma unroll
    for (int i = 0; i < 32; i += 8) {
        float val = tile[x][y + i];
        __nv_bfloat16 hh, ll;
        split1(val, hh, ll);
        size_t idx = dstb + (size_t)(d0 + y + i) * Sq + s0 + x;
        vth[idx] = hh; vtl[idx] = ll;
    }
}

// ---------------- causal softmax: fp32 scores -> bf16 hi/lo probs ----------
__global__ void softmax_kernel(const float* __restrict__ p,
                               __nv_bfloat16* __restrict__ ph,
                               __nv_bfloat16* __restrict__ pl) {
    int i = blockIdx.x;
    int b = blockIdx.y;
    size_t off = ((size_t)b * Sq + i) * Sq;
    const float* row = p + off;
    int L = i + 1;
    int zend = ((i >> 7) + 1) << 7;
    int tid = threadIdx.x;   // 256
    const float scale = 0.14433756729740643f;
    __shared__ float sh[8];

    float m = -3.0e38f;
    float rv[8];
#pragma unroll
    for (int k = 0; k < 8; k++) {
        int j = tid + k * 256;
        rv[k] = (j < L) ? row[j] : -3.0e38f;
        m = fmaxf(m, rv[k]);
    }
    m = warp_max(m);
    if ((tid & 31) == 0) sh[tid >> 5] = m;
    __syncthreads();
    float mm = sh[0];
#pragma unroll
    for (int k = 1; k < 8; k++) mm = fmaxf(mm, sh[k]);
    __syncthreads();

    float sum = 0.0f;
#pragma unroll
    for (int k = 0; k < 8; k++) {
        int j = tid + k * 256;
        if (j < L) { rv[k] = __expf((rv[k] - mm) * scale); sum += rv[k]; }
    }
    sum = warp_sum(sum);
    if ((tid & 31) == 0) sh[tid >> 5] = sum;
    __syncthreads();
    float tot = sh[0];
#pragma unroll
    for (int k = 1; k < 8; k++) tot += sh[k];
    float inv = 1.0f / tot;

#pragma unroll
    for (int k = 0; k < 8; k++) {
        int j = tid + k * 256;
        if (j < zend) {
            float e = (j < L) ? rv[k] * inv : 0.0f;
            __nv_bfloat16 hh, ll;
            split1(e, hh, ll);
            ph[off + j] = hh; pl[off + j] = ll;
        }
    }
}

// ---------------- SIMT SGEMM (logits only): C = A(MxK) * B(NxK)^T ----------
__global__ void __launch_bounds__(256, 2)
gemm_simt(const float* __restrict__ A, int lda,
          const float* __restrict__ B, int ldb,
          float* __restrict__ C, int ldc, int N, int K) {
    int bm = blockIdx.y * 128;
    int bn = blockIdx.x * 128;

    __shared__ float As[8][128];
    __shared__ float Bs[8][128];
    int tid = threadIdx.x;
    int tx = tid & 15, ty = tid >> 4;
    float acc[8][8] = {};

    int lrow = tid >> 1;
    int lkk  = (tid & 1) * 4;
    const float* Ap = A + (size_t)(bm + lrow) * lda + lkk;
    bool bvalid = (bn + lrow) < N;
    const float* Bp = B + (size_t)(bn + lrow) * ldb + lkk;

    for (int k0 = 0; k0 < K; k0 += 8) {
        float4 av = *reinterpret_cast<const float4*>(Ap + k0);
        float4 bv = bvalid ? *reinterpret_cast<const float4*>(Bp + k0)
                           : make_float4(0.f, 0.f, 0.f, 0.f);
        As[lkk+0][lrow]=av.x; As[lkk+1][lrow]=av.y; As[lkk+2][lrow]=av.z; As[lkk+3][lrow]=av.w;
        Bs[lkk+0][lrow]=bv.x; Bs[lkk+1][lrow]=bv.y; Bs[lkk+2][lrow]=bv.z; Bs[lkk+3][lrow]=bv.w;
        __syncthreads();
#pragma unroll
        for (int kk = 0; kk < 8; kk++) {
            float a[8], b[8];
            *reinterpret_cast<float4*>(&a[0]) = *reinterpret_cast<const float4*>(&As[kk][ty*8]);
            *reinterpret_cast<float4*>(&a[4]) = *reinterpret_cast<const float4*>(&As[kk][ty*8+4]);
            *reinterpret_cast<float4*>(&b[0]) = *reinterpret_cast<const float4*>(&Bs[kk][tx*8]);
            *reinterpret_cast<float4*>(&b[4]) = *reinterpret_cast<const float4*>(&Bs[kk][tx*8+4]);
#pragma unroll
            for (int i = 0; i < 8; i++)
#pragma unroll
                for (int j = 0; j < 8; j++)
                    acc[i][j] += a[i] * b[j];
        }
        __syncthreads();
    }
#pragma unroll
    for (int i = 0; i < 8; i++) {
        float* Crow = C + (size_t)(bm + ty * 8 + i) * ldc;
#pragma unroll
        for (int j = 0; j < 8; j++) {
            int n = bn + tx * 8 + j;
            if (n < N) Crow[n] = acc[i][j];
        }
    }
}

// ---------------- driver ----------------
extern "C" void kernel_launch(void* const* d_in, const int* in_sizes, int n_in,
                              void* d_out, int out_size) {
    const int*   q      = (const int*)  d_in[0];
    const float* freqs  = (const float*)d_in[1];
    const float* exp_w  = (const float*)d_in[2];   // (8, 1632, 384)
    const float* proj_w = (const float*)d_in[3];   // (8, 384, 768)
    const float* blk_g  = (const float*)d_in[4];
    const float* blk_b  = (const float*)d_in[5];
    const float* ln_g   = (const float*)d_in[6];
    const float* ln_b   = (const float*)d_in[7];
    const float* out_w  = (const float*)d_in[8];   // (100, 384)
    float* out = (float*)d_out;

    float *x, *xn, *h, *v, *p;
    __nv_bfloat16 *xnh, *xnl, *cath, *catl, *vth, *vtl, *ph, *pl;
    __nv_bfloat16 *qh, *ql, *kh, *kl, *ewh, *ewl, *pwh, *pwl;
    cudaGetSymbolAddress((void**)&x,    g_x);
    cudaGetSymbolAddress((void**)&xn,   g_xn);
    cudaGetSymbolAddress((void**)&h,    g_h);
    cudaGetSymbolAddress((void**)&v,    g_v);
    cudaGetSymbolAddress((void**)&p,    g_p);
    cudaGetSymbolAddress((void**)&xnh,  g_xnh);  cudaGetSymbolAddress((void**)&xnl,  g_xnl);
    cudaGetSymbolAddress((void**)&cath, g_cath); cudaGetSymbolAddress((void**)&catl, g_catl);
    cudaGetSymbolAddress((void**)&vth,  g_vth);  cudaGetSymbolAddress((void**)&vtl,  g_vtl);
    cudaGetSymbolAddress((void**)&ph,   g_ph);   cudaGetSymbolAddress((void**)&pl,   g_pl);
    cudaGetSymbolAddress((void**)&qh,   g_qh);   cudaGetSymbolAddress((void**)&ql,   g_ql);
    cudaGetSymbolAddress((void**)&kh,   g_kh);   cudaGetSymbolAddress((void**)&kl,   g_kl);
    cudaGetSymbolAddress((void**)&ewh,  g_ewh);  cudaGetSymbolAddress((void**)&ewl,  g_ewl);
    cudaGetSymbolAddress((void**)&pwh,  g_pwh);  cudaGetSymbolAddress((void**)&pwl,  g_pwl);

    // pre-split weights (once per launch)
    {
        int n4e = NBq * Hd * Dd / 4;
        int n4p = NBq * Dd * Ed / 4;
        split_w_kernel<<<(n4e + 255) / 256, 256>>>(
            (const float4*)exp_w, (__nv_bfloat162*)ewh, (__nv_bfloat162*)ewl, n4e);
        split_w_kernel<<<(n4p + 255) / 256, 256>>>(
            (const float4*)proj_w, (__nv_bfloat162*)pwh, (__nv_bfloat162*)pwl, n4p);
    }

    embed_ln_kernel<<<Tq, 128>>>(q, freqs, ln_g, ln_b, x);

    for (int blk = 0; blk < NBq; blk++) {
        ln_bf16_kernel<<<Tq, 128>>>(x, xnh, xnl, blk_g + blk * Dd, blk_b + blk * Dd);

        // h = xn @ exp_w[blk]^T   (8192 x 1632, K=384) -> fp32
        gemm_bf_launch<0>(xnh, xnl, Dd, 0,
                          ewh + (size_t)blk * Hd * Dd, ewl + (size_t)blk * Hd * Dd, Dd, 0,
                          h, nullptr, nullptr, Hd, 0,
                          Tq, Hd, Dd, 1, 0);

        geglu_qk_kernel<<<Tq, 256>>>(h, cath, catl, v, qh, ql, kh, kl);

        // scores: qh @ kh^T per batch (K padded to 64), causal tile-skip
        gemm_bf_launch<0>(qh, ql, 64, (long long)Sq * 64,
                          kh, kl, 64, (long long)Sq * 64,
                          p, nullptr, nullptr, Sq, (long long)Sq * Sq,
                          Sq, Sq, 64, Bq, 1);

        softmax_kernel<<<dim3(Sq, Bq), 256>>>(p, ph, pl);

        transpose_v<<<dim3(Sq / 32, Dd / 32, Bq), dim3(32, 8)>>>(v, vth, vtl);

        // attn = P @ V -> cat[:, 384:768] as bf16 hi/lo; K capped causally
        gemm_bf_launch<2>(ph, pl, Sq, (long long)Sq * Sq,
                          vth, vtl, Sq, (long long)Dd * Sq,
                          nullptr, cath + Dd, catl + Dd, Ed, (long long)Sq * Ed,
                          Sq, Dd, Sq, Bq, 2);

        // x += cat @ proj_w[blk]^T
        gemm_bf_launch<1>(cath, catl, Ed, 0,
                          pwh + (size_t)blk * Dd * Ed, pwl + (size_t)blk * Dd * Ed, Ed, 0,
                          x, nullptr, nullptr, Dd, 0,
                          Tq, Dd, Ed, 1, 0);
    }

    ln_kernel<<<Tq, 128>>>(x, xn, ln_g, ln_b);
    gemm_simt<<<dim3(1, Tq / 128), 256>>>(xn, Dd, out_w, Dd, out, VOCABq, VOCABq, Dd);
}

// round 12
// speedup vs baseline: 1.2396x; 1.0007x over previous
#include <cuda_runtime.h>
#include <cuda_bf16.h>
#include <cstdint>

// ---------------- problem constants ----------------
#define Bq      4
#define Sq      2048
#define Tq      (Bq * Sq)      // 8192 tokens
#define Dd      384
#define QKd     48
#define Ed      768
#define Hd      1632           // 2*QK + 2*E
#define HPERM   1664           // permuted expand width: 1536 pairs + 64 qh + 64 kh
#define NBq     8
#define VOCABq  100

// ---------------- scratch (static device globals; no cudaMalloc) -----------
__device__ float g_x[Tq * Dd];                        // residual stream
__device__ float g_xn[Tq * Dd];                       // final-LN output (fp32)
__device__ float g_p[(size_t)Bq * Sq * Sq];           // raw scores fp32

#define AL16 __align__(16)
__device__ AL16 __nv_bfloat16 g_xnh[Tq * Dd],  g_xnl[Tq * Dd];
__device__ AL16 __nv_bfloat16 g_cath[(size_t)Tq * Ed], g_catl[(size_t)Tq * Ed];
__device__ AL16 __nv_bfloat16 g_vth[(size_t)Bq * Dd * Sq], g_vtl[(size_t)Bq * Dd * Sq];
__device__ AL16 __nv_bfloat16 g_ph[(size_t)Bq * Sq * Sq],  g_pl[(size_t)Bq * Sq * Sq];
__device__ AL16 __nv_bfloat16 g_qh[Tq * 64], g_ql[Tq * 64];   // qh padded K=64 (pre-scaled)
__device__ AL16 __nv_bfloat16 g_kh[Tq * 64], g_kl[Tq * 64];   // kh padded K=64
__device__ AL16 __nv_bfloat16 g_ewh[(size_t)NBq * HPERM * Dd], g_ewl[(size_t)NBq * HPERM * Dd];
__device__ AL16 __nv_bfloat16 g_pwh[NBq * Dd * Ed], g_pwl[NBq * Dd * Ed];

// ================= low-level helpers =================
__device__ __forceinline__ uint32_t s2u(const void* p) {
    uint32_t a;
    asm("{ .reg .u64 t; cvta.to.shared.u64 t, %1; cvt.u32.u64 %0, t; }" : "=r"(a) : "l"(p));
    return a;
}
__device__ __forceinline__ void cpa16(uint32_t dst, const void* src, uint32_t sz) {
    asm volatile("cp.async.cg.shared.global [%0], [%1], 16, %2;"
                 :: "r"(dst), "l"(src), "r"(sz) : "memory");
}
__device__ __forceinline__ void cpa_commit() {
    asm volatile("cp.async.commit_group;" ::: "memory");
}
template <int NN>
__device__ __forceinline__ void cpa_wait() {
    asm volatile("cp.async.wait_group %0;" :: "n"(NN) : "memory");
}
__device__ __forceinline__ uint32_t swz(uint32_t off) { return off ^ ((off >> 3) & 0x70); }

__device__ __forceinline__ void ldm_x4(uint32_t addr, uint32_t* r) {
    asm volatile("ldmatrix.sync.aligned.m8n8.x4.shared.b16 {%0,%1,%2,%3}, [%4];"
                 : "=r"(r[0]), "=r"(r[1]), "=r"(r[2]), "=r"(r[3]) : "r"(addr));
}
__device__ __forceinline__ void mma16816(float* c, const uint32_t* a, const uint32_t* b) {
    asm volatile("mma.sync.aligned.m16n8k16.row.col.f32.bf16.bf16.f32 "
                 "{%0,%1,%2,%3}, {%4,%5,%6,%7}, {%8,%9}, {%0,%1,%2,%3};"
                 : "+f"(c[0]), "+f"(c[1]), "+f"(c[2]), "+f"(c[3])
                 : "r"(a[0]), "r"(a[1]), "r"(a[2]), "r"(a[3]), "r"(b[0]), "r"(b[1]));
}
__device__ __forceinline__ void split1(float v, __nv_bfloat16& h, __nv_bfloat16& l) {
    h = __float2bfloat16_rn(v);
    l = __float2bfloat16_rn(v - __bfloat162float(h));
}

// ================= bf16 HMMA GEMM: C = A(MxK) * B(NxK)^T, 3-term split =====
// 128x128 CTA tile, BK=64, 8 warps (2Mx4N), cp.async 3-stage, reg acc.
// causal: 0=none, 1=skip bn>bm, 2=cap K at bm+128. M-order flipped when causal.
// OUTM: 0 = fp32 store, 1 = fp32 add, 2 = bf16 hi/lo store,
//       3 = fused expand epilogue (geglu->cat/V^T, qk split) via device globals.
#define BTILE   16384                   // 128 rows x 64 bf16 x 2B
#define STAGE_B (4 * BTILE)             // Ah, Al, Bh, Bl = 64 KB
#define NSTAGE  3
#define SHM_BF  (NSTAGE * STAGE_B + 128)

template <int OUTM>
__global__ void __launch_bounds__(256, 1)
gemm_bf(const __nv_bfloat16* __restrict__ Ah_, const __nv_bfloat16* __restrict__ Al_,
        int lda, long long sA,
        const __nv_bfloat16* __restrict__ Bh_, const __nv_bfloat16* __restrict__ Bl_,
        int ldb, long long sB,
        float* __restrict__ Cf,
        __nv_bfloat16* __restrict__ Ch, __nv_bfloat16* __restrict__ Cl,
        int ldc, long long sC, int N, int K, int causal) {
    int my = (causal != 0) ? ((int)gridDim.y - 1 - (int)blockIdx.y) : (int)blockIdx.y;
    int bm = my * 128;
    int bn = blockIdx.x * 128;
    if (causal == 1 && bn > bm) return;
    int Keff = (causal == 2) ? ((bm + 128 < K) ? bm + 128 : K) : K;
    int nch = Keff >> 6;

    const __nv_bfloat16* Ah = Ah_ + (long long)blockIdx.z * sA;
    const __nv_bfloat16* Al = Al_ + (long long)blockIdx.z * sA;
    const __nv_bfloat16* Bh = Bh_ + (long long)blockIdx.z * sB;
    const __nv_bfloat16* Bl = Bl_ + (long long)blockIdx.z * sB;

    extern __shared__ char dsm[];
    uint32_t base = (s2u(dsm) + 127u) & ~127u;

    int tid = threadIdx.x;
    int wid = tid >> 5, lane = tid & 31;
    int m0w = (wid >> 2) * 64;      // 2 warps in M
    int n0w = (wid & 3) * 32;       // 4 warps in N

    int lrow = tid >> 3;       // 0..31
    int lu   = tid & 7;        // 0..7

    float acc[4][4][4];
#pragma unroll
    for (int i = 0; i < 4; i++)
#pragma unroll
        for (int j = 0; j < 4; j++)
#pragma unroll
            for (int e = 0; e < 4; e++) acc[i][j][e] = 0.0f;

    uint32_t a_row  = (uint32_t)(lane & 15);
    uint32_t a_colb = (uint32_t)((lane >> 4) * 16);
    uint32_t b_row  = (uint32_t)(((lane >> 4) << 3) + (lane & 7));
    uint32_t b_colb = (uint32_t)(((lane >> 3) & 1) * 16);

    auto load_chunk = [&](int ch, int bsel) {
        int k0 = ch << 6;
        uint32_t tb = base + (uint32_t)bsel * STAGE_B;
#pragma unroll
        for (int i = 0; i < 4; i++) {
            int row = lrow + i * 32;
            uint32_t soff = swz((uint32_t)row * 128u + (uint32_t)lu * 16u);
            size_t aoff = (size_t)(bm + row) * lda + k0 + lu * 8;
            cpa16(tb + soff,             Ah + aoff, 16u);
            cpa16(tb + BTILE + soff,     Al + aoff, 16u);
            uint32_t bsz = ((bn + row) < N) ? 16u : 0u;
            size_t boff = (size_t)(bn + row) * ldb + k0 + lu * 8;
            cpa16(tb + 2 * BTILE + soff, Bh + boff, bsz);
            cpa16(tb + 3 * BTILE + soff, Bl + boff, bsz);
        }
    };

    auto compute = [&](int bsel) {
        uint32_t tb  = base + (uint32_t)bsel * STAGE_B;
        uint32_t tAh = tb, tAl = tb + BTILE, tBh = tb + 2 * BTILE, tBl = tb + 3 * BTILE;
#pragma unroll
        for (int ks = 0; ks < 4; ks++) {
            uint32_t kbyte = (uint32_t)ks * 32u;
            uint32_t afrag[4][4], bhfrag[2][4], blfrag[2][4];
#pragma unroll
            for (int mt = 0; mt < 4; mt++) {
                uint32_t rr = (uint32_t)(m0w + mt * 16) + a_row;
                ldm_x4(tAh + swz(rr * 128u + kbyte + a_colb), afrag[mt]);
            }
#pragma unroll
            for (int bt = 0; bt < 2; bt++) {
                uint32_t rr = (uint32_t)(n0w + bt * 16) + b_row;
                uint32_t off = swz(rr * 128u + kbyte + b_colb);
                ldm_x4(tBh + off, bhfrag[bt]);
                ldm_x4(tBl + off, blfrag[bt]);
            }
#pragma unroll
            for (int mt = 0; mt < 4; mt++)
#pragma unroll
                for (int nt = 0; nt < 4; nt++)
                    mma16816(acc[mt][nt], afrag[mt], &bhfrag[nt >> 1][(nt & 1) * 2]);
#pragma unroll
            for (int mt = 0; mt < 4; mt++)
#pragma unroll
                for (int nt = 0; nt < 4; nt++)
                    mma16816(acc[mt][nt], afrag[mt], &blfrag[nt >> 1][(nt & 1) * 2]);
#pragma unroll
            for (int mt = 0; mt < 4; mt++) {
                uint32_t rr = (uint32_t)(m0w + mt * 16) + a_row;
                ldm_x4(tAl + swz(rr * 128u + kbyte + a_colb), afrag[mt]);
            }
#pragma unroll
            for (int mt = 0; mt < 4; mt++)
#pragma unroll
                for (int nt = 0; nt < 4; nt++)
                    mma16816(acc[mt][nt], afrag[mt], &bhfrag[nt >> 1][(nt & 1) * 2]);
        }
    };

    int issued = 0;
    if (issued < nch) { load_chunk(issued, issued % NSTAGE); cpa_commit(); issued++; }
    if (issued < nch) { load_chunk(issued, issued % NSTAGE); cpa_commit(); issued++; }
    for (int ch = 0; ch < nch; ch++) {
        if (issued < nch) { load_chunk(issued, issued % NSTAGE); cpa_commit(); issued++; }
        int pending = issued - ch - 1;
        if (pending >= 2)      cpa_wait<2>();
        else if (pending == 1) cpa_wait<1>();
        else                   cpa_wait<0>();
        __syncthreads();
        compute(ch % NSTAGE);
        __syncthreads();
    }

    // ---------------- epilogue ----------------
    if (OUTM == 3) {
        // fused expand epilogue: stage acc tile (128x128 fp32) in smem,
        // then coalesced geglu / qk-split / V^T stores via device globals.
        float* sf = reinterpret_cast<float*>((((uintptr_t)dsm) + 127) & ~(uintptr_t)127);
        const int LDS = 132;   // padded row stride (words) to dodge bank conflicts
#pragma unroll
        for (int mt = 0; mt < 4; mt++) {
            int r0 = m0w + mt * 16 + (lane >> 2);
#pragma unroll
            for (int nt = 0; nt < 4; nt++) {
                int c = n0w + nt * 8 + (lane & 3) * 2;
#pragma unroll
                for (int half = 0; half < 2; half++) {
                    int r = r0 + half * 8;
                    sf[r * LDS + c]     = acc[mt][nt][half * 2];
                    sf[r * LDS + c + 1] = acc[mt][nt][half * 2 + 1];
                }
            }
        }
        __syncthreads();
        if (bn < 1536) {
            // pair tiles: (lin_j, pg_j) interleaved; 128 rows x 64 pairs
            int jbase = bn >> 1;                 // 0..767
            bool isV = (jbase >= 384);
            if (!isV) {
#pragma unroll
                for (int i = 0; i < 32; i++) {
                    int vi = tid + i * 256;      // 8192 values
                    int row = vi >> 6, u = vi & 63;
                    float lin = sf[row * LDS + 2 * u];
                    float pg  = sf[row * LDS + 2 * u + 1];
                    float val = lin * 0.5f * pg * (1.0f + erff(pg * 0.70710678118654752f));
                    __nv_bfloat16 hh, ll; split1(val, hh, ll);
                    size_t idx = (size_t)(bm + row) * Ed + jbase + u;
                    g_cath[idx] = hh; g_catl[idx] = ll;
                }
            } else {
#pragma unroll
                for (int i = 0; i < 32; i++) {
                    int vi = tid + i * 256;
                    int row = vi & 127, u = vi >> 7;   // s-contiguous for V^T
                    float lin = sf[row * LDS + 2 * u];
                    float pg  = sf[row * LDS + 2 * u + 1];
                    float val = lin * 0.5f * pg * (1.0f + erff(pg * 0.70710678118654752f));
                    __nv_bfloat16 hh, ll; split1(val, hh, ll);
                    int t = bm + row;
                    int jj = jbase + u - 384;
                    size_t idx = ((size_t)(t >> 11) * Dd + jj) * Sq + (t & (Sq - 1));
                    g_vth[idx] = hh; g_vtl[idx] = ll;
                }
            }
        } else {
            // qk tile: cols 0..63 -> qh (pre-scaled), 64..127 -> kh
#pragma unroll
            for (int i = 0; i < 64; i++) {
                int vi = tid + i * 256;          // 16384 values
                int row = vi >> 7, c = vi & 127;
                float val = sf[row * LDS + c];
                __nv_bfloat16 hh, ll; split1(val, hh, ll);
                size_t idx = (size_t)(bm + row) * 64 + (c & 63);
                if (c < 64) { g_qh[idx] = hh; g_ql[idx] = ll; }
                else        { g_kh[idx] = hh; g_kl[idx] = ll; }
            }
        }
        return;
    }

    float* CfB = (OUTM != 2) ? Cf + (long long)blockIdx.z * sC : nullptr;
    __nv_bfloat16* ChB = (OUTM == 2) ? Ch + (long long)blockIdx.z * sC : nullptr;
    __nv_bfloat16* ClB = (OUTM == 2) ? Cl + (long long)blockIdx.z * sC : nullptr;
#pragma unroll
    for (int mt = 0; mt < 4; mt++) {
        int row0 = bm + m0w + mt * 16 + (lane >> 2);
#pragma unroll
        for (int nt = 0; nt < 4; nt++) {
            int col = bn + n0w + nt * 8 + (lane & 3) * 2;
            float* c = acc[mt][nt];
#pragma unroll
            for (int half = 0; half < 2; half++) {
                int row = row0 + half * 8;
                float v0 = c[half * 2], v1 = c[half * 2 + 1];
                if (OUTM == 2) {
                    if (col + 1 < N) {
                        __nv_bfloat16 h0, l0, h1, l1;
                        split1(v0, h0, l0); split1(v1, h1, l1);
                        __nv_bfloat162 hv; hv.x = h0; hv.y = h1;
                        __nv_bfloat162 lv; lv.x = l0; lv.y = l1;
                        *reinterpret_cast<__nv_bfloat162*>(ChB + (size_t)row * ldc + col) = hv;
                        *reinterpret_cast<__nv_bfloat162*>(ClB + (size_t)row * ldc + col) = lv;
                    }
                } else {
                    float* Crow = CfB + (size_t)row * ldc;
                    if (col + 1 < N) {
                        float2 cv;
                        if (OUTM == 1) {
                            cv = *reinterpret_cast<float2*>(Crow + col);
                            cv.x += v0; cv.y += v1;
                        } else cv = make_float2(v0, v1);
                        *reinterpret_cast<float2*>(Crow + col) = cv;
                    } else if (col < N) {
                        Crow[col] = (OUTM == 1) ? (Crow[col] + v0) : v0;
                    }
                }
            }
        }
    }
}

template <int OUTM>
static inline void gemm_bf_launch(const __nv_bfloat16* Ah, const __nv_bfloat16* Al,
                                  int lda, long long sA,
                                  const __nv_bfloat16* Bh, const __nv_bfloat16* Bl,
                                  int ldb, long long sB,
                                  float* Cf, __nv_bfloat16* Ch, __nv_bfloat16* Cl,
                                  int ldc, long long sC,
                                  int M, int N, int K, int batch, int causal) {
    dim3 grid((N + 127) / 128, M / 128, batch);
    cudaFuncSetAttribute(gemm_bf<OUTM>, cudaFuncAttributeMaxDynamicSharedMemorySize, SHM_BF);
    gemm_bf<OUTM><<<grid, 256, SHM_BF>>>(Ah, Al, lda, sA, Bh, Bl, ldb, sB,
                                         Cf, Ch, Cl, ldc, sC, N, K, causal);
}

// ---------------- reductions ----------------
__device__ __forceinline__ float warp_sum(float v) {
#pragma unroll
    for (int o = 16; o; o >>= 1) v += __shfl_xor_sync(0xffffffffu, v, o);
    return v;
}
__device__ __forceinline__ float warp_max(float v) {
#pragma unroll
    for (int o = 16; o; o >>= 1) v = fmaxf(v, __shfl_xor_sync(0xffffffffu, v, o));
    return v;
}

// ---------------- permute + split expand weights ----------------
// New row order: f' in [0,1536): interleaved (lin_j, pg_j) pairs;
// [1536,1600): qh rows (scaled by 1/sqrt(QK), zero-padded past 48);
// [1600,1664): kh rows (zero-padded past 48).
__global__ void permute_split_ew(const float* __restrict__ exp_w,
                                 __nv_bfloat16* __restrict__ h2,
                                 __nv_bfloat16* __restrict__ l2) {
    int rid = blockIdx.x;                 // 0 .. NBq*HPERM-1
    int blk = rid / HPERM, fp = rid % HPERM;
    int f = 0; bool valid; float scale = 1.0f;
    if (fp < 1536) {
        int j = fp >> 1;
        f = (fp & 1) ? (2 * QKd + Ed + j) : (2 * QKd + j);
        valid = true;
    } else if (fp < 1600) {
        int d = fp - 1536;
        valid = (d < QKd); f = d;
        scale = 0.14433756729740643f;     // 1/sqrt(48) folded into qh weights
    } else {
        int d = fp - 1600;
        valid = (d < QKd); f = QKd + d;
    }
    int tx = threadIdx.x;                 // 96 threads, float4 each
    float4 x = make_float4(0.f, 0.f, 0.f, 0.f);
    if (valid)
        x = reinterpret_cast<const float4*>(exp_w + ((size_t)blk * Hd + f) * Dd)[tx];
    x.x *= scale; x.y *= scale; x.z *= scale; x.w *= scale;
    __nv_bfloat162 ha = __floats2bfloat162_rn(x.x, x.y);
    __nv_bfloat162 hb = __floats2bfloat162_rn(x.z, x.w);
    __nv_bfloat162 la = __floats2bfloat162_rn(x.x - __bfloat162float(ha.x),
                                              x.y - __bfloat162float(ha.y));
    __nv_bfloat162 lb = __floats2bfloat162_rn(x.z - __bfloat162float(hb.x),
                                              x.w - __bfloat162float(hb.y));
    size_t o = ((size_t)blk * HPERM + fp) * Dd + tx * 4;
    *reinterpret_cast<__nv_bfloat162*>(h2 + o)     = ha;
    *reinterpret_cast<__nv_bfloat162*>(h2 + o + 2) = hb;
    *reinterpret_cast<__nv_bfloat162*>(l2 + o)     = la;
    *reinterpret_cast<__nv_bfloat162*>(l2 + o + 2) = lb;
}

// ---------------- weight split (proj): fp32 -> bf16 hi/lo ----------------
__global__ void split_w_kernel(const float4* __restrict__ src,
                               __nv_bfloat162* __restrict__ h2,
                               __nv_bfloat162* __restrict__ l2, int n4) {
    int i = blockIdx.x * 256 + threadIdx.x;
    if (i >= n4) return;
    float4 x = src[i];
    __nv_bfloat162 ha = __floats2bfloat162_rn(x.x, x.y);
    __nv_bfloat162 hb = __floats2bfloat162_rn(x.z, x.w);
    __nv_bfloat162 la = __floats2bfloat162_rn(x.x - __bfloat162float(ha.x),
                                              x.y - __bfloat162float(ha.y));
    __nv_bfloat162 lb = __floats2bfloat162_rn(x.z - __bfloat162float(hb.x),
                                              x.w - __bfloat162float(hb.y));
    h2[2 * i] = ha; h2[2 * i + 1] = hb;
    l2[2 * i] = la; l2[2 * i + 1] = lb;
}

// ---------------- embed (sin/cos) + LayerNorm (fp32 out) ----------------
__global__ void embed_ln_kernel(const int* __restrict__ q,
                                const float* __restrict__ freqs,
                                const float* __restrict__ g,
                                const float* __restrict__ b,
                                float* __restrict__ y) {
    int t = blockIdx.x;
    int tid = threadIdx.x;
    float qv = (float)q[t];
    float v[3];
#pragma unroll
    for (int k = 0; k < 3; k++) {
        int d = tid + k * 128;
        if (d < Dd / 2) v[k] = sinf(qv * freqs[d]);
        else            v[k] = cosf(qv * freqs[d - Dd / 2]);
    }
    float s = v[0] + v[1] + v[2];
    float sq = v[0]*v[0] + v[1]*v[1] + v[2]*v[2];
    s = warp_sum(s); sq = warp_sum(sq);
    __shared__ float shs[4], shq[4], mr[2];
    if ((tid & 31) == 0) { shs[tid >> 5] = s; shq[tid >> 5] = sq; }
    __syncthreads();
    if (tid == 0) {
        float ts = shs[0]+shs[1]+shs[2]+shs[3], tq = shq[0]+shq[1]+shq[2]+shq[3];
        float mean = ts * (1.0f / Dd);
        float var  = tq * (1.0f / Dd) - mean * mean;
        mr[0] = mean; mr[1] = rsqrtf(var + 1e-5f);
    }
    __syncthreads();
    float mean = mr[0], rstd = mr[1];
    float* yr = y + (size_t)t * Dd;
#pragma unroll
    for (int k = 0; k < 3; k++) {
        int d = tid + k * 128;
        yr[d] = (v[k] - mean) * rstd * g[d] + b[d];
    }
}

// ---------------- LayerNorm, fp32 out (final LN) ----------------
__global__ void ln_kernel(const float* __restrict__ x, float* __restrict__ y,
                          const float* __restrict__ g, const float* __restrict__ b) {
    int t = blockIdx.x;
    int tid = threadIdx.x;
    const float* xr = x + (size_t)t * Dd;
    float v0 = xr[tid], v1 = xr[tid + 128], v2 = xr[tid + 256];
    float s  = v0 + v1 + v2;
    float sq = v0*v0 + v1*v1 + v2*v2;
    s = warp_sum(s); sq = warp_sum(sq);
    __shared__ float shs[4], shq[4], mr[2];
    if ((tid & 31) == 0) { shs[tid >> 5] = s; shq[tid >> 5] = sq; }
    __syncthreads();
    if (tid == 0) {
        float ts = shs[0]+shs[1]+shs[2]+shs[3], tq = shq[0]+shq[1]+shq[2]+shq[3];
        float mean = ts * (1.0f / Dd);
        float var  = tq * (1.0f / Dd) - mean * mean;
        mr[0] = mean; mr[1] = rsqrtf(var + 1e-5f);
    }
    __syncthreads();
    float mean = mr[0], rstd = mr[1];
    float* yr = y + (size_t)t * Dd;
    yr[tid]       = (v0 - mean) * rstd * g[tid]       + b[tid];
    yr[tid + 128] = (v1 - mean) * rstd * g[tid + 128] + b[tid + 128];
    yr[tid + 256] = (v2 - mean) * rstd * g[tid + 256] + b[tid + 256];
}

// ---------------- LayerNorm, bf16 hi/lo out (per-block LN) ----------------
__global__ void ln_bf16_kernel(const float* __restrict__ x,
                               __nv_bfloat16* __restrict__ yh,
                               __nv_bfloat16* __restrict__ yl,
                               const float* __restrict__ g,
                               const float* __restrict__ b) {
    int t = blockIdx.x;
    int tid = threadIdx.x;
    const float* xr = x + (size_t)t * Dd;
    float v0 = xr[tid], v1 = xr[tid + 128], v2 = xr[tid + 256];
    float s  = v0 + v1 + v2;
    float sq = v0*v0 + v1*v1 + v2*v2;
    s = warp_sum(s); sq = warp_sum(sq);
    __shared__ float shs[4], shq[4], mr[2];
    if ((tid & 31) == 0) { shs[tid >> 5] = s; shq[tid >> 5] = sq; }
    __syncthreads();
    if (tid == 0) {
        float ts = shs[0]+shs[1]+shs[2]+shs[3], tq = shq[0]+shq[1]+shq[2]+shq[3];
        float mean = ts * (1.0f / Dd);
        float var  = tq * (1.0f / Dd) - mean * mean;
        mr[0] = mean; mr[1] = rsqrtf(var + 1e-5f);
    }
    __syncthreads();
    float mean = mr[0], rstd = mr[1];
    size_t rb = (size_t)t * Dd;
#pragma unroll
    for (int k = 0; k < 3; k++) {
        int d = tid + k * 128;
        float vv = (k == 0 ? v0 : (k == 1 ? v1 : v2));
        float y = (vv - mean) * rstd * g[d] + b[d];
        __nv_bfloat16 hh, ll;
        split1(y, hh, ll);
        yh[rb + d] = hh; yl[rb + d] = ll;
    }
}

// ---------------- causal softmax: fp32 scores -> bf16 hi/lo probs ----------
// scores already pre-scaled by 1/sqrt(QK) via qh weight scaling.
__global__ void softmax_kernel(const float* __restrict__ p,
                               __nv_bfloat16* __restrict__ ph,
                               __nv_bfloat16* __restrict__ pl) {
    int i = blockIdx.x;
    int b = blockIdx.y;
    size_t off = ((size_t)b * Sq + i) * Sq;
    const float* row = p + off;
    int L = i + 1;
    int zend = ((i >> 7) + 1) << 7;
    int tid = threadIdx.x;   // 256
    __shared__ float sh[8];

    float m = -3.0e38f;
    float rv[8];
#pragma unroll
    for (int k = 0; k < 8; k++) {
        int j = tid + k * 256;
        rv[k] = (j < L) ? row[j] : -3.0e38f;
        m = fmaxf(m, rv[k]);
    }
    m = warp_max(m);
    if ((tid & 31) == 0) sh[tid >> 5] = m;
    __syncthreads();
    float mm = sh[0];
#pragma unroll
    for (int k = 1; k < 8; k++) mm = fmaxf(mm, sh[k]);
    __syncthreads();

    float sum = 0.0f;
#pragma unroll
    for (int k = 0; k < 8; k++) {
        int j = tid + k * 256;
        if (j < L) { rv[k] = __expf(rv[k] - mm); sum += rv[k]; }
    }
    sum = warp_sum(sum);
    if ((tid & 31) == 0) sh[tid >> 5] = sum;
    __syncthreads();
    float tot = sh[0];
#pragma unroll
    for (int k = 1; k < 8; k++) tot += sh[k];
    float inv = 1.0f / tot;

#pragma unroll
    for (int k = 0; k < 8; k++) {
        int j = tid + k * 256;
        if (j < zend) {
            float e = (j < L) ? rv[k] * inv : 0.0f;
            __nv_bfloat16 hh, ll;
            split1(e, hh, ll);
            ph[off + j] = hh; pl[off + j] = ll;
        }
    }
}

// ---------------- SIMT SGEMM (logits only): C = A(MxK) * B(NxK)^T ----------
__global__ void __launch_bounds__(256, 2)
gemm_simt(const float* __restrict__ A, int lda,
          const float* __restrict__ B, int ldb,
          float* __restrict__ C, int ldc, int N, int K) {
    int bm = blockIdx.y * 128;
    int bn = blockIdx.x * 128;

    __shared__ float As[8][128];
    __shared__ float Bs[8][128];
    int tid = threadIdx.x;
    int tx = tid & 15, ty = tid >> 4;
    float acc[8][8] = {};

    int lrow = tid >> 1;
    int lkk  = (tid & 1) * 4;
    const float* Ap = A + (size_t)(bm + lrow) * lda + lkk;
    bool bvalid = (bn + lrow) < N;
    const float* Bp = B + (size_t)(bn + lrow) * ldb + lkk;

    for (int k0 = 0; k0 < K; k0 += 8) {
        float4 av = *reinterpret_cast<const float4*>(Ap + k0);
        float4 bv = bvalid ? *reinterpret_cast<const float4*>(Bp + k0)
                           : make_float4(0.f, 0.f, 0.f, 0.f);
        As[lkk+0][lrow]=av.x; As[lkk+1][lrow]=av.y; As[lkk+2][lrow]=av.z; As[lkk+3][lrow]=av.w;
        Bs[lkk+0][lrow]=bv.x; Bs[lkk+1][lrow]=bv.y; Bs[lkk+2][lrow]=bv.z; Bs[lkk+3][lrow]=bv.w;
        __syncthreads();
#pragma unroll
        for (int kk = 0; kk < 8; kk++) {
            float a[8], b[8];
            *reinterpret_cast<float4*>(&a[0]) = *reinterpret_cast<const float4*>(&As[kk][ty*8]);
            *reinterpret_cast<float4*>(&a[4]) = *reinterpret_cast<const float4*>(&As[kk][ty*8+4]);
            *reinterpret_cast<float4*>(&b[0]) = *reinterpret_cast<const float4*>(&Bs[kk][tx*8]);
            *reinterpret_cast<float4*>(&b[4]) = *reinterpret_cast<const float4*>(&Bs[kk][tx*8+4]);
#pragma unroll
            for (int i = 0; i < 8; i++)
#pragma unroll
                for (int j = 0; j < 8; j++)
                    acc[i][j] += a[i] * b[j];
        }
        __syncthreads();
    }
#pragma unroll
    for (int i = 0; i < 8; i++) {
        float* Crow = C + (size_t)(bm + ty * 8 + i) * ldc;
#pragma unroll
        for (int j = 0; j < 8; j++) {
            int n = bn + tx * 8 + j;
            if (n < N) Crow[n] = acc[i][j];
        }
    }
}

// ---------------- driver ----------------
extern "C" void kernel_launch(void* const* d_in, const int* in_sizes, int n_in,
                              void* d_out, int out_size) {
    const int*   q      = (const int*)  d_in[0];
    const float* freqs  = (const float*)d_in[1];
    const float* exp_w  = (const float*)d_in[2];   // (8, 1632, 384)
    const float* proj_w = (const float*)d_in[3];   // (8, 384, 768)
    const float* blk_g  = (const float*)d_in[4];
    const float* blk_b  = (const float*)d_in[5];
    const float* ln_g   = (const float*)d_in[6];
    const float* ln_b   = (const float*)d_in[7];
    const float* out_w  = (const float*)d_in[8];   // (100, 384)
    float* out = (float*)d_out;

    float *x, *xn, *p;
    __nv_bfloat16 *xnh, *xnl, *cath, *catl, *vth, *vtl, *ph, *pl;
    __nv_bfloat16 *qh, *ql, *kh, *kl, *ewh, *ewl, *pwh, *pwl;
    cudaGetSymbolAddress((void**)&x,    g_x);
    cudaGetSymbolAddress((void**)&xn,   g_xn);
    cudaGetSymbolAddress((void**)&p,    g_p);
    cudaGetSymbolAddress((void**)&xnh,  g_xnh);  cudaGetSymbolAddress((void**)&xnl,  g_xnl);
    cudaGetSymbolAddress((void**)&cath, g_cath); cudaGetSymbolAddress((void**)&catl, g_catl);
    cudaGetSymbolAddress((void**)&vth,  g_vth);  cudaGetSymbolAddress((void**)&vtl,  g_vtl);
    cudaGetSymbolAddress((void**)&ph,   g_ph);   cudaGetSymbolAddress((void**)&pl,   g_pl);
    cudaGetSymbolAddress((void**)&qh,   g_qh);   cudaGetSymbolAddress((void**)&ql,   g_ql);
    cudaGetSymbolAddress((void**)&kh,   g_kh);   cudaGetSymbolAddress((void**)&kl,   g_kl);
    cudaGetSymbolAddress((void**)&ewh,  g_ewh);  cudaGetSymbolAddress((void**)&ewl,  g_ewl);
    cudaGetSymbolAddress((void**)&pwh,  g_pwh);  cudaGetSymbolAddress((void**)&pwl,  g_pwl);

    // pre-permute/split weights (once per launch)
    permute_split_ew<<<NBq * HPERM, 96>>>(exp_w, ewh, ewl);
    {
        int n4p = NBq * Dd * Ed / 4;
        split_w_kernel<<<(n4p + 255) / 256, 256>>>(
            (const float4*)proj_w, (__nv_bfloat162*)pwh, (__nv_bfloat162*)pwl, n4p);
    }

    embed_ln_kernel<<<Tq, 128>>>(q, freqs, ln_g, ln_b, x);

    for (int blk = 0; blk < NBq; blk++) {
        ln_bf16_kernel<<<Tq, 128>>>(x, xnh, xnl, blk_g + blk * Dd, blk_b + blk * Dd);

        // expand GEMM with fused geglu / qk-split / V^T epilogue
        gemm_bf_launch<3>(xnh, xnl, Dd, 0,
                          ewh + (size_t)blk * HPERM * Dd, ewl + (size_t)blk * HPERM * Dd, Dd, 0,
                          nullptr, nullptr, nullptr, 0, 0,
                          Tq, HPERM, Dd, 1, 0);

        // scores: qh @ kh^T per batch (pre-scaled, K padded to 64), causal skip
        gemm_bf_launch<0>(qh, ql, 64, (long long)Sq * 64,
                          kh, kl, 64, (long long)Sq * 64,
                          p, nullptr, nullptr, Sq, (long long)Sq * Sq,
                          Sq, Sq, 64, Bq, 1);

        softmax_kernel<<<dim3(Sq, Bq), 256>>>(p, ph, pl);

        // attn = P @ V -> cat[:, 384:768] as bf16 hi/lo; K capped causally
        gemm_bf_launch<2>(ph, pl, Sq, (long long)Sq * Sq,
                          vth, vtl, Sq, (long long)Dd * Sq,
                          nullptr, cath + Dd, catl + Dd, Ed, (long long)Sq * Ed,
                          Sq, Dd, Sq, Bq, 2);

        // x += cat @ proj_w[blk]^T
        gemm_bf_launch<1>(cath, catl, Ed, 0,
                          pwh + (size_t)blk * Dd * Ed, pwl + (size_t)blk * Dd * Ed, Ed, 0,
                          x, nullptr, nullptr, Dd, 0,
                          Tq, Dd, Ed, 1, 0);
    }

    ln_kernel<<<Tq, 128>>>(x, xn, ln_g, ln_b);
    gemm_simt<<<dim3(1, Tq / 128), 256>>>(xn, Dd, out_w, Dd, out, VOCABq, VOCABq, Dd);
}

// round 13
// speedup vs baseline: 1.2563x; 1.0135x over previous
#include <cuda_runtime.h>
#include <cuda_bf16.h>
#include <cstdint>

// ---------------- problem constants ----------------
#define Bq      4
#define Sq      2048
#define Tq      (Bq * Sq)      // 8192 tokens
#define Dd      384
#define QKd     48
#define Ed      768
#define Hd      1632           // 2*QK + 2*E
#define HPERM   1664           // permuted expand width: 1536 pairs + 64 qh + 64 kh
#define NBq     8
#define VOCABq  100

// ---------------- scratch (static device globals; no cudaMalloc) -----------
__device__ float g_x[Tq * Dd];                        // residual stream
__device__ float g_xn[Tq * Dd];                       // final-LN output (fp32)
__device__ float g_p[(size_t)Bq * Sq * Sq];           // raw scores fp32

#define AL16 __align__(16)
__device__ AL16 __nv_bfloat16 g_xnh[Tq * Dd],  g_xnl[Tq * Dd];
__device__ AL16 __nv_bfloat16 g_cath[(size_t)Tq * Ed], g_catl[(size_t)Tq * Ed];
__device__ AL16 __nv_bfloat16 g_vth[(size_t)Bq * Dd * Sq], g_vtl[(size_t)Bq * Dd * Sq];
__device__ AL16 __nv_bfloat16 g_ph[(size_t)Bq * Sq * Sq],  g_pl[(size_t)Bq * Sq * Sq];
__device__ AL16 __nv_bfloat16 g_qh[Tq * 64], g_ql[Tq * 64];   // qh padded K=64 (pre-scaled)
__device__ AL16 __nv_bfloat16 g_kh[Tq * 64], g_kl[Tq * 64];   // kh padded K=64
__device__ AL16 __nv_bfloat16 g_ewh[(size_t)NBq * HPERM * Dd], g_ewl[(size_t)NBq * HPERM * Dd];
__device__ AL16 __nv_bfloat16 g_pwh[NBq * Dd * Ed], g_pwl[NBq * Dd * Ed];

// ================= low-level helpers =================
__device__ __forceinline__ uint32_t s2u(const void* p) {
    uint32_t a;
    asm("{ .reg .u64 t; cvta.to.shared.u64 t, %1; cvt.u32.u64 %0, t; }" : "=r"(a) : "l"(p));
    return a;
}
__device__ __forceinline__ void cpa16(uint32_t dst, const void* src, uint32_t sz) {
    asm volatile("cp.async.cg.shared.global [%0], [%1], 16, %2;"
                 :: "r"(dst), "l"(src), "r"(sz) : "memory");
}
__device__ __forceinline__ void cpa_commit() {
    asm volatile("cp.async.commit_group;" ::: "memory");
}
template <int NN>
__device__ __forceinline__ void cpa_wait() {
    asm volatile("cp.async.wait_group %0;" :: "n"(NN) : "memory");
}
__device__ __forceinline__ uint32_t swz(uint32_t off) { return off ^ ((off >> 3) & 0x70); }

__device__ __forceinline__ void ldm_x4(uint32_t addr, uint32_t* r) {
    asm volatile("ldmatrix.sync.aligned.m8n8.x4.shared.b16 {%0,%1,%2,%3}, [%4];"
                 : "=r"(r[0]), "=r"(r[1]), "=r"(r[2]), "=r"(r[3]) : "r"(addr));
}
__device__ __forceinline__ void mma16816(float* c, const uint32_t* a, const uint32_t* b) {
    asm volatile("mma.sync.aligned.m16n8k16.row.col.f32.bf16.bf16.f32 "
                 "{%0,%1,%2,%3}, {%4,%5,%6,%7}, {%8,%9}, {%0,%1,%2,%3};"
                 : "+f"(c[0]), "+f"(c[1]), "+f"(c[2]), "+f"(c[3])
                 : "r"(a[0]), "r"(a[1]), "r"(a[2]), "r"(a[3]), "r"(b[0]), "r"(b[1]));
}
__device__ __forceinline__ void split1(float v, __nv_bfloat16& h, __nv_bfloat16& l) {
    h = __float2bfloat16_rn(v);
    l = __float2bfloat16_rn(v - __bfloat162float(h));
}

// ================= bf16 HMMA GEMM: C = A(MxK) * B(NxK)^T, 3-term split =====
// 128x128 CTA tile, BK=64, 16 warps (4Mx4N, warp tile 32x32), cp.async
// 3-stage pipeline, reg acc. 512 threads: 4 warps per SMSP for latency hiding.
// causal: 0=none, 1=skip bn>bm, 2=cap K at bm+128. M-order flipped when causal.
// OUTM: 0 = fp32 store, 1 = fp32 add, 2 = bf16 hi/lo store,
//       3 = fused expand epilogue (geglu->cat/V^T, qk split) via device globals.
#define BTILE   16384                   // 128 rows x 64 bf16 x 2B
#define STAGE_B (4 * BTILE)             // Ah, Al, Bh, Bl = 64 KB
#define NSTAGE  3
#define SHM_BF  (NSTAGE * STAGE_B + 128)
#define NTHR    512

template <int OUTM>
__global__ void __launch_bounds__(NTHR, 1)
gemm_bf(const __nv_bfloat16* __restrict__ Ah_, const __nv_bfloat16* __restrict__ Al_,
        int lda, long long sA,
        const __nv_bfloat16* __restrict__ Bh_, const __nv_bfloat16* __restrict__ Bl_,
        int ldb, long long sB,
        float* __restrict__ Cf,
        __nv_bfloat16* __restrict__ Ch, __nv_bfloat16* __restrict__ Cl,
        int ldc, long long sC, int N, int K, int causal) {
    int my = (causal != 0) ? ((int)gridDim.y - 1 - (int)blockIdx.y) : (int)blockIdx.y;
    int bm = my * 128;
    int bn = blockIdx.x * 128;
    if (causal == 1 && bn > bm) return;
    int Keff = (causal == 2) ? ((bm + 128 < K) ? bm + 128 : K) : K;
    int nch = Keff >> 6;

    const __nv_bfloat16* Ah = Ah_ + (long long)blockIdx.z * sA;
    const __nv_bfloat16* Al = Al_ + (long long)blockIdx.z * sA;
    const __nv_bfloat16* Bh = Bh_ + (long long)blockIdx.z * sB;
    const __nv_bfloat16* Bl = Bl_ + (long long)blockIdx.z * sB;

    extern __shared__ char dsm[];
    uint32_t base = (s2u(dsm) + 127u) & ~127u;

    int tid = threadIdx.x;
    int wid = tid >> 5, lane = tid & 31;
    int m0w = (wid >> 2) * 32;      // 4 warps in M, 32 rows each
    int n0w = (wid & 3) * 32;       // 4 warps in N, 32 cols each

    int lrow = tid >> 3;       // 0..63
    int lu   = tid & 7;        // 0..7

    float acc[2][4][4];
#pragma unroll
    for (int i = 0; i < 2; i++)
#pragma unroll
        for (int j = 0; j < 4; j++)
#pragma unroll
            for (int e = 0; e < 4; e++) acc[i][j][e] = 0.0f;

    uint32_t a_row  = (uint32_t)(lane & 15);
    uint32_t a_colb = (uint32_t)((lane >> 4) * 16);
    uint32_t b_row  = (uint32_t)(((lane >> 4) << 3) + (lane & 7));
    uint32_t b_colb = (uint32_t)(((lane >> 3) & 1) * 16);

    auto load_chunk = [&](int ch, int bsel) {
        int k0 = ch << 6;
        uint32_t tb = base + (uint32_t)bsel * STAGE_B;
#pragma unroll
        for (int i = 0; i < 2; i++) {
            int row = lrow + i * 64;
            uint32_t soff = swz((uint32_t)row * 128u + (uint32_t)lu * 16u);
            size_t aoff = (size_t)(bm + row) * lda + k0 + lu * 8;
            cpa16(tb + soff,             Ah + aoff, 16u);
            cpa16(tb + BTILE + soff,     Al + aoff, 16u);
            uint32_t bsz = ((bn + row) < N) ? 16u : 0u;
            size_t boff = (size_t)(bn + row) * ldb + k0 + lu * 8;
            cpa16(tb + 2 * BTILE + soff, Bh + boff, bsz);
            cpa16(tb + 3 * BTILE + soff, Bl + boff, bsz);
        }
    };

    auto compute = [&](int bsel) {
        uint32_t tb  = base + (uint32_t)bsel * STAGE_B;
        uint32_t tAh = tb, tAl = tb + BTILE, tBh = tb + 2 * BTILE, tBl = tb + 3 * BTILE;
#pragma unroll
        for (int ks = 0; ks < 4; ks++) {
            uint32_t kbyte = (uint32_t)ks * 32u;
            uint32_t afrag[2][4], bhfrag[2][4], blfrag[2][4];
#pragma unroll
            for (int mt = 0; mt < 2; mt++) {
                uint32_t rr = (uint32_t)(m0w + mt * 16) + a_row;
                ldm_x4(tAh + swz(rr * 128u + kbyte + a_colb), afrag[mt]);
            }
#pragma unroll
            for (int bt = 0; bt < 2; bt++) {
                uint32_t rr = (uint32_t)(n0w + bt * 16) + b_row;
                uint32_t off = swz(rr * 128u + kbyte + b_colb);
                ldm_x4(tBh + off, bhfrag[bt]);
                ldm_x4(tBl + off, blfrag[bt]);
            }
            // term 1: Ahi*Bhi
#pragma unroll
            for (int mt = 0; mt < 2; mt++)
#pragma unroll
                for (int nt = 0; nt < 4; nt++)
                    mma16816(acc[mt][nt], afrag[mt], &bhfrag[nt >> 1][(nt & 1) * 2]);
            // term 2: Ahi*Blo
#pragma unroll
            for (int mt = 0; mt < 2; mt++)
#pragma unroll
                for (int nt = 0; nt < 4; nt++)
                    mma16816(acc[mt][nt], afrag[mt], &blfrag[nt >> 1][(nt & 1) * 2]);
            // term 3: Alo*Bhi (reload A frags as lo)
#pragma unroll
            for (int mt = 0; mt < 2; mt++) {
                uint32_t rr = (uint32_t)(m0w + mt * 16) + a_row;
                ldm_x4(tAl + swz(rr * 128u + kbyte + a_colb), afrag[mt]);
            }
#pragma unroll
            for (int mt = 0; mt < 2; mt++)
#pragma unroll
                for (int nt = 0; nt < 4; nt++)
                    mma16816(acc[mt][nt], afrag[mt], &bhfrag[nt >> 1][(nt & 1) * 2]);
        }
    };

    int issued = 0;
    if (issued < nch) { load_chunk(issued, issued % NSTAGE); cpa_commit(); issued++; }
    if (issued < nch) { load_chunk(issued, issued % NSTAGE); cpa_commit(); issued++; }
    for (int ch = 0; ch < nch; ch++) {
        if (issued < nch) { load_chunk(issued, issued % NSTAGE); cpa_commit(); issued++; }
        int pending = issued - ch - 1;
        if (pending >= 2)      cpa_wait<2>();
        else if (pending == 1) cpa_wait<1>();
        else                   cpa_wait<0>();
        __syncthreads();
        compute(ch % NSTAGE);
        __syncthreads();
    }

    // ---------------- epilogue ----------------
    if (OUTM == 3) {
        // stage acc tile (128x128 fp32) in smem, then coalesced
        // geglu / qk-split / V^T stores via device globals.
        float* sf = reinterpret_cast<float*>((((uintptr_t)dsm) + 127) & ~(uintptr_t)127);
        const int LDS = 132;
#pragma unroll
        for (int mt = 0; mt < 2; mt++) {
            int r0 = m0w + mt * 16 + (lane >> 2);
#pragma unroll
            for (int nt = 0; nt < 4; nt++) {
                int c = n0w + nt * 8 + (lane & 3) * 2;
#pragma unroll
                for (int half = 0; half < 2; half++) {
                    int r = r0 + half * 8;
                    sf[r * LDS + c]     = acc[mt][nt][half * 2];
                    sf[r * LDS + c + 1] = acc[mt][nt][half * 2 + 1];
                }
            }
        }
        __syncthreads();
        if (bn < 1536) {
            int jbase = bn >> 1;                 // 0..767
            bool isV = (jbase >= 384);
            if (!isV) {
#pragma unroll
                for (int i = 0; i < 16; i++) {
                    int vi = tid + i * NTHR;     // 8192 values
                    int row = vi >> 6, u = vi & 63;
                    float lin = sf[row * LDS + 2 * u];
                    float pg  = sf[row * LDS + 2 * u + 1];
                    float val = lin * 0.5f * pg * (1.0f + erff(pg * 0.70710678118654752f));
                    __nv_bfloat16 hh, ll; split1(val, hh, ll);
                    size_t idx = (size_t)(bm + row) * Ed + jbase + u;
                    g_cath[idx] = hh; g_catl[idx] = ll;
                }
            } else {
#pragma unroll
                for (int i = 0; i < 16; i++) {
                    int vi = tid + i * NTHR;
                    int row = vi & 127, u = vi >> 7;   // s-contiguous for V^T
                    float lin = sf[row * LDS + 2 * u];
                    float pg  = sf[row * LDS + 2 * u + 1];
                    float val = lin * 0.5f * pg * (1.0f + erff(pg * 0.70710678118654752f));
                    __nv_bfloat16 hh, ll; split1(val, hh, ll);
                    int t = bm + row;
                    int jj = jbase + u - 384;
                    size_t idx = ((size_t)(t >> 11) * Dd + jj) * Sq + (t & (Sq - 1));
                    g_vth[idx] = hh; g_vtl[idx] = ll;
                }
            }
        } else {
#pragma unroll
            for (int i = 0; i < 32; i++) {
                int vi = tid + i * NTHR;         // 16384 values
                int row = vi >> 7, c = vi & 127;
                float val = sf[row * LDS + c];
                __nv_bfloat16 hh, ll; split1(val, hh, ll);
                size_t idx = (size_t)(bm + row) * 64 + (c & 63);
                if (c < 64) { g_qh[idx] = hh; g_ql[idx] = ll; }
                else        { g_kh[idx] = hh; g_kl[idx] = ll; }
            }
        }
        return;
    }

    float* CfB = (OUTM != 2) ? Cf + (long long)blockIdx.z * sC : nullptr;
    __nv_bfloat16* ChB = (OUTM == 2) ? Ch + (long long)blockIdx.z * sC : nullptr;
    __nv_bfloat16* ClB = (OUTM == 2) ? Cl + (long long)blockIdx.z * sC : nullptr;
#pragma unroll
    for (int mt = 0; mt < 2; mt++) {
        int row0 = bm + m0w + mt * 16 + (lane >> 2);
#pragma unroll
        for (int nt = 0; nt < 4; nt++) {
            int col = bn + n0w + nt * 8 + (lane & 3) * 2;
            float* c = acc[mt][nt];
#pragma unroll
            for (int half = 0; half < 2; half++) {
                int row = row0 + half * 8;
                float v0 = c[half * 2], v1 = c[half * 2 + 1];
                if (OUTM == 2) {
                    if (col + 1 < N) {
                        __nv_bfloat16 h0, l0, h1, l1;
                        split1(v0, h0, l0); split1(v1, h1, l1);
                        __nv_bfloat162 hv; hv.x = h0; hv.y = h1;
                        __nv_bfloat162 lv; lv.x = l0; lv.y = l1;
                        *reinterpret_cast<__nv_bfloat162*>(ChB + (size_t)row * ldc + col) = hv;
                        *reinterpret_cast<__nv_bfloat162*>(ClB + (size_t)row * ldc + col) = lv;
                    }
                } else {
                    float* Crow = CfB + (size_t)row * ldc;
                    if (col + 1 < N) {
                        float2 cv;
                        if (OUTM == 1) {
                            cv = *reinterpret_cast<float2*>(Crow + col);
                            cv.x += v0; cv.y += v1;
                        } else cv = make_float2(v0, v1);
                        *reinterpret_cast<float2*>(Crow + col) = cv;
                    } else if (col < N) {
                        Crow[col] = (OUTM == 1) ? (Crow[col] + v0) : v0;
                    }
                }
            }
        }
    }
}

template <int OUTM>
static inline void gemm_bf_launch(const __nv_bfloat16* Ah, const __nv_bfloat16* Al,
                                  int lda, long long sA,
                                  const __nv_bfloat16* Bh, const __nv_bfloat16* Bl,
                                  int ldb, long long sB,
                                  float* Cf, __nv_bfloat16* Ch, __nv_bfloat16* Cl,
                                  int ldc, long long sC,
                                  int M, int N, int K, int batch, int causal) {
    dim3 grid((N + 127) / 128, M / 128, batch);
    cudaFuncSetAttribute(gemm_bf<OUTM>, cudaFuncAttributeMaxDynamicSharedMemorySize, SHM_BF);
    gemm_bf<OUTM><<<grid, NTHR, SHM_BF>>>(Ah, Al, lda, sA, Bh, Bl, ldb, sB,
                                          Cf, Ch, Cl, ldc, sC, N, K, causal);
}

// ---------------- reductions ----------------
__device__ __forceinline__ float warp_sum(float v) {
#pragma unroll
    for (int o = 16; o; o >>= 1) v += __shfl_xor_sync(0xffffffffu, v, o);
    return v;
}
__device__ __forceinline__ float warp_max(float v) {
#pragma unroll
    for (int o = 16; o; o >>= 1) v = fmaxf(v, __shfl_xor_sync(0xffffffffu, v, o));
    return v;
}

// ---------------- permute + split expand weights ----------------
__global__ void permute_split_ew(const float* __restrict__ exp_w,
                                 __nv_bfloat16* __restrict__ h2,
                                 __nv_bfloat16* __restrict__ l2) {
    int rid = blockIdx.x;                 // 0 .. NBq*HPERM-1
    int blk = rid / HPERM, fp = rid % HPERM;
    int f = 0; bool valid; float scale = 1.0f;
    if (fp < 1536) {
        int j = fp >> 1;
        f = (fp & 1) ? (2 * QKd + Ed + j) : (2 * QKd + j);
        valid = true;
    } else if (fp < 1600) {
        int d = fp - 1536;
        valid = (d < QKd); f = d;
        scale = 0.14433756729740643f;     // 1/sqrt(48) folded into qh weights
    } else {
        int d = fp - 1600;
        valid = (d < QKd); f = QKd + d;
    }
    int tx = threadIdx.x;                 // 96 threads, float4 each
    float4 x = make_float4(0.f, 0.f, 0.f, 0.f);
    if (valid)
        x = reinterpret_cast<const float4*>(exp_w + ((size_t)blk * Hd + f) * Dd)[tx];
    x.x *= scale; x.y *= scale; x.z *= scale; x.w *= scale;
    __nv_bfloat162 ha = __floats2bfloat162_rn(x.x, x.y);
    __nv_bfloat162 hb = __floats2bfloat162_rn(x.z, x.w);
    __nv_bfloat162 la = __floats2bfloat162_rn(x.x - __bfloat162float(ha.x),
                                              x.y - __bfloat162float(ha.y));
    __nv_bfloat162 lb = __floats2bfloat162_rn(x.z - __bfloat162float(hb.x),
                                              x.w - __bfloat162float(hb.y));
    size_t o = ((size_t)blk * HPERM + fp) * Dd + tx * 4;
    *reinterpret_cast<__nv_bfloat162*>(h2 + o)     = ha;
    *reinterpret_cast<__nv_bfloat162*>(h2 + o + 2) = hb;
    *reinterpret_cast<__nv_bfloat162*>(l2 + o)     = la;
    *reinterpret_cast<__nv_bfloat162*>(l2 + o + 2) = lb;
}

// ---------------- weight split (proj): fp32 -> bf16 hi/lo ----------------
__global__ void split_w_kernel(const float4* __restrict__ src,
                               __nv_bfloat162* __restrict__ h2,
                               __nv_bfloat162* __restrict__ l2, int n4) {
    int i = blockIdx.x * 256 + threadIdx.x;
    if (i >= n4) return;
    float4 x = src[i];
    __nv_bfloat162 ha = __floats2bfloat162_rn(x.x, x.y);
    __nv_bfloat162 hb = __floats2bfloat162_rn(x.z, x.w);
    __nv_bfloat162 la = __floats2bfloat162_rn(x.x - __bfloat162float(ha.x),
                                              x.y - __bfloat162float(ha.y));
    __nv_bfloat162 lb = __floats2bfloat162_rn(x.z - __bfloat162float(hb.x),
                                              x.w - __bfloat162float(hb.y));
    h2[2 * i] = ha; h2[2 * i + 1] = hb;
    l2[2 * i] = la; l2[2 * i + 1] = lb;
}

// ---------------- embed (sin/cos) + LayerNorm (fp32 out) ----------------
__global__ void embed_ln_kernel(const int* __restrict__ q,
                                const float* __restrict__ freqs,
                                const float* __restrict__ g,
                                const float* __restrict__ b,
                                float* __restrict__ y) {
    int t = blockIdx.x;
    int tid = threadIdx.x;
    float qv = (float)q[t];
    float v[3];
#pragma unroll
    for (int k = 0; k < 3; k++) {
        int d = tid + k * 128;
        if (d < Dd / 2) v[k] = sinf(qv * freqs[d]);
        else            v[k] = cosf(qv * freqs[d - Dd / 2]);
    }
    float s = v[0] + v[1] + v[2];
    float sq = v[0]*v[0] + v[1]*v[1] + v[2]*v[2];
    s = warp_sum(s); sq = warp_sum(sq);
    __shared__ float shs[4], shq[4], mr[2];
    if ((tid & 31) == 0) { shs[tid >> 5] = s; shq[tid >> 5] = sq; }
    __syncthreads();
    if (tid == 0) {
        float ts = shs[0]+shs[1]+shs[2]+shs[3], tq = shq[0]+shq[1]+shq[2]+shq[3];
        float mean = ts * (1.0f / Dd);
        float var  = tq * (1.0f / Dd) - mean * mean;
        mr[0] = mean; mr[1] = rsqrtf(var + 1e-5f);
    }
    __syncthreads();
    float mean = mr[0], rstd = mr[1];
    float* yr = y + (size_t)t * Dd;
#pragma unroll
    for (int k = 0; k < 3; k++) {
        int d = tid + k * 128;
        yr[d] = (v[k] - mean) * rstd * g[d] + b[d];
    }
}

// ---------------- LayerNorm, fp32 out (final LN) ----------------
__global__ void ln_kernel(const float* __restrict__ x, float* __restrict__ y,
                          const float* __restrict__ g, const float* __restrict__ b) {
    int t = blockIdx.x;
    int tid = threadIdx.x;
    const float* xr = x + (size_t)t * Dd;
    float v0 = xr[tid], v1 = xr[tid + 128], v2 = xr[tid + 256];
    float s  = v0 + v1 + v2;
    float sq = v0*v0 + v1*v1 + v2*v2;
    s = warp_sum(s); sq = warp_sum(sq);
    __shared__ float shs[4], shq[4], mr[2];
    if ((tid & 31) == 0) { shs[tid >> 5] = s; shq[tid >> 5] = sq; }
    __syncthreads();
    if (tid == 0) {
        float ts = shs[0]+shs[1]+shs[2]+shs[3], tq = shq[0]+shq[1]+shq[2]+shq[3];
        float mean = ts * (1.0f / Dd);
        float var  = tq * (1.0f / Dd) - mean * mean;
        mr[0] = mean; mr[1] = rsqrtf(var + 1e-5f);
    }
    __syncthreads();
    float mean = mr[0], rstd = mr[1];
    float* yr = y + (size_t)t * Dd;
    yr[tid]       = (v0 - mean) * rstd * g[tid]       + b[tid];
    yr[tid + 128] = (v1 - mean) * rstd * g[tid + 128] + b[tid + 128];
    yr[tid + 256] = (v2 - mean) * rstd * g[tid + 256] + b[tid + 256];
}

// ---------------- LayerNorm, bf16 hi/lo out (per-block LN) ----------------
__global__ void ln_bf16_kernel(const float* __restrict__ x,
                               __nv_bfloat16* __restrict__ yh,
                               __nv_bfloat16* __restrict__ yl,
                               const float* __restrict__ g,
                               const float* __restrict__ b) {
    int t = blockIdx.x;
    int tid = threadIdx.x;
    const float* xr = x + (size_t)t * Dd;
    float v0 = xr[tid], v1 = xr[tid + 128], v2 = xr[tid + 256];
    float s  = v0 + v1 + v2;
    float sq = v0*v0 + v1*v1 + v2*v2;
    s = warp_sum(s); sq = warp_sum(sq);
    __shared__ float shs[4], shq[4], mr[2];
    if ((tid & 31) == 0) { shs[tid >> 5] = s; shq[tid >> 5] = sq; }
    __syncthreads();
    if (tid == 0) {
        float ts = shs[0]+shs[1]+shs[2]+shs[3], tq = shq[0]+shq[1]+shq[2]+shq[3];
        float mean = ts * (1.0f / Dd);
        float var  = tq * (1.0f / Dd) - mean * mean;
        mr[0] = mean; mr[1] = rsqrtf(var + 1e-5f);
    }
    __syncthreads();
    float mean = mr[0], rstd = mr[1];
    size_t rb = (size_t)t * Dd;
#pragma unroll
    for (int k = 0; k < 3; k++) {
        int d = tid + k * 128;
        float vv = (k == 0 ? v0 : (k == 1 ? v1 : v2));
        float y = (vv - mean) * rstd * g[d] + b[d];
        __nv_bfloat16 hh, ll;
        split1(y, hh, ll);
        yh[rb + d] = hh; yl[rb + d] = ll;
    }
}

// ---------------- causal softmax: fp32 scores -> bf16 hi/lo probs ----------
__global__ void softmax_kernel(const float* __restrict__ p,
                               __nv_bfloat16* __restrict__ ph,
                               __nv_bfloat16* __restrict__ pl) {
    int i = blockIdx.x;
    int b = blockIdx.y;
    size_t off = ((size_t)b * Sq + i) * Sq;
    const float* row = p + off;
    int L = i + 1;
    int zend = ((i >> 7) + 1) << 7;
    int tid = threadIdx.x;   // 256
    __shared__ float sh[8];

    float m = -3.0e38f;
    float rv[8];
#pragma unroll
    for (int k = 0; k < 8; k++) {
        int j = tid + k * 256;
        rv[k] = (j < L) ? row[j] : -3.0e38f;
        m = fmaxf(m, rv[k]);
    }
    m = warp_max(m);
    if ((tid & 31) == 0) sh[tid >> 5] = m;
    __syncthreads();
    float mm = sh[0];
#pragma unroll
    for (int k = 1; k < 8; k++) mm = fmaxf(mm, sh[k]);
    __syncthreads();

    float sum = 0.0f;
#pragma unroll
    for (int k = 0; k < 8; k++) {
        int j = tid + k * 256;
        if (j < L) { rv[k] = __expf(rv[k] - mm); sum += rv[k]; }
    }
    sum = warp_sum(sum);
    if ((tid & 31) == 0) sh[tid >> 5] = sum;
    __syncthreads();
    float tot = sh[0];
#pragma unroll
    for (int k = 1; k < 8; k++) tot += sh[k];
    float inv = 1.0f / tot;

#pragma unroll
    for (int k = 0; k < 8; k++) {
        int j = tid + k * 256;
        if (j < zend) {
            float e = (j < L) ? rv[k] * inv : 0.0f;
            __nv_bfloat16 hh, ll;
            split1(e, hh, ll);
            ph[off + j] = hh; pl[off + j] = ll;
        }
    }
}

// ---------------- SIMT SGEMM (logits only): C = A(MxK) * B(NxK)^T ----------
__global__ void __launch_bounds__(256, 2)
gemm_simt(const float* __restrict__ A, int lda,
          const float* __restrict__ B, int ldb,
          float* __restrict__ C, int ldc, int N, int K) {
    int bm = blockIdx.y * 128;
    int bn = blockIdx.x * 128;

    __shared__ float As[8][128];
    __shared__ float Bs[8][128];
    int tid = threadIdx.x;
    int tx = tid & 15, ty = tid >> 4;
    float acc[8][8] = {};

    int lrow = tid >> 1;
    int lkk  = (tid & 1) * 4;
    const float* Ap = A + (size_t)(bm + lrow) * lda + lkk;
    bool bvalid = (bn + lrow) < N;
    const float* Bp = B + (size_t)(bn + lrow) * ldb + lkk;

    for (int k0 = 0; k0 < K; k0 += 8) {
        float4 av = *reinterpret_cast<const float4*>(Ap + k0);
        float4 bv = bvalid ? *reinterpret_cast<const float4*>(Bp + k0)
                           : make_float4(0.f, 0.f, 0.f, 0.f);
        As[lkk+0][lrow]=av.x; As[lkk+1][lrow]=av.y; As[lkk+2][lrow]=av.z; As[lkk+3][lrow]=av.w;
        Bs[lkk+0][lrow]=bv.x; Bs[lkk+1][lrow]=bv.y; Bs[lkk+2][lrow]=bv.z; Bs[lkk+3][lrow]=bv.w;
        __syncthreads();
#pragma unroll
        for (int kk = 0; kk < 8; kk++) {
            float a[8], b[8];
            *reinterpret_cast<float4*>(&a[0]) = *reinterpret_cast<const float4*>(&As[kk][ty*8]);
            *reinterpret_cast<float4*>(&a[4]) = *reinterpret_cast<const float4*>(&As[kk][ty*8+4]);
            *reinterpret_cast<float4*>(&b[0]) = *reinterpret_cast<const float4*>(&Bs[kk][tx*8]);
            *reinterpret_cast<float4*>(&b[4]) = *reinterpret_cast<const float4*>(&Bs[kk][tx*8+4]);
#pragma unroll
            for (int i = 0; i < 8; i++)
#pragma unroll
                for (int j = 0; j < 8; j++)
                    acc[i][j] += a[i] * b[j];
        }
        __syncthreads();
    }
#pragma unroll
    for (int i = 0; i < 8; i++) {
        float* Crow = C + (size_t)(bm + ty * 8 + i) * ldc;
#pragma unroll
        for (int j = 0; j < 8; j++) {
            int n = bn + tx * 8 + j;
            if (n < N) Crow[n] = acc[i][j];
        }
    }
}

// ---------------- driver ----------------
extern "C" void kernel_launch(void* const* d_in, const int* in_sizes, int n_in,
                              void* d_out, int out_size) {
    const int*   q      = (const int*)  d_in[0];
    const float* freqs  = (const float*)d_in[1];
    const float* exp_w  = (const float*)d_in[2];   // (8, 1632, 384)
    const float* proj_w = (const float*)d_in[3];   // (8, 384, 768)
    const float* blk_g  = (const float*)d_in[4];
    const float* blk_b  = (const float*)d_in[5];
    const float* ln_g   = (const float*)d_in[6];
    const float* ln_b   = (const float*)d_in[7];
    const float* out_w  = (const float*)d_in[8];   // (100, 384)
    float* out = (float*)d_out;

    float *x, *xn, *p;
    __nv_bfloat16 *xnh, *xnl, *cath, *catl, *vth, *vtl, *ph, *pl;
    __nv_bfloat16 *qh, *ql, *kh, *kl, *ewh, *ewl, *pwh, *pwl;
    cudaGetSymbolAddress((void**)&x,    g_x);
    cudaGetSymbolAddress((void**)&xn,   g_xn);
    cudaGetSymbolAddress((void**)&p,    g_p);
    cudaGetSymbolAddress((void**)&xnh,  g_xnh);  cudaGetSymbolAddress((void**)&xnl,  g_xnl);
    cudaGetSymbolAddress((void**)&cath, g_cath); cudaGetSymbolAddress((void**)&catl, g_catl);
    cudaGetSymbolAddress((void**)&vth,  g_vth);  cudaGetSymbolAddress((void**)&vtl,  g_vtl);
    cudaGetSymbolAddress((void**)&ph,   g_ph);   cudaGetSymbolAddress((void**)&pl,   g_pl);
    cudaGetSymbolAddress((void**)&qh,   g_qh);   cudaGetSymbolAddress((void**)&ql,   g_ql);
    cudaGetSymbolAddress((void**)&kh,   g_kh);   cudaGetSymbolAddress((void**)&kl,   g_kl);
    cudaGetSymbolAddress((void**)&ewh,  g_ewh);  cudaGetSymbolAddress((void**)&ewl,  g_ewl);
    cudaGetSymbolAddress((void**)&pwh,  g_pwh);  cudaGetSymbolAddress((void**)&pwl,  g_pwl);

    // pre-permute/split weights (once per launch)
    permute_split_ew<<<NBq * HPERM, 96>>>(exp_w, ewh, ewl);
    {
        int n4p = NBq * Dd * Ed / 4;
        split_w_kernel<<<(n4p + 255) / 256, 256>>>(
            (const float4*)proj_w, (__nv_bfloat162*)pwh, (__nv_bfloat162*)pwl, n4p);
    }

    embed_ln_kernel<<<Tq, 128>>>(q, freqs, ln_g, ln_b, x);

    for (int blk = 0; blk < NBq; blk++) {
        ln_bf16_kernel<<<Tq, 128>>>(x, xnh, xnl, blk_g + blk * Dd, blk_b + blk * Dd);

        // expand GEMM with fused geglu / qk-split / V^T epilogue
        gemm_bf_launch<3>(xnh, xnl, Dd, 0,
                          ewh + (size_t)blk * HPERM * Dd, ewl + (size_t)blk * HPERM * Dd, Dd, 0,
                          nullptr, nullptr, nullptr, 0, 0,
                          Tq, HPERM, Dd, 1, 0);

        // scores: qh @ kh^T per batch (pre-scaled, K padded to 64), causal skip
        gemm_bf_launch<0>(qh, ql, 64, (long long)Sq * 64,
                          kh, kl, 64, (long long)Sq * 64,
                          p, nullptr, nullptr, Sq, (long long)Sq * Sq,
                          Sq, Sq, 64, Bq, 1);

        softmax_kernel<<<dim3(Sq, Bq), 256>>>(p, ph, pl);

        // attn = P @ V -> cat[:, 384:768] as bf16 hi/lo; K capped causally
        gemm_bf_launch<2>(ph, pl, Sq, (long long)Sq * Sq,
                          vth, vtl, Sq, (long long)Dd * Sq,
                          nullptr, cath + Dd, catl + Dd, Ed, (long long)Sq * Ed,
                          Sq, Dd, Sq, Bq, 2);

        // x += cat @ proj_w[blk]^T
        gemm_bf_launch<1>(cath, catl, Ed, 0,
                          pwh + (size_t)blk * Dd * Ed, pwl + (size_t)blk * Dd * Ed, Ed, 0,
                          x, nullptr, nullptr, Dd, 0,
                          Tq, Dd, Ed, 1, 0);
    }

    ln_kernel<<<Tq, 128>>>(x, xn, ln_g, ln_b);
    gemm_simt<<<dim3(1, Tq / 128), 256>>>(xn, Dd, out_w, Dd, out, VOCABq, VOCABq, Dd);
}

// round 14
// speedup vs baseline: 1.6000x; 1.2735x over previous
#include <cuda_runtime.h>
#include <cuda_fp16.h>
#include <cstdint>

// ---------------- problem constants ----------------
#define Bq      4
#define Sq      2048
#define Tq      (Bq * Sq)      // 8192 tokens
#define Dd      384
#define QKd     48
#define Ed      768
#define Hd      1632           // 2*QK + 2*E
#define HPERM   1664           // permuted expand width: 1536 pairs + 64 qh + 64 kh
#define NBq     8
#define VOCABq  100

// ---------------- scratch (static device globals; no cudaMalloc) -----------
__device__ float g_x[Tq * Dd];                        // residual stream
__device__ float g_xn[Tq * Dd];                       // final-LN output (fp32)
__device__ float g_p[(size_t)Bq * Sq * Sq];           // raw scores fp32

#define AL16 __align__(16)
// A-side operands: exact fp16 hi/lo pairs
__device__ AL16 __half g_xnh[Tq * Dd],  g_xnl[Tq * Dd];
__device__ AL16 __half g_cath[(size_t)Tq * Ed], g_catl[(size_t)Tq * Ed];
__device__ AL16 __half g_ph[(size_t)Bq * Sq * Sq],  g_pl[(size_t)Bq * Sq * Sq];
__device__ AL16 __half g_qh[Tq * 64], g_ql[Tq * 64];   // qh padded K=64 (pre-scaled)
// B-side operands: single fp16 (rounded)
__device__ AL16 __half g_kh[Tq * 64];                  // kh padded K=64
__device__ AL16 __half g_vt[(size_t)Bq * Dd * Sq];     // V^T per batch [d, s]
__device__ AL16 __half g_ew[(size_t)NBq * HPERM * Dd];
__device__ AL16 __half g_pw[NBq * Dd * Ed];

// ================= low-level helpers =================
__device__ __forceinline__ uint32_t s2u(const void* p) {
    uint32_t a;
    asm("{ .reg .u64 t; cvta.to.shared.u64 t, %1; cvt.u32.u64 %0, t; }" : "=r"(a) : "l"(p));
    return a;
}
__device__ __forceinline__ void cpa16(uint32_t dst, const void* src, uint32_t sz) {
    asm volatile("cp.async.cg.shared.global [%0], [%1], 16, %2;"
                 :: "r"(dst), "l"(src), "r"(sz) : "memory");
}
__device__ __forceinline__ void cpa_commit() {
    asm volatile("cp.async.commit_group;" ::: "memory");
}
template <int NN>
__device__ __forceinline__ void cpa_wait() {
    asm volatile("cp.async.wait_group %0;" :: "n"(NN) : "memory");
}
__device__ __forceinline__ uint32_t swz(uint32_t off) { return off ^ ((off >> 3) & 0x70); }

__device__ __forceinline__ void ldm_x4(uint32_t addr, uint32_t* r) {
    asm volatile("ldmatrix.sync.aligned.m8n8.x4.shared.b16 {%0,%1,%2,%3}, [%4];"
                 : "=r"(r[0]), "=r"(r[1]), "=r"(r[2]), "=r"(r[3]) : "r"(addr));
}
// fp16 inputs, fp32 accumulator
__device__ __forceinline__ void mma16816(float* c, const uint32_t* a, const uint32_t* b) {
    asm volatile("mma.sync.aligned.m16n8k16.row.col.f32.f16.f16.f32 "
                 "{%0,%1,%2,%3}, {%4,%5,%6,%7}, {%8,%9}, {%0,%1,%2,%3};"
                 : "+f"(c[0]), "+f"(c[1]), "+f"(c[2]), "+f"(c[3])
                 : "r"(a[0]), "r"(a[1]), "r"(a[2]), "r"(a[3]), "r"(b[0]), "r"(b[1]));
}
__device__ __forceinline__ void split1h(float v, __half& h, __half& l) {
    h = __float2half_rn(v);
    l = __float2half_rn(v - __half2float(h));
}

// ================= fp16 HMMA GEMM: C = (Ah+Al)(MxK) * Bh(NxK)^T, 2-term ===
// A pre-split exact fp16 pair; B single fp16. 128x128 CTA tile, BK=64,
// 16 warps (4Mx4N, warp tile 32x32), cp.async 3-stage, reg acc, 512 threads.
// causal: 0=none, 1=skip bn>bm, 2=cap K at bm+128. M-order flipped when causal.
// OUTM: 0 = fp32 store, 1 = fp32 add, 2 = fp16 hi/lo pair store,
//       3 = fused expand epilogue (geglu->cat/V^T, qk split) via device globals.
#define BTILE   16384                   // 128 rows x 64 fp16 x 2B
#define STAGE_B (3 * BTILE)             // Ah, Al, Bh = 48 KB
#define NSTAGE  3
#define SHM_BF  (NSTAGE * STAGE_B + 128)
#define NTHR    512

template <int OUTM>
__global__ void __launch_bounds__(NTHR, 1)
gemm_bf(const __half* __restrict__ Ah_, const __half* __restrict__ Al_,
        int lda, long long sA,
        const __half* __restrict__ Bh_,
        int ldb, long long sB,
        float* __restrict__ Cf,
        __half* __restrict__ Ch, __half* __restrict__ Cl,
        int ldc, long long sC, int N, int K, int causal) {
    int my = (causal != 0) ? ((int)gridDim.y - 1 - (int)blockIdx.y) : (int)blockIdx.y;
    int bm = my * 128;
    int bn = blockIdx.x * 128;
    if (causal == 1 && bn > bm) return;
    int Keff = (causal == 2) ? ((bm + 128 < K) ? bm + 128 : K) : K;
    int nch = Keff >> 6;

    const __half* Ah = Ah_ + (long long)blockIdx.z * sA;
    const __half* Al = Al_ + (long long)blockIdx.z * sA;
    const __half* Bh = Bh_ + (long long)blockIdx.z * sB;

    extern __shared__ char dsm[];
    uint32_t base = (s2u(dsm) + 127u) & ~127u;

    int tid = threadIdx.x;
    int wid = tid >> 5, lane = tid & 31;
    int m0w = (wid >> 2) * 32;      // 4 warps in M
    int n0w = (wid & 3) * 32;       // 4 warps in N

    int lrow = tid >> 3;       // 0..63
    int lu   = tid & 7;        // 0..7

    float acc[2][4][4];
#pragma unroll
    for (int i = 0; i < 2; i++)
#pragma unroll
        for (int j = 0; j < 4; j++)
#pragma unroll
            for (int e = 0; e < 4; e++) acc[i][j][e] = 0.0f;

    uint32_t a_row  = (uint32_t)(lane & 15);
    uint32_t a_colb = (uint32_t)((lane >> 4) * 16);
    uint32_t b_row  = (uint32_t)(((lane >> 4) << 3) + (lane & 7));
    uint32_t b_colb = (uint32_t)(((lane >> 3) & 1) * 16);

    auto load_chunk = [&](int ch, int bsel) {
        int k0 = ch << 6;
        uint32_t tb = base + (uint32_t)bsel * STAGE_B;
#pragma unroll
        for (int i = 0; i < 2; i++) {
            int row = lrow + i * 64;
            uint32_t soff = swz((uint32_t)row * 128u + (uint32_t)lu * 16u);
            size_t aoff = (size_t)(bm + row) * lda + k0 + lu * 8;
            cpa16(tb + soff,             Ah + aoff, 16u);
            cpa16(tb + BTILE + soff,     Al + aoff, 16u);
            uint32_t bsz = ((bn + row) < N) ? 16u : 0u;
            size_t boff = (size_t)(bn + row) * ldb + k0 + lu * 8;
            cpa16(tb + 2 * BTILE + soff, Bh + boff, bsz);
        }
    };

    auto compute = [&](int bsel) {
        uint32_t tb  = base + (uint32_t)bsel * STAGE_B;
        uint32_t tAh = tb, tAl = tb + BTILE, tBh = tb + 2 * BTILE;
#pragma unroll
        for (int ks = 0; ks < 4; ks++) {
            uint32_t kbyte = (uint32_t)ks * 32u;
            uint32_t afrag[2][4], bfrag[2][4];
#pragma unroll
            for (int mt = 0; mt < 2; mt++) {
                uint32_t rr = (uint32_t)(m0w + mt * 16) + a_row;
                ldm_x4(tAh + swz(rr * 128u + kbyte + a_colb), afrag[mt]);
            }
#pragma unroll
            for (int bt = 0; bt < 2; bt++) {
                uint32_t rr = (uint32_t)(n0w + bt * 16) + b_row;
                ldm_x4(tBh + swz(rr * 128u + kbyte + b_colb), bfrag[bt]);
            }
            // term 1: Ahi * Bh
#pragma unroll
            for (int mt = 0; mt < 2; mt++)
#pragma unroll
                for (int nt = 0; nt < 4; nt++)
                    mma16816(acc[mt][nt], afrag[mt], &bfrag[nt >> 1][(nt & 1) * 2]);
            // term 2: Alo * Bh (reload A frags as lo)
#pragma unroll
            for (int mt = 0; mt < 2; mt++) {
                uint32_t rr = (uint32_t)(m0w + mt * 16) + a_row;
                ldm_x4(tAl + swz(rr * 128u + kbyte + a_colb), afrag[mt]);
            }
#pragma unroll
            for (int mt = 0; mt < 2; mt++)
#pragma unroll
                for (int nt = 0; nt < 4; nt++)
                    mma16816(acc[mt][nt], afrag[mt], &bfrag[nt >> 1][(nt & 1) * 2]);
        }
    };

    int issued = 0;
    if (issued < nch) { load_chunk(issued, issued % NSTAGE); cpa_commit(); issued++; }
    if (issued < nch) { load_chunk(issued, issued % NSTAGE); cpa_commit(); issued++; }
    for (int ch = 0; ch < nch; ch++) {
        if (issued < nch) { load_chunk(issued, issued % NSTAGE); cpa_commit(); issued++; }
        int pending = issued - ch - 1;
        if (pending >= 2)      cpa_wait<2>();
        else if (pending == 1) cpa_wait<1>();
        else                   cpa_wait<0>();
        __syncthreads();
        compute(ch % NSTAGE);
        __syncthreads();
    }

    // ---------------- epilogue ----------------
    if (OUTM == 3) {
        // stage acc tile (128x128 fp32) in smem, then coalesced
        // geglu / qk-split / V^T stores via device globals.
        float* sf = reinterpret_cast<float*>((((uintptr_t)dsm) + 127) & ~(uintptr_t)127);
        const int LDS = 132;
#pragma unroll
        for (int mt = 0; mt < 2; mt++) {
            int r0 = m0w + mt * 16 + (lane >> 2);
#pragma unroll
            for (int nt = 0; nt < 4; nt++) {
                int c = n0w + nt * 8 + (lane & 3) * 2;
#pragma unroll
                for (int half = 0; half < 2; half++) {
                    int r = r0 + half * 8;
                    sf[r * LDS + c]     = acc[mt][nt][half * 2];
                    sf[r * LDS + c + 1] = acc[mt][nt][half * 2 + 1];
                }
            }
        }
        __syncthreads();
        if (bn < 1536) {
            int jbase = bn >> 1;                 // 0..767
            bool isV = (jbase >= 384);
            if (!isV) {
#pragma unroll
                for (int i = 0; i < 16; i++) {
                    int vi = tid + i * NTHR;     // 8192 values
                    int row = vi >> 6, u = vi & 63;
                    float lin = sf[row * LDS + 2 * u];
                    float pg  = sf[row * LDS + 2 * u + 1];
                    float val = lin * 0.5f * pg * (1.0f + erff(pg * 0.70710678118654752f));
                    __half hh, ll; split1h(val, hh, ll);
                    size_t idx = (size_t)(bm + row) * Ed + jbase + u;
                    g_cath[idx] = hh; g_catl[idx] = ll;
                }
            } else {
#pragma unroll
                for (int i = 0; i < 16; i++) {
                    int vi = tid + i * NTHR;
                    int row = vi & 127, u = vi >> 7;   // s-contiguous for V^T
                    float lin = sf[row * LDS + 2 * u];
                    float pg  = sf[row * LDS + 2 * u + 1];
                    float val = lin * 0.5f * pg * (1.0f + erff(pg * 0.70710678118654752f));
                    int t = bm + row;
                    int jj = jbase + u - 384;
                    size_t idx = ((size_t)(t >> 11) * Dd + jj) * Sq + (t & (Sq - 1));
                    g_vt[idx] = __float2half_rn(val);  // B operand: single fp16
                }
            }
        } else {
#pragma unroll
            for (int i = 0; i < 32; i++) {
                int vi = tid + i * NTHR;         // 16384 values
                int row = vi >> 7, c = vi & 127;
                float val = sf[row * LDS + c];
                size_t idx = (size_t)(bm + row) * 64 + (c & 63);
                if (c < 64) {                     // qh: A operand, exact pair
                    __half hh, ll; split1h(val, hh, ll);
                    g_qh[idx] = hh; g_ql[idx] = ll;
                } else {                          // kh: B operand, single fp16
                    g_kh[idx] = __float2half_rn(val);
                }
            }
        }
        return;
    }

    float* CfB = (OUTM != 2) ? Cf + (long long)blockIdx.z * sC : nullptr;
    __half* ChB = (OUTM == 2) ? Ch + (long long)blockIdx.z * sC : nullptr;
    __half* ClB = (OUTM == 2) ? Cl + (long long)blockIdx.z * sC : nullptr;
#pragma unroll
    for (int mt = 0; mt < 2; mt++) {
        int row0 = bm + m0w + mt * 16 + (lane >> 2);
#pragma unroll
        for (int nt = 0; nt < 4; nt++) {
            int col = bn + n0w + nt * 8 + (lane & 3) * 2;
            float* c = acc[mt][nt];
#pragma unroll
            for (int half = 0; half < 2; half++) {
                int row = row0 + half * 8;
                float v0 = c[half * 2], v1 = c[half * 2 + 1];
                if (OUTM == 2) {
                    if (col + 1 < N) {
                        __half h0, l0, h1, l1;
                        split1h(v0, h0, l0); split1h(v1, h1, l1);
                        *reinterpret_cast<__half2*>(ChB + (size_t)row * ldc + col) =
                            __halves2half2(h0, h1);
                        *reinterpret_cast<__half2*>(ClB + (size_t)row * ldc + col) =
                            __halves2half2(l0, l1);
                    }
                } else {
                    float* Crow = CfB + (size_t)row * ldc;
                    if (col + 1 < N) {
                        float2 cv;
                        if (OUTM == 1) {
                            cv = *reinterpret_cast<float2*>(Crow + col);
                            cv.x += v0; cv.y += v1;
                        } else cv = make_float2(v0, v1);
                        *reinterpret_cast<float2*>(Crow + col) = cv;
                    } else if (col < N) {
                        Crow[col] = (OUTM == 1) ? (Crow[col] + v0) : v0;
                    }
                }
            }
        }
    }
}

template <int OUTM>
static inline void gemm_bf_launch(const __half* Ah, const __half* Al,
                                  int lda, long long sA,
                                  const __half* Bh, int ldb, long long sB,
                                  float* Cf, __half* Ch, __half* Cl,
                                  int ldc, long long sC,
                                  int M, int N, int K, int batch, int causal) {
    dim3 grid((N + 127) / 128, M / 128, batch);
    cudaFuncSetAttribute(gemm_bf<OUTM>, cudaFuncAttributeMaxDynamicSharedMemorySize, SHM_BF);
    gemm_bf<OUTM><<<grid, NTHR, SHM_BF>>>(Ah, Al, lda, sA, Bh, ldb, sB,
                                          Cf, Ch, Cl, ldc, sC, N, K, causal);
}

// ---------------- reductions ----------------
__device__ __forceinline__ float warp_sum(float v) {
#pragma unroll
    for (int o = 16; o; o >>= 1) v += __shfl_xor_sync(0xffffffffu, v, o);
    return v;
}
__device__ __forceinline__ float warp_max(float v) {
#pragma unroll
    for (int o = 16; o; o >>= 1) v = fmaxf(v, __shfl_xor_sync(0xffffffffu, v, o));
    return v;
}

// ---------------- permute + fp16-round expand weights ----------------
// Row order: [0,1536): interleaved (lin_j, pg_j); [1536,1600): qh rows
// (scaled 1/sqrt(QK), zero-padded); [1600,1664): kh rows (zero-padded).
__global__ void permute_round_ew(const float* __restrict__ exp_w,
                                 __half* __restrict__ wout) {
    int rid = blockIdx.x;                 // 0 .. NBq*HPERM-1
    int blk = rid / HPERM, fp = rid % HPERM;
    int f = 0; bool valid; float scale = 1.0f;
    if (fp < 1536) {
        int j = fp >> 1;
        f = (fp & 1) ? (2 * QKd + Ed + j) : (2 * QKd + j);
        valid = true;
    } else if (fp < 1600) {
        int d = fp - 1536;
        valid = (d < QKd); f = d;
        scale = 0.14433756729740643f;
    } else {
        int d = fp - 1600;
        valid = (d < QKd); f = QKd + d;
    }
    int tx = threadIdx.x;                 // 96 threads, float4 each
    float4 x = make_float4(0.f, 0.f, 0.f, 0.f);
    if (valid)
        x = reinterpret_cast<const float4*>(exp_w + ((size_t)blk * Hd + f) * Dd)[tx];
    size_t o = ((size_t)blk * HPERM + fp) * Dd + tx * 4;
    *reinterpret_cast<__half2*>(wout + o)     = __floats2half2_rn(x.x * scale, x.y * scale);
    *reinterpret_cast<__half2*>(wout + o + 2) = __floats2half2_rn(x.z * scale, x.w * scale);
}

// ---------------- proj weights: fp32 -> fp16 round ----------------
__global__ void round_w_kernel(const float4* __restrict__ src,
                               __half2* __restrict__ dst, int n4) {
    int i = blockIdx.x * 256 + threadIdx.x;
    if (i >= n4) return;
    float4 x = src[i];
    dst[2 * i]     = __floats2half2_rn(x.x, x.y);
    dst[2 * i + 1] = __floats2half2_rn(x.z, x.w);
}

// ---------------- embed (sin/cos) + LayerNorm (fp32 out) ----------------
__global__ void embed_ln_kernel(const int* __restrict__ q,
                                const float* __restrict__ freqs,
                                const float* __restrict__ g,
                                const float* __restrict__ b,
                                float* __restrict__ y) {
    int t = blockIdx.x;
    int tid = threadIdx.x;
    float qv = (float)q[t];
    float v[3];
#pragma unroll
    for (int k = 0; k < 3; k++) {
        int d = tid + k * 128;
        if (d < Dd / 2) v[k] = sinf(qv * freqs[d]);
        else            v[k] = cosf(qv * freqs[d - Dd / 2]);
    }
    float s = v[0] + v[1] + v[2];
    float sq = v[0]*v[0] + v[1]*v[1] + v[2]*v[2];
    s = warp_sum(s); sq = warp_sum(sq);
    __shared__ float shs[4], shq[4], mr[2];
    if ((tid & 31) == 0) { shs[tid >> 5] = s; shq[tid >> 5] = sq; }
    __syncthreads();
    if (tid == 0) {
        float ts = shs[0]+shs[1]+shs[2]+shs[3], tq = shq[0]+shq[1]+shq[2]+shq[3];
        float mean = ts * (1.0f / Dd);
        float var  = tq * (1.0f / Dd) - mean * mean;
        mr[0] = mean; mr[1] = rsqrtf(var + 1e-5f);
    }
    __syncthreads();
    float mean = mr[0], rstd = mr[1];
    float* yr = y + (size_t)t * Dd;
#pragma unroll
    for (int k = 0; k < 3; k++) {
        int d = tid + k * 128;
        yr[d] = (v[k] - mean) * rstd * g[d] + b[d];
    }
}

// ---------------- LayerNorm, fp32 out (final LN) ----------------
__global__ void ln_kernel(const float* __restrict__ x, float* __restrict__ y,
                          const float* __restrict__ g, const float* __restrict__ b) {
    int t = blockIdx.x;
    int tid = threadIdx.x;
    const float* xr = x + (size_t)t * Dd;
    float v0 = xr[tid], v1 = xr[tid + 128], v2 = xr[tid + 256];
    float s  = v0 + v1 + v2;
    float sq = v0*v0 + v1*v1 + v2*v2;
    s = warp_sum(s); sq = warp_sum(sq);
    __shared__ float shs[4], shq[4], mr[2];
    if ((tid & 31) == 0) { shs[tid >> 5] = s; shq[tid >> 5] = sq; }
    __syncthreads();
    if (tid == 0) {
        float ts = shs[0]+shs[1]+shs[2]+shs[3], tq = shq[0]+shq[1]+shq[2]+shq[3];
        float mean = ts * (1.0f / Dd);
        float var  = tq * (1.0f / Dd) - mean * mean;
        mr[0] = mean; mr[1] = rsqrtf(var + 1e-5f);
    }
    __syncthreads();
    float mean = mr[0], rstd = mr[1];
    float* yr = y + (size_t)t * Dd;
    yr[tid]       = (v0 - mean) * rstd * g[tid]       + b[tid];
    yr[tid + 128] = (v1 - mean) * rstd * g[tid + 128] + b[tid + 128];
    yr[tid + 256] = (v2 - mean) * rstd * g[tid + 256] + b[tid + 256];
}

// ---------------- LayerNorm, fp16 hi/lo out (per-block LN) ----------------
__global__ void ln_f16_kernel(const float* __restrict__ x,
                              __half* __restrict__ yh,
                              __half* __restrict__ yl,
                              const float* __restrict__ g,
                              const float* __restrict__ b) {
    int t = blockIdx.x;
    int tid = threadIdx.x;
    const float* xr = x + (size_t)t * Dd;
    float v0 = xr[tid], v1 = xr[tid + 128], v2 = xr[tid + 256];
    float s  = v0 + v1 + v2;
    float sq = v0*v0 + v1*v1 + v2*v2;
    s = warp_sum(s); sq = warp_sum(sq);
    __shared__ float shs[4], shq[4], mr[2];
    if ((tid & 31) == 0) { shs[tid >> 5] = s; shq[tid >> 5] = sq; }
    __syncthreads();
    if (tid == 0) {
        float ts = shs[0]+shs[1]+shs[2]+shs[3], tq = shq[0]+shq[1]+shq[2]+shq[3];
        float mean = ts * (1.0f / Dd);
        float var  = tq * (1.0f / Dd) - mean * mean;
        mr[0] = mean; mr[1] = rsqrtf(var + 1e-5f);
    }
    __syncthreads();
    float mean = mr[0], rstd = mr[1];
    size_t rb = (size_t)t * Dd;
#pragma unroll
    for (int k = 0; k < 3; k++) {
        int d = tid + k * 128;
        float vv = (k == 0 ? v0 : (k == 1 ? v1 : v2));
        float y = (vv - mean) * rstd * g[d] + b[d];
        __half hh, ll;
        split1h(y, hh, ll);
        yh[rb + d] = hh; yl[rb + d] = ll;
    }
}

// ---------------- causal softmax: fp32 scores -> fp16 hi/lo probs ----------
__global__ void softmax_kernel(const float* __restrict__ p,
                               __half* __restrict__ ph,
                               __half* __restrict__ pl) {
    int i = blockIdx.x;
    int b = blockIdx.y;
    size_t off = ((size_t)b * Sq + i) * Sq;
    const float* row = p + off;
    int L = i + 1;
    int zend = ((i >> 7) + 1) << 7;
    int tid = threadIdx.x;   // 256
    __shared__ float sh[8];

    float m = -3.0e38f;
    float rv[8];
#pragma unroll
    for (int k = 0; k < 8; k++) {
        int j = tid + k * 256;
        rv[k] = (j < L) ? row[j] : -3.0e38f;
        m = fmaxf(m, rv[k]);
    }
    m = warp_max(m);
    if ((tid & 31) == 0) sh[tid >> 5] = m;
    __syncthreads();
    float mm = sh[0];
#pragma unroll
    for (int k = 1; k < 8; k++) mm = fmaxf(mm, sh[k]);
    __syncthreads();

    float sum = 0.0f;
#pragma unroll
    for (int k = 0; k < 8; k++) {
        int j = tid + k * 256;
        if (j < L) { rv[k] = __expf(rv[k] - mm); sum += rv[k]; }
    }
    sum = warp_sum(sum);
    if ((tid & 31) == 0) sh[tid >> 5] = sum;
    __syncthreads();
    float tot = sh[0];
#pragma unroll
    for (int k = 1; k < 8; k++) tot += sh[k];
    float inv = 1.0f / tot;

#pragma unroll
    for (int k = 0; k < 8; k++) {
        int j = tid + k * 256;
        if (j < zend) {
            float e = (j < L) ? rv[k] * inv : 0.0f;
            __half hh, ll;
            split1h(e, hh, ll);
            ph[off + j] = hh; pl[off + j] = ll;
        }
    }
}

// ---------------- SIMT SGEMM (logits only): C = A(MxK) * B(NxK)^T ----------
__global__ void __launch_bounds__(256, 2)
gemm_simt(const float* __restrict__ A, int lda,
          const float* __restrict__ B, int ldb,
          float* __restrict__ C, int ldc, int N, int K) {
    int bm = blockIdx.y * 128;
    int bn = blockIdx.x * 128;

    __shared__ float As[8][128];
    __shared__ float Bs[8][128];
    int tid = threadIdx.x;
    int tx = tid & 15, ty = tid >> 4;
    float acc[8][8] = {};

    int lrow = tid >> 1;
    int lkk  = (tid & 1) * 4;
    const float* Ap = A + (size_t)(bm + lrow) * lda + lkk;
    bool bvalid = (bn + lrow) < N;
    const float* Bp = B + (size_t)(bn + lrow) * ldb + lkk;

    for (int k0 = 0; k0 < K; k0 += 8) {
        float4 av = *reinterpret_cast<const float4*>(Ap + k0);
        float4 bv = bvalid ? *reinterpret_cast<const float4*>(Bp + k0)
                           : make_float4(0.f, 0.f, 0.f, 0.f);
        As[lkk+0][lrow]=av.x; As[lkk+1][lrow]=av.y; As[lkk+2][lrow]=av.z; As[lkk+3][lrow]=av.w;
        Bs[lkk+0][lrow]=bv.x; Bs[lkk+1][lrow]=bv.y; Bs[lkk+2][lrow]=bv.z; Bs[lkk+3][lrow]=bv.w;
        __syncthreads();
#pragma unroll
        for (int kk = 0; kk < 8; kk++) {
            float a[8], b[8];
            *reinterpret_cast<float4*>(&a[0]) = *reinterpret_cast<const float4*>(&As[kk][ty*8]);
            *reinterpret_cast<float4*>(&a[4]) = *reinterpret_cast<const float4*>(&As[kk][ty*8+4]);
            *reinterpret_cast<float4*>(&b[0]) = *reinterpret_cast<const float4*>(&Bs[kk][tx*8]);
            *reinterpret_cast<float4*>(&b[4]) = *reinterpret_cast<const float4*>(&Bs[kk][tx*8+4]);
#pragma unroll
            for (int i = 0; i < 8; i++)
#pragma unroll
                for (int j = 0; j < 8; j++)
                    acc[i][j] += a[i] * b[j];
        }
        __syncthreads();
    }
#pragma unroll
    for (int i = 0; i < 8; i++) {
        float* Crow = C + (size_t)(bm + ty * 8 + i) * ldc;
#pragma unroll
        for (int j = 0; j < 8; j++) {
            int n = bn + tx * 8 + j;
            if (n < N) Crow[n] = acc[i][j];
        }
    }
}

// ---------------- driver ----------------
extern "C" void kernel_launch(void* const* d_in, const int* in_sizes, int n_in,
                              void* d_out, int out_size) {
    const int*   q      = (const int*)  d_in[0];
    const float* freqs  = (const float*)d_in[1];
    const float* exp_w  = (const float*)d_in[2];   // (8, 1632, 384)
    const float* proj_w = (const float*)d_in[3];   // (8, 384, 768)
    const float* blk_g  = (const float*)d_in[4];
    const float* blk_b  = (const float*)d_in[5];
    const float* ln_g   = (const float*)d_in[6];
    const float* ln_b   = (const float*)d_in[7];
    const float* out_w  = (const float*)d_in[8];   // (100, 384)
    float* out = (float*)d_out;

    float *x, *xn, *p;
    __half *xnh, *xnl, *cath, *catl, *vt, *ph, *pl;
    __half *qh, *ql, *kh, *ew, *pw;
    cudaGetSymbolAddress((void**)&x,    g_x);
    cudaGetSymbolAddress((void**)&xn,   g_xn);
    cudaGetSymbolAddress((void**)&p,    g_p);
    cudaGetSymbolAddress((void**)&xnh,  g_xnh);  cudaGetSymbolAddress((void**)&xnl,  g_xnl);
    cudaGetSymbolAddress((void**)&cath, g_cath); cudaGetSymbolAddress((void**)&catl, g_catl);
    cudaGetSymbolAddress((void**)&vt,   g_vt);
    cudaGetSymbolAddress((void**)&ph,   g_ph);   cudaGetSymbolAddress((void**)&pl,   g_pl);
    cudaGetSymbolAddress((void**)&qh,   g_qh);   cudaGetSymbolAddress((void**)&ql,   g_ql);
    cudaGetSymbolAddress((void**)&kh,   g_kh);
    cudaGetSymbolAddress((void**)&ew,   g_ew);   cudaGetSymbolAddress((void**)&pw,   g_pw);

    // pre-permute/round weights (once per launch)
    permute_round_ew<<<NBq * HPERM, 96>>>(exp_w, ew);
    {
        int n4p = NBq * Dd * Ed / 4;
        round_w_kernel<<<(n4p + 255) / 256, 256>>>(
            (const float4*)proj_w, (__half2*)pw, n4p);
    }

    embed_ln_kernel<<<Tq, 128>>>(q, freqs, ln_g, ln_b, x);

    for (int blk = 0; blk < NBq; blk++) {
        ln_f16_kernel<<<Tq, 128>>>(x, xnh, xnl, blk_g + blk * Dd, blk_b + blk * Dd);

        // expand GEMM with fused geglu / qk-split / V^T epilogue
        gemm_bf_launch<3>(xnh, xnl, Dd, 0,
                          ew + (size_t)blk * HPERM * Dd, Dd, 0,
                          nullptr, nullptr, nullptr, 0, 0,
                          Tq, HPERM, Dd, 1, 0);

        // scores: qh @ kh^T per batch (pre-scaled, K padded to 64), causal skip
        gemm_bf_launch<0>(qh, ql, 64, (long long)Sq * 64,
                          kh, 64, (long long)Sq * 64,
                          p, nullptr, nullptr, Sq, (long long)Sq * Sq,
                          Sq, Sq, 64, Bq, 1);

        softmax_kernel<<<dim3(Sq, Bq), 256>>>(p, ph, pl);

        // attn = P @ V -> cat[:, 384:768] as fp16 hi/lo; K capped causally
        gemm_bf_launch<2>(ph, pl, Sq, (long long)Sq * Sq,
                          vt, Sq, (long long)Dd * Sq,
                          nullptr, cath + Dd, catl + Dd, Ed, (long long)Sq * Ed,
                          Sq, Dd, Sq, Bq, 2);

        // x += cat @ proj_w[blk]^T
        gemm_bf_launch<1>(cath, catl, Ed, 0,
                          pw + (size_t)blk * Dd * Ed, Ed, 0,
                          x, nullptr, nullptr, Dd, 0,
                          Tq, Dd, Ed, 1, 0);
    }

    ln_kernel<<<Tq, 128>>>(x, xn, ln_g, ln_b);
    gemm_simt<<<dim3(1, Tq / 128), 256>>>(xn, Dd, out_w, Dd, out, VOCABq, VOCABq, Dd);
}

// round 15
// speedup vs baseline: 2.1687x; 1.3554x over previous
#include <cuda_runtime.h>
#include <cuda_fp16.h>
#include <cstdint>

// ---------------- problem constants ----------------
#define Bq      4
#define Sq      2048
#define Tq      (Bq * Sq)      // 8192 tokens
#define Dd      384
#define QKd     48
#define Ed      768
#define Hd      1632           // 2*QK + 2*E
#define HPERM   1664           // permuted expand width: 1536 pairs + 64 qh + 64 kh
#define NBq     8
#define VOCABq  100

// ---------------- scratch (static device globals; no cudaMalloc) -----------
__device__ float g_x[Tq * Dd];                        // residual stream
__device__ float g_xn[Tq * Dd];                       // final-LN output (fp32)
__device__ float g_p[(size_t)Bq * Sq * Sq];           // raw scores fp32

#define AL16 __align__(16)
__device__ AL16 __half g_xnh[Tq * Dd];                 // LN out fp16
__device__ AL16 __half g_cat[(size_t)Tq * Ed];         // [loc | attn] fp16
__device__ AL16 __half g_ph[(size_t)Bq * Sq * Sq];     // probs fp16
__device__ AL16 __half g_qh[Tq * 64];                  // qh padded K=64 (pre-scaled)
__device__ AL16 __half g_kh[Tq * 64];                  // kh padded K=64
__device__ AL16 __half g_vt[(size_t)Bq * Dd * Sq];     // V^T per batch [d, s]
__device__ AL16 __half g_ew[(size_t)NBq * HPERM * Dd];
__device__ AL16 __half g_pw[NBq * Dd * Ed];

// ================= low-level helpers =================
__device__ __forceinline__ uint32_t s2u(const void* p) {
    uint32_t a;
    asm("{ .reg .u64 t; cvta.to.shared.u64 t, %1; cvt.u32.u64 %0, t; }" : "=r"(a) : "l"(p));
    return a;
}
__device__ __forceinline__ void cpa16(uint32_t dst, const void* src, uint32_t sz) {
    asm volatile("cp.async.cg.shared.global [%0], [%1], 16, %2;"
                 :: "r"(dst), "l"(src), "r"(sz) : "memory");
}
__device__ __forceinline__ void cpa_commit() {
    asm volatile("cp.async.commit_group;" ::: "memory");
}
template <int NN>
__device__ __forceinline__ void cpa_wait() {
    asm volatile("cp.async.wait_group %0;" :: "n"(NN) : "memory");
}
__device__ __forceinline__ uint32_t swz(uint32_t off) { return off ^ ((off >> 3) & 0x70); }

__device__ __forceinline__ void ldm_x4(uint32_t addr, uint32_t* r) {
    asm volatile("ldmatrix.sync.aligned.m8n8.x4.shared.b16 {%0,%1,%2,%3}, [%4];"
                 : "=r"(r[0]), "=r"(r[1]), "=r"(r[2]), "=r"(r[3]) : "r"(addr));
}
// fp16 inputs, fp32 accumulator
__device__ __forceinline__ void mma16816(float* c, const uint32_t* a, const uint32_t* b) {
    asm volatile("mma.sync.aligned.m16n8k16.row.col.f32.f16.f16.f32 "
                 "{%0,%1,%2,%3}, {%4,%5,%6,%7}, {%8,%9}, {%0,%1,%2,%3};"
                 : "+f"(c[0]), "+f"(c[1]), "+f"(c[2]), "+f"(c[3])
                 : "r"(a[0]), "r"(a[1]), "r"(a[2]), "r"(a[3]), "r"(b[0]), "r"(b[1]));
}

// ================= fp16 HMMA GEMM: C = A(MxK) * B(NxK)^T, single-term =====
// A and B single fp16. 128x128 CTA tile, BK=64, 16 warps (4Mx4N, warp tile
// 32x32), cp.async 3-stage, reg acc, 512 threads.
// causal: 0=none, 1=skip bn>bm, 2=cap K at bm+128. M-order flipped when causal.
// OUTM: 0 = fp32 store, 1 = fp32 add, 2 = fp16 store,
//       3 = fused expand epilogue (geglu->cat/V^T, qk split) via device globals.
#define BTILE   16384                   // 128 rows x 64 fp16 x 2B
#define STAGE_B (2 * BTILE)             // Ah, Bh = 32 KB
#define NSTAGE  3
#define SHM_BF  (NSTAGE * STAGE_B + 128)
#define NTHR    512

template <int OUTM>
__global__ void __launch_bounds__(NTHR, 1)
gemm_bf(const __half* __restrict__ Ah_,
        int lda, long long sA,
        const __half* __restrict__ Bh_,
        int ldb, long long sB,
        float* __restrict__ Cf, __half* __restrict__ Ch,
        int ldc, long long sC, int N, int K, int causal) {
    int my = (causal != 0) ? ((int)gridDim.y - 1 - (int)blockIdx.y) : (int)blockIdx.y;
    int bm = my * 128;
    int bn = blockIdx.x * 128;
    if (causal == 1 && bn > bm) return;
    int Keff = (causal == 2) ? ((bm + 128 < K) ? bm + 128 : K) : K;
    int nch = Keff >> 6;

    const __half* Ah = Ah_ + (long long)blockIdx.z * sA;
    const __half* Bh = Bh_ + (long long)blockIdx.z * sB;

    extern __shared__ char dsm[];
    uint32_t base = (s2u(dsm) + 127u) & ~127u;

    int tid = threadIdx.x;
    int wid = tid >> 5, lane = tid & 31;
    int m0w = (wid >> 2) * 32;      // 4 warps in M
    int n0w = (wid & 3) * 32;       // 4 warps in N

    int lrow = tid >> 3;       // 0..63
    int lu   = tid & 7;        // 0..7

    float acc[2][4][4];
#pragma unroll
    for (int i = 0; i < 2; i++)
#pragma unroll
        for (int j = 0; j < 4; j++)
#pragma unroll
            for (int e = 0; e < 4; e++) acc[i][j][e] = 0.0f;

    uint32_t a_row  = (uint32_t)(lane & 15);
    uint32_t a_colb = (uint32_t)((lane >> 4) * 16);
    uint32_t b_row  = (uint32_t)(((lane >> 4) << 3) + (lane & 7));
    uint32_t b_colb = (uint32_t)(((lane >> 3) & 1) * 16);

    auto load_chunk = [&](int ch, int bsel) {
        int k0 = ch << 6;
        uint32_t tb = base + (uint32_t)bsel * STAGE_B;
#pragma unroll
        for (int i = 0; i < 2; i++) {
            int row = lrow + i * 64;
            uint32_t soff = swz((uint32_t)row * 128u + (uint32_t)lu * 16u);
            size_t aoff = (size_t)(bm + row) * lda + k0 + lu * 8;
            cpa16(tb + soff, Ah + aoff, 16u);
            uint32_t bsz = ((bn + row) < N) ? 16u : 0u;
            size_t boff = (size_t)(bn + row) * ldb + k0 + lu * 8;
            cpa16(tb + BTILE + soff, Bh + boff, bsz);
        }
    };

    auto compute = [&](int bsel) {
        uint32_t tb  = base + (uint32_t)bsel * STAGE_B;
        uint32_t tAh = tb, tBh = tb + BTILE;
#pragma unroll
        for (int ks = 0; ks < 4; ks++) {
            uint32_t kbyte = (uint32_t)ks * 32u;
            uint32_t afrag[2][4], bfrag[2][4];
#pragma unroll
            for (int mt = 0; mt < 2; mt++) {
                uint32_t rr = (uint32_t)(m0w + mt * 16) + a_row;
                ldm_x4(tAh + swz(rr * 128u + kbyte + a_colb), afrag[mt]);
            }
#pragma unroll
            for (int bt = 0; bt < 2; bt++) {
                uint32_t rr = (uint32_t)(n0w + bt * 16) + b_row;
                ldm_x4(tBh + swz(rr * 128u + kbyte + b_colb), bfrag[bt]);
            }
#pragma unroll
            for (int mt = 0; mt < 2; mt++)
#pragma unroll
                for (int nt = 0; nt < 4; nt++)
                    mma16816(acc[mt][nt], afrag[mt], &bfrag[nt >> 1][(nt & 1) * 2]);
        }
    };

    int issued = 0;
    if (issued < nch) { load_chunk(issued, issued % NSTAGE); cpa_commit(); issued++; }
    if (issued < nch) { load_chunk(issued, issued % NSTAGE); cpa_commit(); issued++; }
    for (int ch = 0; ch < nch; ch++) {
        if (issued < nch) { load_chunk(issued, issued % NSTAGE); cpa_commit(); issued++; }
        int pending = issued - ch - 1;
        if (pending >= 2)      cpa_wait<2>();
        else if (pending == 1) cpa_wait<1>();
        else                   cpa_wait<0>();
        __syncthreads();
        compute(ch % NSTAGE);
        __syncthreads();
    }

    // ---------------- epilogue ----------------
    if (OUTM == 3) {
        // stage acc tile (128x128 fp32) in smem, then coalesced
        // geglu / qk-split / V^T stores via device globals.
        float* sf = reinterpret_cast<float*>((((uintptr_t)dsm) + 127) & ~(uintptr_t)127);
        const int LDS = 132;
#pragma unroll
        for (int mt = 0; mt < 2; mt++) {
            int r0 = m0w + mt * 16 + (lane >> 2);
#pragma unroll
            for (int nt = 0; nt < 4; nt++) {
                int c = n0w + nt * 8 + (lane & 3) * 2;
#pragma unroll
                for (int half = 0; half < 2; half++) {
                    int r = r0 + half * 8;
                    sf[r * LDS + c]     = acc[mt][nt][half * 2];
                    sf[r * LDS + c + 1] = acc[mt][nt][half * 2 + 1];
                }
            }
        }
        __syncthreads();
        if (bn < 1536) {
            int jbase = bn >> 1;                 // 0..767
            bool isV = (jbase >= 384);
            if (!isV) {
#pragma unroll
                for (int i = 0; i < 16; i++) {
                    int vi = tid + i * NTHR;     // 8192 values
                    int row = vi >> 6, u = vi & 63;
                    float lin = sf[row * LDS + 2 * u];
                    float pg  = sf[row * LDS + 2 * u + 1];
                    float val = lin * 0.5f * pg * (1.0f + erff(pg * 0.70710678118654752f));
                    g_cat[(size_t)(bm + row) * Ed + jbase + u] = __float2half_rn(val);
                }
            } else {
#pragma unroll
                for (int i = 0; i < 16; i++) {
                    int vi = tid + i * NTHR;
                    int row = vi & 127, u = vi >> 7;   // s-contiguous for V^T
                    float lin = sf[row * LDS + 2 * u];
                    float pg  = sf[row * LDS + 2 * u + 1];
                    float val = lin * 0.5f * pg * (1.0f + erff(pg * 0.70710678118654752f));
                    int t = bm + row;
                    int jj = jbase + u - 384;
                    size_t idx = ((size_t)(t >> 11) * Dd + jj) * Sq + (t & (Sq - 1));
                    g_vt[idx] = __float2half_rn(val);
                }
            }
        } else {
#pragma unroll
            for (int i = 0; i < 32; i++) {
                int vi = tid + i * NTHR;         // 16384 values
                int row = vi >> 7, c = vi & 127;
                float val = sf[row * LDS + c];
                size_t idx = (size_t)(bm + row) * 64 + (c & 63);
                if (c < 64) g_qh[idx] = __float2half_rn(val);
                else        g_kh[idx] = __float2half_rn(val);
            }
        }
        return;
    }

    float* CfB = (OUTM != 2) ? Cf + (long long)blockIdx.z * sC : nullptr;
    __half* ChB = (OUTM == 2) ? Ch + (long long)blockIdx.z * sC : nullptr;
#pragma unroll
    for (int mt = 0; mt < 2; mt++) {
        int row0 = bm + m0w + mt * 16 + (lane >> 2);
#pragma unroll
        for (int nt = 0; nt < 4; nt++) {
            int col = bn + n0w + nt * 8 + (lane & 3) * 2;
            float* c = acc[mt][nt];
#pragma unroll
            for (int half = 0; half < 2; half++) {
                int row = row0 + half * 8;
                float v0 = c[half * 2], v1 = c[half * 2 + 1];
                if (OUTM == 2) {
                    if (col + 1 < N)
                        *reinterpret_cast<__half2*>(ChB + (size_t)row * ldc + col) =
                            __floats2half2_rn(v0, v1);
                } else {
                    float* Crow = CfB + (size_t)row * ldc;
                    if (col + 1 < N) {
                        float2 cv;
                        if (OUTM == 1) {
                            cv = *reinterpret_cast<float2*>(Crow + col);
                            cv.x += v0; cv.y += v1;
                        } else cv = make_float2(v0, v1);
                        *reinterpret_cast<float2*>(Crow + col) = cv;
                    } else if (col < N) {
                        Crow[col] = (OUTM == 1) ? (Crow[col] + v0) : v0;
                    }
                }
            }
        }
    }
}

template <int OUTM>
static inline void gemm_bf_launch(const __half* Ah, int lda, long long sA,
                                  const __half* Bh, int ldb, long long sB,
                                  float* Cf, __half* Ch,
                                  int ldc, long long sC,
                                  int M, int N, int K, int batch, int causal) {
    dim3 grid((N + 127) / 128, M / 128, batch);
    cudaFuncSetAttribute(gemm_bf<OUTM>, cudaFuncAttributeMaxDynamicSharedMemorySize, SHM_BF);
    gemm_bf<OUTM><<<grid, NTHR, SHM_BF>>>(Ah, lda, sA, Bh, ldb, sB,
                                          Cf, Ch, ldc, sC, N, K, causal);
}

// ---------------- reductions ----------------
__device__ __forceinline__ float warp_sum(float v) {
#pragma unroll
    for (int o = 16; o; o >>= 1) v += __shfl_xor_sync(0xffffffffu, v, o);
    return v;
}
__device__ __forceinline__ float warp_max(float v) {
#pragma unroll
    for (int o = 16; o; o >>= 1) v = fmaxf(v, __shfl_xor_sync(0xffffffffu, v, o));
    return v;
}

// ---------------- permute + fp16-round expand weights ----------------
// Row order: [0,1536): interleaved (lin_j, pg_j); [1536,1600): qh rows
// (scaled 1/sqrt(QK), zero-padded); [1600,1664): kh rows (zero-padded).
__global__ void permute_round_ew(const float* __restrict__ exp_w,
                                 __half* __restrict__ wout) {
    int rid = blockIdx.x;                 // 0 .. NBq*HPERM-1
    int blk = rid / HPERM, fp = rid % HPERM;
    int f = 0; bool valid; float scale = 1.0f;
    if (fp < 1536) {
        int j = fp >> 1;
        f = (fp & 1) ? (2 * QKd + Ed + j) : (2 * QKd + j);
        valid = true;
    } else if (fp < 1600) {
        int d = fp - 1536;
        valid = (d < QKd); f = d;
        scale = 0.14433756729740643f;
    } else {
        int d = fp - 1600;
        valid = (d < QKd); f = QKd + d;
    }
    int tx = threadIdx.x;                 // 96 threads, float4 each
    float4 x = make_float4(0.f, 0.f, 0.f, 0.f);
    if (valid)
        x = reinterpret_cast<const float4*>(exp_w + ((size_t)blk * Hd + f) * Dd)[tx];
    size_t o = ((size_t)blk * HPERM + fp) * Dd + tx * 4;
    *reinterpret_cast<__half2*>(wout + o)     = __floats2half2_rn(x.x * scale, x.y * scale);
    *reinterpret_cast<__half2*>(wout + o + 2) = __floats2half2_rn(x.z * scale, x.w * scale);
}

// ---------------- proj weights: fp32 -> fp16 round ----------------
__global__ void round_w_kernel(const float4* __restrict__ src,
                               __half2* __restrict__ dst, int n4) {
    int i = blockIdx.x * 256 + threadIdx.x;
    if (i >= n4) return;
    float4 x = src[i];
    dst[2 * i]     = __floats2half2_rn(x.x, x.y);
    dst[2 * i + 1] = __floats2half2_rn(x.z, x.w);
}

// ---------------- embed (sin/cos) + LayerNorm (fp32 out) ----------------
__global__ void embed_ln_kernel(const int* __restrict__ q,
                                const float* __restrict__ freqs,
                                const float* __restrict__ g,
                                const float* __restrict__ b,
                                float* __restrict__ y) {
    int t = blockIdx.x;
    int tid = threadIdx.x;
    float qv = (float)q[t];
    float v[3];
#pragma unroll
    for (int k = 0; k < 3; k++) {
        int d = tid + k * 128;
        if (d < Dd / 2) v[k] = sinf(qv * freqs[d]);
        else            v[k] = cosf(qv * freqs[d - Dd / 2]);
    }
    float s = v[0] + v[1] + v[2];
    float sq = v[0]*v[0] + v[1]*v[1] + v[2]*v[2];
    s = warp_sum(s); sq = warp_sum(sq);
    __shared__ float shs[4], shq[4], mr[2];
    if ((tid & 31) == 0) { shs[tid >> 5] = s; shq[tid >> 5] = sq; }
    __syncthreads();
    if (tid == 0) {
        float ts = shs[0]+shs[1]+shs[2]+shs[3], tq = shq[0]+shq[1]+shq[2]+shq[3];
        float mean = ts * (1.0f / Dd);
        float var  = tq * (1.0f / Dd) - mean * mean;
        mr[0] = mean; mr[1] = rsqrtf(var + 1e-5f);
    }
    __syncthreads();
    float mean = mr[0], rstd = mr[1];
    float* yr = y + (size_t)t * Dd;
#pragma unroll
    for (int k = 0; k < 3; k++) {
        int d = tid + k * 128;
        yr[d] = (v[k] - mean) * rstd * g[d] + b[d];
    }
}

// ---------------- LayerNorm, fp32 out (final LN) ----------------
__global__ void ln_kernel(const float* __restrict__ x, float* __restrict__ y,
                          const float* __restrict__ g, const float* __restrict__ b) {
    int t = blockIdx.x;
    int tid = threadIdx.x;
    const float* xr = x + (size_t)t * Dd;
    float v0 = xr[tid], v1 = xr[tid + 128], v2 = xr[tid + 256];
    float s  = v0 + v1 + v2;
    float sq = v0*v0 + v1*v1 + v2*v2;
    s = warp_sum(s); sq = warp_sum(sq);
    __shared__ float shs[4], shq[4], mr[2];
    if ((tid & 31) == 0) { shs[tid >> 5] = s; shq[tid >> 5] = sq; }
    __syncthreads();
    if (tid == 0) {
        float ts = shs[0]+shs[1]+shs[2]+shs[3], tq = shq[0]+shq[1]+shq[2]+shq[3];
        float mean = ts * (1.0f / Dd);
        float var  = tq * (1.0f / Dd) - mean * mean;
        mr[0] = mean; mr[1] = rsqrtf(var + 1e-5f);
    }
    __syncthreads();
    float mean = mr[0], rstd = mr[1];
    float* yr = y + (size_t)t * Dd;
    yr[tid]       = (v0 - mean) * rstd * g[tid]       + b[tid];
    yr[tid + 128] = (v1 - mean) * rstd * g[tid + 128] + b[tid + 128];
    yr[tid + 256] = (v2 - mean) * rstd * g[tid + 256] + b[tid + 256];
}

// ---------------- LayerNorm, fp16 out (per-block LN) ----------------
__global__ void ln_f16_kernel(const float* __restrict__ x,
                              __half* __restrict__ yh,
                              const float* __restrict__ g,
                              const float* __restrict__ b) {
    int t = blockIdx.x;
    int tid = threadIdx.x;
    const float* xr = x + (size_t)t * Dd;
    float v0 = xr[tid], v1 = xr[tid + 128], v2 = xr[tid + 256];
    float s  = v0 + v1 + v2;
    float sq = v0*v0 + v1*v1 + v2*v2;
    s = warp_sum(s); sq = warp_sum(sq);
    __shared__ float shs[4], shq[4], mr[2];
    if ((tid & 31) == 0) { shs[tid >> 5] = s; shq[tid >> 5] = sq; }
    __syncthreads();
    if (tid == 0) {
        float ts = shs[0]+shs[1]+shs[2]+shs[3], tq = shq[0]+shq[1]+shq[2]+shq[3];
        float mean = ts * (1.0f / Dd);
        float var  = tq * (1.0f / Dd) - mean * mean;
        mr[0] = mean; mr[1] = rsqrtf(var + 1e-5f);
    }
    __syncthreads();
    float mean = mr[0], rstd = mr[1];
    size_t rb = (size_t)t * Dd;
#pragma unroll
    for (int k = 0; k < 3; k++) {
        int d = tid + k * 128;
        float vv = (k == 0 ? v0 : (k == 1 ? v1 : v2));
        float y = (vv - mean) * rstd * g[d] + b[d];
        yh[rb + d] = __float2half_rn(y);
    }
}

// ---------------- causal softmax: fp32 scores -> fp16 probs ----------------
__global__ void softmax_kernel(const float* __restrict__ p,
                               __half* __restrict__ ph) {
    int i = blockIdx.x;
    int b = blockIdx.y;
    size_t off = ((size_t)b * Sq + i) * Sq;
    const float* row = p + off;
    int L = i + 1;
    int zend = ((i >> 7) + 1) << 7;
    int tid = threadIdx.x;   // 256
    __shared__ float sh[8];

    float m = -3.0e38f;
    float rv[8];
#pragma unroll
    for (int k = 0; k < 8; k++) {
        int j = tid + k * 256;
        rv[k] = (j < L) ? row[j] : -3.0e38f;
        m = fmaxf(m, rv[k]);
    }
    m = warp_max(m);
    if ((tid & 31) == 0) sh[tid >> 5] = m;
    __syncthreads();
    float mm = sh[0];
#pragma unroll
    for (int k = 1; k < 8; k++) mm = fmaxf(mm, sh[k]);
    __syncthreads();

    float sum = 0.0f;
#pragma unroll
    for (int k = 0; k < 8; k++) {
        int j = tid + k * 256;
        if (j < L) { rv[k] = __expf(rv[k] - mm); sum += rv[k]; }
    }
    sum = warp_sum(sum);
    if ((tid & 31) == 0) sh[tid >> 5] = sum;
    __syncthreads();
    float tot = sh[0];
#pragma unroll
    for (int k = 1; k < 8; k++) tot += sh[k];
    float inv = 1.0f / tot;

#pragma unroll
    for (int k = 0; k < 8; k++) {
        int j = tid + k * 256;
        if (j < zend) {
            float e = (j < L) ? rv[k] * inv : 0.0f;
            ph[off + j] = __float2half_rn(e);
        }
    }
}

// ---------------- SIMT SGEMM (logits only): C = A(MxK) * B(NxK)^T ----------
__global__ void __launch_bounds__(256, 2)
gemm_simt(const float* __restrict__ A, int lda,
          const float* __restrict__ B, int ldb,
          float* __restrict__ C, int ldc, int N, int K) {
    int bm = blockIdx.y * 128;
    int bn = blockIdx.x * 128;

    __shared__ float As[8][128];
    __shared__ float Bs[8][128];
    int tid = threadIdx.x;
    int tx = tid & 15, ty = tid >> 4;
    float acc[8][8] = {};

    int lrow = tid >> 1;
    int lkk  = (tid & 1) * 4;
    const float* Ap = A + (size_t)(bm + lrow) * lda + lkk;
    bool bvalid = (bn + lrow) < N;
    const float* Bp = B + (size_t)(bn + lrow) * ldb + lkk;

    for (int k0 = 0; k0 < K; k0 += 8) {
        float4 av = *reinterpret_cast<const float4*>(Ap + k0);
        float4 bv = bvalid ? *reinterpret_cast<const float4*>(Bp + k0)
                           : make_float4(0.f, 0.f, 0.f, 0.f);
        As[lkk+0][lrow]=av.x; As[lkk+1][lrow]=av.y; As[lkk+2][lrow]=av.z; As[lkk+3][lrow]=av.w;
        Bs[lkk+0][lrow]=bv.x; Bs[lkk+1][lrow]=bv.y; Bs[lkk+2][lrow]=bv.z; Bs[lkk+3][lrow]=bv.w;
        __syncthreads();
#pragma unroll
        for (int kk = 0; kk < 8; kk++) {
            float a[8], b[8];
            *reinterpret_cast<float4*>(&a[0]) = *reinterpret_cast<const float4*>(&As[kk][ty*8]);
            *reinterpret_cast<float4*>(&a[4]) = *reinterpret_cast<const float4*>(&As[kk][ty*8+4]);
            *reinterpret_cast<float4*>(&b[0]) = *reinterpret_cast<const float4*>(&Bs[kk][tx*8]);
            *reinterpret_cast<float4*>(&b[4]) = *reinterpret_cast<const float4*>(&Bs[kk][tx*8+4]);
#pragma unroll
            for (int i = 0; i < 8; i++)
#pragma unroll
                for (int j = 0; j < 8; j++)
                    acc[i][j] += a[i] * b[j];
        }
        __syncthreads();
    }
#pragma unroll
    for (int i = 0; i < 8; i++) {
        float* Crow = C + (size_t)(bm + ty * 8 + i) * ldc;
#pragma unroll
        for (int j = 0; j < 8; j++) {
            int n = bn + tx * 8 + j;
            if (n < N) Crow[n] = acc[i][j];
        }
    }
}

// ---------------- driver ----------------
extern "C" void kernel_launch(void* const* d_in, const int* in_sizes, int n_in,
                              void* d_out, int out_size) {
    const int*   q      = (const int*)  d_in[0];
    const float* freqs  = (const float*)d_in[1];
    const float* exp_w  = (const float*)d_in[2];   // (8, 1632, 384)
    const float* proj_w = (const float*)d_in[3];   // (8, 384, 768)
    const float* blk_g  = (const float*)d_in[4];
    const float* blk_b  = (const float*)d_in[5];
    const float* ln_g   = (const float*)d_in[6];
    const float* ln_b   = (const float*)d_in[7];
    const float* out_w  = (const float*)d_in[8];   // (100, 384)
    float* out = (float*)d_out;

    float *x, *xn, *p;
    __half *xnh, *cat, *vt, *ph, *qh, *kh, *ew, *pw;
    cudaGetSymbolAddress((void**)&x,   g_x);
    cudaGetSymbolAddress((void**)&xn,  g_xn);
    cudaGetSymbolAddress((void**)&p,   g_p);
    cudaGetSymbolAddress((void**)&xnh, g_xnh);
    cudaGetSymbolAddress((void**)&cat, g_cat);
    cudaGetSymbolAddress((void**)&vt,  g_vt);
    cudaGetSymbolAddress((void**)&ph,  g_ph);
    cudaGetSymbolAddress((void**)&qh,  g_qh);
    cudaGetSymbolAddress((void**)&kh,  g_kh);
    cudaGetSymbolAddress((void**)&ew,  g_ew);
    cudaGetSymbolAddress((void**)&pw,  g_pw);

    // pre-permute/round weights (once per launch)
    permute_round_ew<<<NBq * HPERM, 96>>>(exp_w, ew);
    {
        int n4p = NBq * Dd * Ed / 4;
        round_w_kernel<<<(n4p + 255) / 256, 256>>>(
            (const float4*)proj_w, (__half2*)pw, n4p);
    }

    embed_ln_kernel<<<Tq, 128>>>(q, freqs, ln_g, ln_b, x);

    for (int blk = 0; blk < NBq; blk++) {
        ln_f16_kernel<<<Tq, 128>>>(x, xnh, blk_g + blk * Dd, blk_b + blk * Dd);

        // expand GEMM with fused geglu / qk-split / V^T epilogue
        gemm_bf_launch<3>(xnh, Dd, 0,
                          ew + (size_t)blk * HPERM * Dd, Dd, 0,
                          nullptr, nullptr, 0, 0,
                          Tq, HPERM, Dd, 1, 0);

        // scores: qh @ kh^T per batch (pre-scaled, K padded to 64), causal skip
        gemm_bf_launch<0>(qh, 64, (long long)Sq * 64,
                          kh, 64, (long long)Sq * 64,
                          p, nullptr, Sq, (long long)Sq * Sq,
                          Sq, Sq, 64, Bq, 1);

        softmax_kernel<<<dim3(Sq, Bq), 256>>>(p, ph);

        // attn = P @ V -> cat[:, 384:768] as fp16; K capped causally
        gemm_bf_launch<2>(ph, Sq, (long long)Sq * Sq,
                          vt, Sq, (long long)Dd * Sq,
                          nullptr, cat + Dd, Ed, (long long)Sq * Ed,
                          Sq, Dd, Sq, Bq, 2);

        // x += cat @ proj_w[blk]^T
        gemm_bf_launch<1>(cat, Ed, 0,
                          pw + (size_t)blk * Dd * Ed, Ed, 0,
                          x, nullptr, Dd, 0,
                          Tq, Dd, Ed, 1, 0);
    }

    ln_kernel<<<Tq, 128>>>(x, xn, ln_g, ln_b);
    gemm_simt<<<dim3(1, Tq / 128), 256>>>(xn, Dd, out_w, Dd, out, VOCABq, VOCABq, Dd);
}

// round 16
// speedup vs baseline: 2.2116x; 1.0198x over previous
#include <cuda_runtime.h>
#include <cuda_fp16.h>
#include <cstdint>

// ---------------- problem constants ----------------
#define Bq      4
#define Sq      2048
#define Tq      (Bq * Sq)      // 8192 tokens
#define Dd      384
#define QKd     48
#define Ed      768
#define Hd      1632           // 2*QK + 2*E
#define HPERM   1664           // permuted expand width: 1536 pairs + 64 qh + 64 kh
#define NBq     8
#define VOCABq  100

// ---------------- scratch (static device globals; no cudaMalloc) -----------
__device__ float g_x[Tq * Dd];                        // residual stream
__device__ float g_xn[Tq * Dd];                       // final-LN output (fp32)

#define AL16 __align__(16)
__device__ AL16 __half g_xnh[Tq * Dd];                 // LN out fp16
__device__ AL16 __half g_cat[(size_t)Tq * Ed];         // [loc | attn] fp16
__device__ AL16 __half g_qh[Tq * 64];                  // qh padded K=64 (pre-scaled)
__device__ AL16 __half g_kh[Tq * 64];                  // kh padded K=64
__device__ AL16 __half g_vt[(size_t)Bq * Dd * Sq];     // V^T per batch [d, s]
__device__ AL16 __half g_ew[(size_t)NBq * HPERM * Dd];
__device__ AL16 __half g_pw[NBq * Dd * Ed];

// ================= low-level helpers =================
__device__ __forceinline__ uint32_t s2u(const void* p) {
    uint32_t a;
    asm("{ .reg .u64 t; cvta.to.shared.u64 t, %1; cvt.u32.u64 %0, t; }" : "=r"(a) : "l"(p));
    return a;
}
__device__ __forceinline__ void cpa16(uint32_t dst, const void* src, uint32_t sz) {
    asm volatile("cp.async.cg.shared.global [%0], [%1], 16, %2;"
                 :: "r"(dst), "l"(src), "r"(sz) : "memory");
}
__device__ __forceinline__ void cpa_commit() {
    asm volatile("cp.async.commit_group;" ::: "memory");
}
template <int NN>
__device__ __forceinline__ void cpa_wait() {
    asm volatile("cp.async.wait_group %0;" :: "n"(NN) : "memory");
}
__device__ __forceinline__ uint32_t swz(uint32_t off) { return off ^ ((off >> 3) & 0x70); }

__device__ __forceinline__ void ldm_x4(uint32_t addr, uint32_t* r) {
    asm volatile("ldmatrix.sync.aligned.m8n8.x4.shared.b16 {%0,%1,%2,%3}, [%4];"
                 : "=r"(r[0]), "=r"(r[1]), "=r"(r[2]), "=r"(r[3]) : "r"(addr));
}
__device__ __forceinline__ void mma16816(float* c, const uint32_t* a, const uint32_t* b) {
    asm volatile("mma.sync.aligned.m16n8k16.row.col.f32.f16.f16.f32 "
                 "{%0,%1,%2,%3}, {%4,%5,%6,%7}, {%8,%9}, {%0,%1,%2,%3};"
                 : "+f"(c[0]), "+f"(c[1]), "+f"(c[2]), "+f"(c[3])
                 : "r"(a[0]), "r"(a[1]), "r"(a[2]), "r"(a[3]), "r"(b[0]), "r"(b[1]));
}

// ================= fp16 HMMA GEMM: C = A(MxK) * B(NxK)^T, single-term =====
// 128x128 CTA tile, BK=64, 16 warps (4Mx4N), cp.async 3-stage, 512 threads.
// OUTM: 0 = fp32 store, 1 = fp32 add, 2 = fp16 store,
//       3 = fused expand epilogue (geglu->cat/V^T, qk split) via device globals.
#define BTILE   16384                   // 128 rows x 64 fp16 x 2B
#define STAGE_B (2 * BTILE)             // Ah, Bh = 32 KB
#define NSTAGE  3
#define SHM_BF  (NSTAGE * STAGE_B + 128)
#define NTHR    512

template <int OUTM>
__global__ void __launch_bounds__(NTHR, 1)
gemm_bf(const __half* __restrict__ Ah_,
        int lda, long long sA,
        const __half* __restrict__ Bh_,
        int ldb, long long sB,
        float* __restrict__ Cf, __half* __restrict__ Ch,
        int ldc, long long sC, int N, int K) {
    int bm = blockIdx.y * 128;
    int bn = blockIdx.x * 128;
    int nch = K >> 6;

    const __half* Ah = Ah_ + (long long)blockIdx.z * sA;
    const __half* Bh = Bh_ + (long long)blockIdx.z * sB;

    extern __shared__ char dsm[];
    uint32_t base = (s2u(dsm) + 127u) & ~127u;

    int tid = threadIdx.x;
    int wid = tid >> 5, lane = tid & 31;
    int m0w = (wid >> 2) * 32;
    int n0w = (wid & 3) * 32;

    int lrow = tid >> 3;
    int lu   = tid & 7;

    float acc[2][4][4];
#pragma unroll
    for (int i = 0; i < 2; i++)
#pragma unroll
        for (int j = 0; j < 4; j++)
#pragma unroll
            for (int e = 0; e < 4; e++) acc[i][j][e] = 0.0f;

    uint32_t a_row  = (uint32_t)(lane & 15);
    uint32_t a_colb = (uint32_t)((lane >> 4) * 16);
    uint32_t b_row  = (uint32_t)(((lane >> 4) << 3) + (lane & 7));
    uint32_t b_colb = (uint32_t)(((lane >> 3) & 1) * 16);

    auto load_chunk = [&](int ch, int bsel) {
        int k0 = ch << 6;
        uint32_t tb = base + (uint32_t)bsel * STAGE_B;
#pragma unroll
        for (int i = 0; i < 2; i++) {
            int row = lrow + i * 64;
            uint32_t soff = swz((uint32_t)row * 128u + (uint32_t)lu * 16u);
            size_t aoff = (size_t)(bm + row) * lda + k0 + lu * 8;
            cpa16(tb + soff, Ah + aoff, 16u);
            uint32_t bsz = ((bn + row) < N) ? 16u : 0u;
            size_t boff = (size_t)(bn + row) * ldb + k0 + lu * 8;
            cpa16(tb + BTILE + soff, Bh + boff, bsz);
        }
    };

    auto compute = [&](int bsel) {
        uint32_t tb  = base + (uint32_t)bsel * STAGE_B;
        uint32_t tAh = tb, tBh = tb + BTILE;
#pragma unroll
        for (int ks = 0; ks < 4; ks++) {
            uint32_t kbyte = (uint32_t)ks * 32u;
            uint32_t afrag[2][4], bfrag[2][4];
#pragma unroll
            for (int mt = 0; mt < 2; mt++) {
                uint32_t rr = (uint32_t)(m0w + mt * 16) + a_row;
                ldm_x4(tAh + swz(rr * 128u + kbyte + a_colb), afrag[mt]);
            }
#pragma unroll
            for (int bt = 0; bt < 2; bt++) {
                uint32_t rr = (uint32_t)(n0w + bt * 16) + b_row;
                ldm_x4(tBh + swz(rr * 128u + kbyte + b_colb), bfrag[bt]);
            }
#pragma unroll
            for (int mt = 0; mt < 2; mt++)
#pragma unroll
                for (int nt = 0; nt < 4; nt++)
                    mma16816(acc[mt][nt], afrag[mt], &bfrag[nt >> 1][(nt & 1) * 2]);
        }
    };

    int issued = 0;
    if (issued < nch) { load_chunk(issued, issued % NSTAGE); cpa_commit(); issued++; }
    if (issued < nch) { load_chunk(issued, issued % NSTAGE); cpa_commit(); issued++; }
    for (int ch = 0; ch < nch; ch++) {
        if (issued < nch) { load_chunk(issued, issued % NSTAGE); cpa_commit(); issued++; }
        int pending = issued - ch - 1;
        if (pending >= 2)      cpa_wait<2>();
        else if (pending == 1) cpa_wait<1>();
        else                   cpa_wait<0>();
        __syncthreads();
        compute(ch % NSTAGE);
        __syncthreads();
    }

    // ---------------- epilogue ----------------
    if (OUTM == 3) {
        float* sf = reinterpret_cast<float*>((((uintptr_t)dsm) + 127) & ~(uintptr_t)127);
        const int LDS = 132;
#pragma unroll
        for (int mt = 0; mt < 2; mt++) {
            int r0 = m0w + mt * 16 + (lane >> 2);
#pragma unroll
            for (int nt = 0; nt < 4; nt++) {
                int c = n0w + nt * 8 + (lane & 3) * 2;
#pragma unroll
                for (int half = 0; half < 2; half++) {
                    int r = r0 + half * 8;
                    sf[r * LDS + c]     = acc[mt][nt][half * 2];
                    sf[r * LDS + c + 1] = acc[mt][nt][half * 2 + 1];
                }
            }
        }
        __syncthreads();
        if (bn < 1536) {
            int jbase = bn >> 1;
            bool isV = (jbase >= 384);
            if (!isV) {
#pragma unroll
                for (int i = 0; i < 16; i++) {
                    int vi = tid + i * NTHR;
                    int row = vi >> 6, u = vi & 63;
                    float lin = sf[row * LDS + 2 * u];
                    float pg  = sf[row * LDS + 2 * u + 1];
                    float val = lin * 0.5f * pg * (1.0f + erff(pg * 0.70710678118654752f));
                    g_cat[(size_t)(bm + row) * Ed + jbase + u] = __float2half_rn(val);
                }
            } else {
#pragma unroll
                for (int i = 0; i < 16; i++) {
                    int vi = tid + i * NTHR;
                    int row = vi & 127, u = vi >> 7;
                    float lin = sf[row * LDS + 2 * u];
                    float pg  = sf[row * LDS + 2 * u + 1];
                    float val = lin * 0.5f * pg * (1.0f + erff(pg * 0.70710678118654752f));
                    int t = bm + row;
                    int jj = jbase + u - 384;
                    size_t idx = ((size_t)(t >> 11) * Dd + jj) * Sq + (t & (Sq - 1));
                    g_vt[idx] = __float2half_rn(val);
                }
            }
        } else {
#pragma unroll
            for (int i = 0; i < 32; i++) {
                int vi = tid + i * NTHR;
                int row = vi >> 7, c = vi & 127;
                float val = sf[row * LDS + c];
                size_t idx = (size_t)(bm + row) * 64 + (c & 63);
                if (c < 64) g_qh[idx] = __float2half_rn(val);
                else        g_kh[idx] = __float2half_rn(val);
            }
        }
        return;
    }

    float* CfB = (OUTM != 2) ? Cf + (long long)blockIdx.z * sC : nullptr;
    __half* ChB = (OUTM == 2) ? Ch + (long long)blockIdx.z * sC : nullptr;
#pragma unroll
    for (int mt = 0; mt < 2; mt++) {
        int row0 = bm + m0w + mt * 16 + (lane >> 2);
#pragma unroll
        for (int nt = 0; nt < 4; nt++) {
            int col = bn + n0w + nt * 8 + (lane & 3) * 2;
            float* c = acc[mt][nt];
#pragma unroll
            for (int half = 0; half < 2; half++) {
                int row = row0 + half * 8;
                float v0 = c[half * 2], v1 = c[half * 2 + 1];
                if (OUTM == 2) {
                    if (col + 1 < N)
                        *reinterpret_cast<__half2*>(ChB + (size_t)row * ldc + col) =
                            __floats2half2_rn(v0, v1);
                } else {
                    float* Crow = CfB + (size_t)row * ldc;
                    if (col + 1 < N) {
                        float2 cv;
                        if (OUTM == 1) {
                            cv = *reinterpret_cast<float2*>(Crow + col);
                            cv.x += v0; cv.y += v1;
                        } else cv = make_float2(v0, v1);
                        *reinterpret_cast<float2*>(Crow + col) = cv;
                    } else if (col < N) {
                        Crow[col] = (OUTM == 1) ? (Crow[col] + v0) : v0;
                    }
                }
            }
        }
    }
}

template <int OUTM>
static inline void gemm_bf_launch(const __half* Ah, int lda, long long sA,
                                  const __half* Bh, int ldb, long long sB,
                                  float* Cf, __half* Ch,
                                  int ldc, long long sC,
                                  int M, int N, int K, int batch) {
    dim3 grid((N + 127) / 128, M / 128, batch);
    cudaFuncSetAttribute(gemm_bf<OUTM>, cudaFuncAttributeMaxDynamicSharedMemorySize, SHM_BF);
    gemm_bf<OUTM><<<grid, NTHR, SHM_BF>>>(Ah, lda, sA, Bh, ldb, sB,
                                          Cf, Ch, ldc, sC, N, K);
}

// ================= flash attention: scores + online softmax + P@V =========
// CTA = (d-slice ns of 128, query block qb of 128, batch). 512 threads,
// 16 warps 4Mx4N (warp tile 32x32 for both S and PV phases).
// smem: stats 5632B + Q 16K + K 16K + P 2x16K + V 2x16K = 103936 B.
#define FLASH_SHM (5632 + 6 * 16384)

__global__ void __launch_bounds__(512, 1)
flash_kernel(const __half* __restrict__ qh, const __half* __restrict__ kh,
             const __half* __restrict__ vt, __half* __restrict__ cat) {
    int ns = blockIdx.x;                              // 0..2  (d slice)
    int qb = (int)gridDim.y - 1 - (int)blockIdx.y;    // biggest-K first
    int b  = blockIdx.z;

    extern __shared__ char dsm[];
    float* fm   = reinterpret_cast<float*>(dsm);      // [128] running max
    float* fl   = fm + 128;                           // [128] running sum
    float* fsc  = fl + 128;                           // [128] rescale factor
    float* fpmx = fsc + 128;                          // [4][128]
    float* fpsm = fpmx + 512;                         // [4][128]
    char*  tile = dsm + 5632;                         // 128B aligned (5632=44*128)
    uint32_t sQ  = s2u(tile);
    uint32_t sK  = sQ + 16384;
    uint32_t sP0 = sK + 16384, sP1 = sP0 + 16384;
    uint32_t sV0 = sP1 + 16384, sV1 = sV0 + 16384;
    char* tP0 = tile + 16384 * 2;   // pointer forms for stores
    char* tP1 = tile + 16384 * 3;

    int tid = threadIdx.x;
    int wid = tid >> 5, lane = tid & 31;
    int m0w = (wid >> 2) * 32, n0w = (wid & 3) * 32;

    uint32_t a_row  = (uint32_t)(lane & 15);
    uint32_t a_colb = (uint32_t)((lane >> 4) * 16);
    uint32_t b_row  = (uint32_t)(((lane >> 4) << 3) + (lane & 7));
    uint32_t b_colb = (uint32_t)(((lane >> 3) & 1) * 16);

    float oacc[2][4][4];
#pragma unroll
    for (int i = 0; i < 2; i++)
#pragma unroll
        for (int j = 0; j < 4; j++)
#pragma unroll
            for (int e = 0; e < 4; e++) oacc[i][j][e] = 0.0f;
    if (tid < 128) { fm[tid] = -1.0e30f; fl[tid] = 0.0f; }

    // load Q tile (128 q rows x 64 dims)
    {
        const __half* qbase = qh + ((size_t)b * Sq + (size_t)qb * 128) * 64;
#pragma unroll
        for (int i = 0; i < 2; i++) {
            int u = tid + i * 512;
            int row = u >> 3, cu = u & 7;
            cpa16(sQ + swz((uint32_t)row * 128u + (uint32_t)cu * 16u),
                  qbase + (size_t)row * 64 + cu * 8, 16u);
        }
        cpa_commit();
    }

    for (int kb = 0; kb <= qb; kb++) {
        // load K tile and both V chunks
        {
            const __half* kbase = kh + ((size_t)b * Sq + (size_t)kb * 128) * 64;
#pragma unroll
            for (int i = 0; i < 2; i++) {
                int u = tid + i * 512;
                int row = u >> 3, cu = u & 7;
                cpa16(sK + swz((uint32_t)row * 128u + (uint32_t)cu * 16u),
                      kbase + (size_t)row * 64 + cu * 8, 16u);
            }
            const __half* vbase = vt + ((size_t)b * Dd + (size_t)ns * 128) * Sq + kb * 128;
#pragma unroll
            for (int i = 0; i < 4; i++) {
                int u = tid + i * 512;             // 2048 units over 2 chunks
                int chunk = u >> 10;
                int uu = u & 1023;
                int row = uu >> 3, cu = uu & 7;
                cpa16((chunk ? sV1 : sV0) + swz((uint32_t)row * 128u + (uint32_t)cu * 16u),
                      vbase + (size_t)row * Sq + chunk * 64 + cu * 8, 16u);
            }
            cpa_commit();
            cpa_wait<0>();
            __syncthreads();
        }

        // ---- S = Q @ K^T (K=64, 1 chunk) ----
        float sacc[2][4][4];
#pragma unroll
        for (int i = 0; i < 2; i++)
#pragma unroll
            for (int j = 0; j < 4; j++)
#pragma unroll
                for (int e = 0; e < 4; e++) sacc[i][j][e] = 0.0f;
#pragma unroll
        for (int ks = 0; ks < 4; ks++) {
            uint32_t kbyte = (uint32_t)ks * 32u;
            uint32_t af[2][4], bf[2][4];
#pragma unroll
            for (int mt = 0; mt < 2; mt++) {
                uint32_t rr = (uint32_t)(m0w + mt * 16) + a_row;
                ldm_x4(sQ + swz(rr * 128u + kbyte + a_colb), af[mt]);
            }
#pragma unroll
            for (int bt = 0; bt < 2; bt++) {
                uint32_t rr = (uint32_t)(n0w + bt * 16) + b_row;
                ldm_x4(sK + swz(rr * 128u + kbyte + b_colb), bf[bt]);
            }
#pragma unroll
            for (int mt = 0; mt < 2; mt++)
#pragma unroll
                for (int nt = 0; nt < 4; nt++)
                    mma16816(sacc[mt][nt], af[mt], &bf[nt >> 1][(nt & 1) * 2]);
        }

        // ---- causal mask on diagonal block ----
        if (kb == qb) {
#pragma unroll
            for (int mt = 0; mt < 2; mt++)
#pragma unroll
                for (int half = 0; half < 2; half++) {
                    int gr = m0w + mt * 16 + (lane >> 2) + half * 8;
#pragma unroll
                    for (int nt = 0; nt < 4; nt++)
#pragma unroll
                        for (int e = 0; e < 2; e++) {
                            int gc = n0w + nt * 8 + (lane & 3) * 2 + e;
                            if (gc > gr) sacc[mt][nt][half * 2 + e] = -3.0e38f;
                        }
                }
        }

        // ---- row max (warp shuffle + smem across 4 N-warps) ----
#pragma unroll
        for (int mt = 0; mt < 2; mt++)
#pragma unroll
            for (int half = 0; half < 2; half++) {
                int row = m0w + mt * 16 + (lane >> 2) + half * 8;
                float r = -3.0e38f;
#pragma unroll
                for (int nt = 0; nt < 4; nt++) {
                    r = fmaxf(r, sacc[mt][nt][half * 2]);
                    r = fmaxf(r, sacc[mt][nt][half * 2 + 1]);
                }
                r = fmaxf(r, __shfl_xor_sync(0xffffffffu, r, 1));
                r = fmaxf(r, __shfl_xor_sync(0xffffffffu, r, 2));
                if ((lane & 3) == 0) fpmx[(wid & 3) * 128 + row] = r;
            }
        __syncthreads();
        if (tid < 128) {
            float mo = fm[tid];
            float mn = fmaxf(fmaxf(fpmx[tid], fpmx[128 + tid]),
                             fmaxf(fpmx[256 + tid], fpmx[384 + tid]));
            mn = fmaxf(mo, mn);
            float sc = __expf(mo - mn);
            fm[tid] = mn; fsc[tid] = sc; fl[tid] *= sc;
        }
        __syncthreads();

        // ---- exp, write P fp16 to smem, rescale out acc, row sums ----
#pragma unroll
        for (int mt = 0; mt < 2; mt++)
#pragma unroll
            for (int half = 0; half < 2; half++) {
                int row = m0w + mt * 16 + (lane >> 2) + half * 8;
                float mrow = fm[row], sc = fsc[row];
                float ps = 0.0f;
#pragma unroll
                for (int nt = 0; nt < 4; nt++) {
                    float p0 = __expf(sacc[mt][nt][half * 2]     - mrow);
                    float p1 = __expf(sacc[mt][nt][half * 2 + 1] - mrow);
                    ps += p0 + p1;
                    oacc[mt][nt][half * 2]     *= sc;
                    oacc[mt][nt][half * 2 + 1] *= sc;
                    int gc = n0w + nt * 8 + (lane & 3) * 2;
                    char* tp = (gc >= 64) ? tP1 : tP0;
                    *reinterpret_cast<__half2*>(
                        tp + swz((uint32_t)row * 128u + (uint32_t)(gc & 63) * 2u)) =
                        __floats2half2_rn(p0, p1);
                }
                ps += __shfl_xor_sync(0xffffffffu, ps, 1);
                ps += __shfl_xor_sync(0xffffffffu, ps, 2);
                if ((lane & 3) == 0) fpsm[(wid & 3) * 128 + row] = ps;
            }
        __syncthreads();
        if (tid < 128)
            fl[tid] += fpsm[tid] + fpsm[128 + tid] + fpsm[256 + tid] + fpsm[384 + tid];
        __syncthreads();

        // ---- out += P @ V (2 chunks of K=64) ----
#pragma unroll
        for (int c = 0; c < 2; c++) {
            uint32_t aB = c ? sP1 : sP0;
            uint32_t bB = c ? sV1 : sV0;
#pragma unroll
            for (int ks = 0; ks < 4; ks++) {
                uint32_t kbyte = (uint32_t)ks * 32u;
                uint32_t af[2][4], bf[2][4];
#pragma unroll
                for (int mt = 0; mt < 2; mt++) {
                    uint32_t rr = (uint32_t)(m0w + mt * 16) + a_row;
                    ldm_x4(aB + swz(rr * 128u + kbyte + a_colb), af[mt]);
                }
#pragma unroll
                for (int bt = 0; bt < 2; bt++) {
                    uint32_t rr = (uint32_t)(n0w + bt * 16) + b_row;
                    ldm_x4(bB + swz(rr * 128u + kbyte + b_colb), bf[bt]);
                }
#pragma unroll
                for (int mt = 0; mt < 2; mt++)
#pragma unroll
                    for (int nt = 0; nt < 4; nt++)
                        mma16816(oacc[mt][nt], af[mt], &bf[nt >> 1][(nt & 1) * 2]);
            }
        }
        __syncthreads();   // tiles reusable next iteration
    }

    // ---- epilogue: normalize and store to cat[:, 384 + ns*128 ..] ----
#pragma unroll
    for (int mt = 0; mt < 2; mt++)
#pragma unroll
        for (int half = 0; half < 2; half++) {
            int row = m0w + mt * 16 + (lane >> 2) + half * 8;
            float inv = 1.0f / fl[row];
            size_t t = (size_t)b * Sq + (size_t)qb * 128 + row;
#pragma unroll
            for (int nt = 0; nt < 4; nt++) {
                float o0 = oacc[mt][nt][half * 2]     * inv;
                float o1 = oacc[mt][nt][half * 2 + 1] * inv;
                int gc = 384 + ns * 128 + n0w + nt * 8 + (lane & 3) * 2;
                *reinterpret_cast<__half2*>(cat + t * Ed + gc) = __floats2half2_rn(o0, o1);
            }
        }
}

// ---------------- reductions ----------------
__device__ __forceinline__ float warp_sum(float v) {
#pragma unroll
    for (int o = 16; o; o >>= 1) v += __shfl_xor_sync(0xffffffffu, v, o);
    return v;
}

// ---------------- permute + fp16-round expand weights ----------------
__global__ void permute_round_ew(const float* __restrict__ exp_w,
                                 __half* __restrict__ wout) {
    int rid = blockIdx.x;
    int blk = rid / HPERM, fp = rid % HPERM;
    int f = 0; bool valid; float scale = 1.0f;
    if (fp < 1536) {
        int j = fp >> 1;
        f = (fp & 1) ? (2 * QKd + Ed + j) : (2 * QKd + j);
        valid = true;
    } else if (fp < 1600) {
        int d = fp - 1536;
        valid = (d < QKd); f = d;
        scale = 0.14433756729740643f;
    } else {
        int d = fp - 1600;
        valid = (d < QKd); f = QKd + d;
    }
    int tx = threadIdx.x;
    float4 x = make_float4(0.f, 0.f, 0.f, 0.f);
    if (valid)
        x = reinterpret_cast<const float4*>(exp_w + ((size_t)blk * Hd + f) * Dd)[tx];
    size_t o = ((size_t)blk * HPERM + fp) * Dd + tx * 4;
    *reinterpret_cast<__half2*>(wout + o)     = __floats2half2_rn(x.x * scale, x.y * scale);
    *reinterpret_cast<__half2*>(wout + o + 2) = __floats2half2_rn(x.z * scale, x.w * scale);
}

// ---------------- proj weights: fp32 -> fp16 round ----------------
__global__ void round_w_kernel(const float4* __restrict__ src,
                               __half2* __restrict__ dst, int n4) {
    int i = blockIdx.x * 256 + threadIdx.x;
    if (i >= n4) return;
    float4 x = src[i];
    dst[2 * i]     = __floats2half2_rn(x.x, x.y);
    dst[2 * i + 1] = __floats2half2_rn(x.z, x.w);
}

// ---------------- embed (sin/cos) + LayerNorm (fp32 out) ----------------
__global__ void embed_ln_kernel(const int* __restrict__ q,
                                const float* __restrict__ freqs,
                                const float* __restrict__ g,
                                const float* __restrict__ b,
                                float* __restrict__ y) {
    int t = blockIdx.x;
    int tid = threadIdx.x;
    float qv = (float)q[t];
    float v[3];
#pragma unroll
    for (int k = 0; k < 3; k++) {
        int d = tid + k * 128;
        if (d < Dd / 2) v[k] = sinf(qv * freqs[d]);
        else            v[k] = cosf(qv * freqs[d - Dd / 2]);
    }
    float s = v[0] + v[1] + v[2];
    float sq = v[0]*v[0] + v[1]*v[1] + v[2]*v[2];
    s = warp_sum(s); sq = warp_sum(sq);
    __shared__ float shs[4], shq[4], mr[2];
    if ((tid & 31) == 0) { shs[tid >> 5] = s; shq[tid >> 5] = sq; }
    __syncthreads();
    if (tid == 0) {
        float ts = shs[0]+shs[1]+shs[2]+shs[3], tq = shq[0]+shq[1]+shq[2]+shq[3];
        float mean = ts * (1.0f / Dd);
        float var  = tq * (1.0f / Dd) - mean * mean;
        mr[0] = mean; mr[1] = rsqrtf(var + 1e-5f);
    }
    __syncthreads();
    float mean = mr[0], rstd = mr[1];
    float* yr = y + (size_t)t * Dd;
#pragma unroll
    for (int k = 0; k < 3; k++) {
        int d = tid + k * 128;
        yr[d] = (v[k] - mean) * rstd * g[d] + b[d];
    }
}

// ---------------- LayerNorm, fp32 out (final LN) ----------------
__global__ void ln_kernel(const float* __restrict__ x, float* __restrict__ y,
                          const float* __restrict__ g, const float* __restrict__ b) {
    int t = blockIdx.x;
    int tid = threadIdx.x;
    const float* xr = x + (size_t)t * Dd;
    float v0 = xr[tid], v1 = xr[tid + 128], v2 = xr[tid + 256];
    float s  = v0 + v1 + v2;
    float sq = v0*v0 + v1*v1 + v2*v2;
    s = warp_sum(s); sq = warp_sum(sq);
    __shared__ float shs[4], shq[4], mr[2];
    if ((tid & 31) == 0) { shs[tid >> 5] = s; shq[tid >> 5] = sq; }
    __syncthreads();
    if (tid == 0) {
        float ts = shs[0]+shs[1]+shs[2]+shs[3], tq = shq[0]+shq[1]+shq[2]+shq[3];
        float mean = ts * (1.0f / Dd);
        float var  = tq * (1.0f / Dd) - mean * mean;
        mr[0] = mean; mr[1] = rsqrtf(var + 1e-5f);
    }
    __syncthreads();
    float mean = mr[0], rstd = mr[1];
    float* yr = y + (size_t)t * Dd;
    yr[tid]       = (v0 - mean) * rstd * g[tid]       + b[tid];
    yr[tid + 128] = (v1 - mean) * rstd * g[tid + 128] + b[tid + 128];
    yr[tid + 256] = (v2 - mean) * rstd * g[tid + 256] + b[tid + 256];
}

// ---------------- LayerNorm, fp16 out (per-block LN) ----------------
__global__ void ln_f16_kernel(const float* __restrict__ x,
                              __half* __restrict__ yh,
                              const float* __restrict__ g,
                              const float* __restrict__ b) {
    int t = blockIdx.x;
    int tid = threadIdx.x;
    const float* xr = x + (size_t)t * Dd;
    float v0 = xr[tid], v1 = xr[tid + 128], v2 = xr[tid + 256];
    float s  = v0 + v1 + v2;
    float sq = v0*v0 + v1*v1 + v2*v2;
    s = warp_sum(s); sq = warp_sum(sq);
    __shared__ float shs[4], shq[4], mr[2];
    if ((tid & 31) == 0) { shs[tid >> 5] = s; shq[tid >> 5] = sq; }
    __syncthreads();
    if (tid == 0) {
        float ts = shs[0]+shs[1]+shs[2]+shs[3], tq = shq[0]+shq[1]+shq[2]+shq[3];
        float mean = ts * (1.0f / Dd);
        float var  = tq * (1.0f / Dd) - mean * mean;
        mr[0] = mean; mr[1] = rsqrtf(var + 1e-5f);
    }
    __syncthreads();
    float mean = mr[0], rstd = mr[1];
    size_t rb = (size_t)t * Dd;
#pragma unroll
    for (int k = 0; k < 3; k++) {
        int d = tid + k * 128;
        float vv = (k == 0 ? v0 : (k == 1 ? v1 : v2));
        float y = (vv - mean) * rstd * g[d] + b[d];
        yh[rb + d] = __float2half_rn(y);
    }
}

// ---------------- SIMT SGEMM (logits only) ----------------
__global__ void __launch_bounds__(256, 2)
gemm_simt(const float* __restrict__ A, int lda,
          const float* __restrict__ B, int ldb,
          float* __restrict__ C, int ldc, int N, int K) {
    int bm = blockIdx.y * 128;
    int bn = blockIdx.x * 128;

    __shared__ float As[8][128];
    __shared__ float Bs[8][128];
    int tid = threadIdx.x;
    int tx = tid & 15, ty = tid >> 4;
    float acc[8][8] = {};

    int lrow = tid >> 1;
    int lkk  = (tid & 1) * 4;
    const float* Ap = A + (size_t)(bm + lrow) * lda + lkk;
    bool bvalid = (bn + lrow) < N;
    const float* Bp = B + (size_t)(bn + lrow) * ldb + lkk;

    for (int k0 = 0; k0 < K; k0 += 8) {
        float4 av = *reinterpret_cast<const float4*>(Ap + k0);
        float4 bv = bvalid ? *reinterpret_cast<const float4*>(Bp + k0)
                           : make_float4(0.f, 0.f, 0.f, 0.f);
        As[lkk+0][lrow]=av.x; As[lkk+1][lrow]=av.y; As[lkk+2][lrow]=av.z; As[lkk+3][lrow]=av.w;
        Bs[lkk+0][lrow]=bv.x; Bs[lkk+1][lrow]=bv.y; Bs[lkk+2][lrow]=bv.z; Bs[lkk+3][lrow]=bv.w;
        __syncthreads();
#pragma unroll
        for (int kk = 0; kk < 8; kk++) {
            float a[8], b[8];
            *reinterpret_cast<float4*>(&a[0]) = *reinterpret_cast<const float4*>(&As[kk][ty*8]);
            *reinterpret_cast<float4*>(&a[4]) = *reinterpret_cast<const float4*>(&As[kk][ty*8+4]);
            *reinterpret_cast<float4*>(&b[0]) = *reinterpret_cast<const float4*>(&Bs[kk][tx*8]);
            *reinterpret_cast<float4*>(&b[4]) = *reinterpret_cast<const float4*>(&Bs[kk][tx*8+4]);
#pragma unroll
            for (int i = 0; i < 8; i++)
#pragma unroll
                for (int j = 0; j < 8; j++)
                    acc[i][j] += a[i] * b[j];
        }
        __syncthreads();
    }
#pragma unroll
    for (int i = 0; i < 8; i++) {
        float* Crow = C + (size_t)(bm + ty * 8 + i) * ldc;
#pragma unroll
        for (int j = 0; j < 8; j++) {
            int n = bn + tx * 8 + j;
            if (n < N) Crow[n] = acc[i][j];
        }
    }
}

// ---------------- driver ----------------
extern "C" void kernel_launch(void* const* d_in, const int* in_sizes, int n_in,
                              void* d_out, int out_size) {
    const int*   q      = (const int*)  d_in[0];
    const float* freqs  = (const float*)d_in[1];
    const float* exp_w  = (const float*)d_in[2];
    const float* proj_w = (const float*)d_in[3];
    const float* blk_g  = (const float*)d_in[4];
    const float* blk_b  = (const float*)d_in[5];
    const float* ln_g   = (const float*)d_in[6];
    const float* ln_b   = (const float*)d_in[7];
    const float* out_w  = (const float*)d_in[8];
    float* out = (float*)d_out;

    float *x, *xn;
    __half *xnh, *cat, *vt, *qh, *kh, *ew, *pw;
    cudaGetSymbolAddress((void**)&x,   g_x);
    cudaGetSymbolAddress((void**)&xn,  g_xn);
    cudaGetSymbolAddress((void**)&xnh, g_xnh);
    cudaGetSymbolAddress((void**)&cat, g_cat);
    cudaGetSymbolAddress((void**)&vt,  g_vt);
    cudaGetSymbolAddress((void**)&qh,  g_qh);
    cudaGetSymbolAddress((void**)&kh,  g_kh);
    cudaGetSymbolAddress((void**)&ew,  g_ew);
    cudaGetSymbolAddress((void**)&pw,  g_pw);

    permute_round_ew<<<NBq * HPERM, 96>>>(exp_w, ew);
    {
        int n4p = NBq * Dd * Ed / 4;
        round_w_kernel<<<(n4p + 255) / 256, 256>>>(
            (const float4*)proj_w, (__half2*)pw, n4p);
    }

    embed_ln_kernel<<<Tq, 128>>>(q, freqs, ln_g, ln_b, x);

    cudaFuncSetAttribute(flash_kernel, cudaFuncAttributeMaxDynamicSharedMemorySize, FLASH_SHM);

    for (int blk = 0; blk < NBq; blk++) {
        ln_f16_kernel<<<Tq, 128>>>(x, xnh, blk_g + blk * Dd, blk_b + blk * Dd);

        // expand GEMM with fused geglu / qk-split / V^T epilogue
        gemm_bf_launch<3>(xnh, Dd, 0,
                          ew + (size_t)blk * HPERM * Dd, Dd, 0,
                          nullptr, nullptr, 0, 0,
                          Tq, HPERM, Dd, 1);

        // fused attention: scores + online softmax + P@V -> cat[:, 384:768]
        flash_kernel<<<dim3(3, Sq / 128, Bq), 512, FLASH_SHM>>>(qh, kh, vt, cat);

        // x += cat @ proj_w[blk]^T
        gemm_bf_launch<1>(cat, Ed, 0,
                          pw + (size_t)blk * Dd * Ed, Ed, 0,
                          x, nullptr, Dd, 0,
                          Tq, Dd, Ed, 1);
    }

    ln_kernel<<<Tq, 128>>>(x, xn, ln_g, ln_b);
    gemm_simt<<<dim3(1, Tq / 128), 256>>>(xn, Dd, out_w, Dd, out, VOCABq, VOCABq, Dd);
}

// round 17
// speedup vs baseline: 2.3396x; 1.0579x over previous
#include <cuda_runtime.h>
#include <cuda_fp16.h>
#include <cstdint>

// ---------------- problem constants ----------------
#define Bq      4
#define Sq      2048
#define Tq      (Bq * Sq)      // 8192 tokens
#define Dd      384
#define QKd     48
#define Ed      768
#define Hd      1632           // 2*QK + 2*E
#define HPERM   1664           // permuted expand width: 1536 pairs + 64 qh + 64 kh
#define NBq     8
#define VOCABq  100

// ---------------- scratch (static device globals; no cudaMalloc) -----------
__device__ float g_x[Tq * Dd];                        // residual stream
__device__ float g_xn[Tq * Dd];                       // final-LN output (fp32)

#define AL16 __align__(16)
__device__ AL16 __half g_xnh[Tq * Dd];                 // LN out fp16
__device__ AL16 __half g_cat[(size_t)Tq * Ed];         // [loc | attn] fp16
__device__ AL16 __half g_qh[Tq * 64];                  // qh padded K=64 (pre-scaled)
__device__ AL16 __half g_kh[Tq * 64];                  // kh padded K=64
__device__ AL16 __half g_vt[(size_t)Bq * Dd * Sq];     // V^T per batch [d, s]
__device__ AL16 __half g_ew[(size_t)NBq * HPERM * Dd];
__device__ AL16 __half g_pw[NBq * Dd * Ed];

// ================= low-level helpers =================
__device__ __forceinline__ uint32_t s2u(const void* p) {
    uint32_t a;
    asm("{ .reg .u64 t; cvta.to.shared.u64 t, %1; cvt.u32.u64 %0, t; }" : "=r"(a) : "l"(p));
    return a;
}
__device__ __forceinline__ void cpa16(uint32_t dst, const void* src, uint32_t sz) {
    asm volatile("cp.async.cg.shared.global [%0], [%1], 16, %2;"
                 :: "r"(dst), "l"(src), "r"(sz) : "memory");
}
__device__ __forceinline__ void cpa_commit() {
    asm volatile("cp.async.commit_group;" ::: "memory");
}
template <int NN>
__device__ __forceinline__ void cpa_wait() {
    asm volatile("cp.async.wait_group %0;" :: "n"(NN) : "memory");
}
__device__ __forceinline__ uint32_t swz(uint32_t off) { return off ^ ((off >> 3) & 0x70); }

__device__ __forceinline__ void ldm_x4(uint32_t addr, uint32_t* r) {
    asm volatile("ldmatrix.sync.aligned.m8n8.x4.shared.b16 {%0,%1,%2,%3}, [%4];"
                 : "=r"(r[0]), "=r"(r[1]), "=r"(r[2]), "=r"(r[3]) : "r"(addr));
}
__device__ __forceinline__ void mma16816(float* c, const uint32_t* a, const uint32_t* b) {
    asm volatile("mma.sync.aligned.m16n8k16.row.col.f32.f16.f16.f32 "
                 "{%0,%1,%2,%3}, {%4,%5,%6,%7}, {%8,%9}, {%0,%1,%2,%3};"
                 : "+f"(c[0]), "+f"(c[1]), "+f"(c[2]), "+f"(c[3])
                 : "r"(a[0]), "r"(a[1]), "r"(a[2]), "r"(a[3]), "r"(b[0]), "r"(b[1]));
}

// ================= fp16 HMMA GEMM: C = A(MxK) * B(NxK)^T, single-term =====
// 128x128 CTA tile, BK=64, 16 warps (4Mx4N), cp.async 3-stage, 512 threads.
// OUTM: 0 = fp32 store, 1 = fp32 add, 2 = fp16 store,
//       3 = fused expand epilogue (geglu->cat/V^T, qk split) via device globals.
#define BTILE   16384                   // 128 rows x 64 fp16 x 2B
#define STAGE_B (2 * BTILE)             // Ah, Bh = 32 KB
#define NSTAGE  3
#define SHM_BF  (NSTAGE * STAGE_B + 128)
#define NTHR    512

template <int OUTM>
__global__ void __launch_bounds__(NTHR, 1)
gemm_bf(const __half* __restrict__ Ah_,
        int lda, long long sA,
        const __half* __restrict__ Bh_,
        int ldb, long long sB,
        float* __restrict__ Cf, __half* __restrict__ Ch,
        int ldc, long long sC, int N, int K) {
    int bm = blockIdx.y * 128;
    int bn = blockIdx.x * 128;
    int nch = K >> 6;

    const __half* Ah = Ah_ + (long long)blockIdx.z * sA;
    const __half* Bh = Bh_ + (long long)blockIdx.z * sB;

    extern __shared__ char dsm[];
    uint32_t base = (s2u(dsm) + 127u) & ~127u;

    int tid = threadIdx.x;
    int wid = tid >> 5, lane = tid & 31;
    int m0w = (wid >> 2) * 32;
    int n0w = (wid & 3) * 32;

    int lrow = tid >> 3;
    int lu   = tid & 7;

    float acc[2][4][4];
#pragma unroll
    for (int i = 0; i < 2; i++)
#pragma unroll
        for (int j = 0; j < 4; j++)
#pragma unroll
            for (int e = 0; e < 4; e++) acc[i][j][e] = 0.0f;

    uint32_t a_row  = (uint32_t)(lane & 15);
    uint32_t a_colb = (uint32_t)((lane >> 4) * 16);
    uint32_t b_row  = (uint32_t)(((lane >> 4) << 3) + (lane & 7));
    uint32_t b_colb = (uint32_t)(((lane >> 3) & 1) * 16);

    auto load_chunk = [&](int ch, int bsel) {
        int k0 = ch << 6;
        uint32_t tb = base + (uint32_t)bsel * STAGE_B;
#pragma unroll
        for (int i = 0; i < 2; i++) {
            int row = lrow + i * 64;
            uint32_t soff = swz((uint32_t)row * 128u + (uint32_t)lu * 16u);
            size_t aoff = (size_t)(bm + row) * lda + k0 + lu * 8;
            cpa16(tb + soff, Ah + aoff, 16u);
            uint32_t bsz = ((bn + row) < N) ? 16u : 0u;
            size_t boff = (size_t)(bn + row) * ldb + k0 + lu * 8;
            cpa16(tb + BTILE + soff, Bh + boff, bsz);
        }
    };

    auto compute = [&](int bsel) {
        uint32_t tb  = base + (uint32_t)bsel * STAGE_B;
        uint32_t tAh = tb, tBh = tb + BTILE;
#pragma unroll
        for (int ks = 0; ks < 4; ks++) {
            uint32_t kbyte = (uint32_t)ks * 32u;
            uint32_t afrag[2][4], bfrag[2][4];
#pragma unroll
            for (int mt = 0; mt < 2; mt++) {
                uint32_t rr = (uint32_t)(m0w + mt * 16) + a_row;
                ldm_x4(tAh + swz(rr * 128u + kbyte + a_colb), afrag[mt]);
            }
#pragma unroll
            for (int bt = 0; bt < 2; bt++) {
                uint32_t rr = (uint32_t)(n0w + bt * 16) + b_row;
                ldm_x4(tBh + swz(rr * 128u + kbyte + b_colb), bfrag[bt]);
            }
#pragma unroll
            for (int mt = 0; mt < 2; mt++)
#pragma unroll
                for (int nt = 0; nt < 4; nt++)
                    mma16816(acc[mt][nt], afrag[mt], &bfrag[nt >> 1][(nt & 1) * 2]);
        }
    };

    int issued = 0;
    if (issued < nch) { load_chunk(issued, issued % NSTAGE); cpa_commit(); issued++; }
    if (issued < nch) { load_chunk(issued, issued % NSTAGE); cpa_commit(); issued++; }
    for (int ch = 0; ch < nch; ch++) {
        if (issued < nch) { load_chunk(issued, issued % NSTAGE); cpa_commit(); issued++; }
        int pending = issued - ch - 1;
        if (pending >= 2)      cpa_wait<2>();
        else if (pending == 1) cpa_wait<1>();
        else                   cpa_wait<0>();
        __syncthreads();
        compute(ch % NSTAGE);
        __syncthreads();
    }

    // ---------------- epilogue ----------------
    if (OUTM == 3) {
        float* sf = reinterpret_cast<float*>((((uintptr_t)dsm) + 127) & ~(uintptr_t)127);
        const int LDS = 132;
#pragma unroll
        for (int mt = 0; mt < 2; mt++) {
            int r0 = m0w + mt * 16 + (lane >> 2);
#pragma unroll
            for (int nt = 0; nt < 4; nt++) {
                int c = n0w + nt * 8 + (lane & 3) * 2;
#pragma unroll
                for (int half = 0; half < 2; half++) {
                    int r = r0 + half * 8;
                    sf[r * LDS + c]     = acc[mt][nt][half * 2];
                    sf[r * LDS + c + 1] = acc[mt][nt][half * 2 + 1];
                }
            }
        }
        __syncthreads();
        if (bn < 1536) {
            int jbase = bn >> 1;
            bool isV = (jbase >= 384);
            if (!isV) {
#pragma unroll
                for (int i = 0; i < 16; i++) {
                    int vi = tid + i * NTHR;
                    int row = vi >> 6, u = vi & 63;
                    float lin = sf[row * LDS + 2 * u];
                    float pg  = sf[row * LDS + 2 * u + 1];
                    float val = lin * 0.5f * pg * (1.0f + erff(pg * 0.70710678118654752f));
                    g_cat[(size_t)(bm + row) * Ed + jbase + u] = __float2half_rn(val);
                }
            } else {
#pragma unroll
                for (int i = 0; i < 16; i++) {
                    int vi = tid + i * NTHR;
                    int row = vi & 127, u = vi >> 7;
                    float lin = sf[row * LDS + 2 * u];
                    float pg  = sf[row * LDS + 2 * u + 1];
                    float val = lin * 0.5f * pg * (1.0f + erff(pg * 0.70710678118654752f));
                    int t = bm + row;
                    int jj = jbase + u - 384;
                    size_t idx = ((size_t)(t >> 11) * Dd + jj) * Sq + (t & (Sq - 1));
                    g_vt[idx] = __float2half_rn(val);
                }
            }
        } else {
#pragma unroll
            for (int i = 0; i < 32; i++) {
                int vi = tid + i * NTHR;
                int row = vi >> 7, c = vi & 127;
                float val = sf[row * LDS + c];
                size_t idx = (size_t)(bm + row) * 64 + (c & 63);
                if (c < 64) g_qh[idx] = __float2half_rn(val);
                else        g_kh[idx] = __float2half_rn(val);
            }
        }
        return;
    }

    float* CfB = (OUTM != 2) ? Cf + (long long)blockIdx.z * sC : nullptr;
    __half* ChB = (OUTM == 2) ? Ch + (long long)blockIdx.z * sC : nullptr;
#pragma unroll
    for (int mt = 0; mt < 2; mt++) {
        int row0 = bm + m0w + mt * 16 + (lane >> 2);
#pragma unroll
        for (int nt = 0; nt < 4; nt++) {
            int col = bn + n0w + nt * 8 + (lane & 3) * 2;
            float* c = acc[mt][nt];
#pragma unroll
            for (int half = 0; half < 2; half++) {
                int row = row0 + half * 8;
                float v0 = c[half * 2], v1 = c[half * 2 + 1];
                if (OUTM == 2) {
                    if (col + 1 < N)
                        *reinterpret_cast<__half2*>(ChB + (size_t)row * ldc + col) =
                            __floats2half2_rn(v0, v1);
                } else {
                    float* Crow = CfB + (size_t)row * ldc;
                    if (col + 1 < N) {
                        float2 cv;
                        if (OUTM == 1) {
                            cv = *reinterpret_cast<float2*>(Crow + col);
                            cv.x += v0; cv.y += v1;
                        } else cv = make_float2(v0, v1);
                        *reinterpret_cast<float2*>(Crow + col) = cv;
                    } else if (col < N) {
                        Crow[col] = (OUTM == 1) ? (Crow[col] + v0) : v0;
                    }
                }
            }
        }
    }
}

template <int OUTM>
static inline void gemm_bf_launch(const __half* Ah, int lda, long long sA,
                                  const __half* Bh, int ldb, long long sB,
                                  float* Cf, __half* Ch,
                                  int ldc, long long sC,
                                  int M, int N, int K, int batch) {
    dim3 grid((N + 127) / 128, M / 128, batch);
    cudaFuncSetAttribute(gemm_bf<OUTM>, cudaFuncAttributeMaxDynamicSharedMemorySize, SHM_BF);
    gemm_bf<OUTM><<<grid, NTHR, SHM_BF>>>(Ah, lda, sA, Bh, ldb, sB,
                                          Cf, Ch, ldc, sC, N, K);
}

// ================= flash attention: scores + online softmax + P@V =========
// CTA = (d-slice ns of 128, query block qb of 128, batch). 512 threads,
// 16 warps 4Mx4N. K/V double-buffered with 1-iteration cp.async prefetch.
// smem: stats 5632 + Q 16K + P 32K + 2 x (K 16K + V 32K) = 149 KB.
#define FLASH_SHM (5632 + 9 * 16384)

__global__ void __launch_bounds__(512, 1)
flash_kernel(const __half* __restrict__ qh, const __half* __restrict__ kh,
             const __half* __restrict__ vt, __half* __restrict__ cat) {
    int ns = blockIdx.x;                              // 0..2  (d slice)
    int qb = (int)gridDim.y - 1 - (int)blockIdx.y;    // biggest-K first
    int b  = blockIdx.z;

    extern __shared__ char dsm[];
    float* fm   = reinterpret_cast<float*>(dsm);      // [128] running max
    float* fl   = fm + 128;                           // [128] running sum
    float* fsc  = fl + 128;                           // [128] rescale factor
    float* fpmx = fsc + 128;                          // [4][128]
    float* fpsm = fpmx + 512;                         // [4][128]
    char*  tile = dsm + 5632;                         // 128B aligned
    uint32_t sQ  = s2u(tile);
    uint32_t sP0 = sQ + 16384, sP1 = sP0 + 16384;
    char* tP0 = tile + 16384;
    char* tP1 = tile + 2 * 16384;
    // double-buffered K/V: buf i at sKV[i] = {K 16K, V0 16K, V1 16K}
    uint32_t sKV0 = sP1 + 16384;
    uint32_t sKV1 = sKV0 + 3 * 16384;

    int tid = threadIdx.x;
    int wid = tid >> 5, lane = tid & 31;
    int m0w = (wid >> 2) * 32, n0w = (wid & 3) * 32;

    uint32_t a_row  = (uint32_t)(lane & 15);
    uint32_t a_colb = (uint32_t)((lane >> 4) * 16);
    uint32_t b_row  = (uint32_t)(((lane >> 4) << 3) + (lane & 7));
    uint32_t b_colb = (uint32_t)(((lane >> 3) & 1) * 16);

    float oacc[2][4][4];
#pragma unroll
    for (int i = 0; i < 2; i++)
#pragma unroll
        for (int j = 0; j < 4; j++)
#pragma unroll
            for (int e = 0; e < 4; e++) oacc[i][j][e] = 0.0f;
    if (tid < 128) { fm[tid] = -1.0e30f; fl[tid] = 0.0f; }

    auto load_kv = [&](int kb, int bufsel) {
        uint32_t kB = bufsel ? sKV1 : sKV0;
        const __half* kbase = kh + ((size_t)b * Sq + (size_t)kb * 128) * 64;
#pragma unroll
        for (int i = 0; i < 2; i++) {
            int u = tid + i * 512;
            int row = u >> 3, cu = u & 7;
            cpa16(kB + swz((uint32_t)row * 128u + (uint32_t)cu * 16u),
                  kbase + (size_t)row * 64 + cu * 8, 16u);
        }
        const __half* vbase = vt + ((size_t)b * Dd + (size_t)ns * 128) * Sq + kb * 128;
#pragma unroll
        for (int i = 0; i < 4; i++) {
            int u = tid + i * 512;
            int chunk = u >> 10;
            int uu = u & 1023;
            int row = uu >> 3, cu = uu & 7;
            cpa16(kB + 16384 + (uint32_t)chunk * 16384u +
                      swz((uint32_t)row * 128u + (uint32_t)cu * 16u),
                  vbase + (size_t)row * Sq + chunk * 64 + cu * 8, 16u);
        }
    };

    // group 0: Q tile + K/V(0)
    {
        const __half* qbase = qh + ((size_t)b * Sq + (size_t)qb * 128) * 64;
#pragma unroll
        for (int i = 0; i < 2; i++) {
            int u = tid + i * 512;
            int row = u >> 3, cu = u & 7;
            cpa16(sQ + swz((uint32_t)row * 128u + (uint32_t)cu * 16u),
                  qbase + (size_t)row * 64 + cu * 8, 16u);
        }
        load_kv(0, 0);
        cpa_commit();
    }

    for (int kb = 0; kb <= qb; kb++) {
        int bsel = kb & 1;
        uint32_t sK  = bsel ? sKV1 : sKV0;
        uint32_t sV0 = sK + 16384, sV1 = sK + 32768;

        if (kb < qb) {
            load_kv(kb + 1, bsel ^ 1);   // prefetch next K/V
            cpa_commit();
            cpa_wait<1>();
        } else {
            cpa_wait<0>();
        }
        __syncthreads();

        // ---- S = Q @ K^T (K=48 effective: padding cols 48..63 are zero) ----
        float sacc[2][4][4];
#pragma unroll
        for (int i = 0; i < 2; i++)
#pragma unroll
            for (int j = 0; j < 4; j++)
#pragma unroll
                for (int e = 0; e < 4; e++) sacc[i][j][e] = 0.0f;
#pragma unroll
        for (int ks = 0; ks < 3; ks++) {
            uint32_t kbyte = (uint32_t)ks * 32u;
            uint32_t af[2][4], bf[2][4];
#pragma unroll
            for (int mt = 0; mt < 2; mt++) {
                uint32_t rr = (uint32_t)(m0w + mt * 16) + a_row;
                ldm_x4(sQ + swz(rr * 128u + kbyte + a_colb), af[mt]);
            }
#pragma unroll
            for (int bt = 0; bt < 2; bt++) {
                uint32_t rr = (uint32_t)(n0w + bt * 16) + b_row;
                ldm_x4(sK + swz(rr * 128u + kbyte + b_colb), bf[bt]);
            }
#pragma unroll
            for (int mt = 0; mt < 2; mt++)
#pragma unroll
                for (int nt = 0; nt < 4; nt++)
                    mma16816(sacc[mt][nt], af[mt], &bf[nt >> 1][(nt & 1) * 2]);
        }

        // ---- causal mask on diagonal block ----
        if (kb == qb) {
#pragma unroll
            for (int mt = 0; mt < 2; mt++)
#pragma unroll
                for (int half = 0; half < 2; half++) {
                    int gr = m0w + mt * 16 + (lane >> 2) + half * 8;
#pragma unroll
                    for (int nt = 0; nt < 4; nt++)
#pragma unroll
                        for (int e = 0; e < 2; e++) {
                            int gc = n0w + nt * 8 + (lane & 3) * 2 + e;
                            if (gc > gr) sacc[mt][nt][half * 2 + e] = -3.0e38f;
                        }
                }
        }

        // ---- row max ----
#pragma unroll
        for (int mt = 0; mt < 2; mt++)
#pragma unroll
            for (int half = 0; half < 2; half++) {
                int row = m0w + mt * 16 + (lane >> 2) + half * 8;
                float r = -3.0e38f;
#pragma unroll
                for (int nt = 0; nt < 4; nt++) {
                    r = fmaxf(r, sacc[mt][nt][half * 2]);
                    r = fmaxf(r, sacc[mt][nt][half * 2 + 1]);
                }
                r = fmaxf(r, __shfl_xor_sync(0xffffffffu, r, 1));
                r = fmaxf(r, __shfl_xor_sync(0xffffffffu, r, 2));
                if ((lane & 3) == 0) fpmx[(wid & 3) * 128 + row] = r;
            }
        __syncthreads();
        if (tid < 128) {
            float mo = fm[tid];
            float mn = fmaxf(fmaxf(fpmx[tid], fpmx[128 + tid]),
                             fmaxf(fpmx[256 + tid], fpmx[384 + tid]));
            mn = fmaxf(mo, mn);
            float sc = __expf(mo - mn);
            fm[tid] = mn; fsc[tid] = sc; fl[tid] *= sc;
        }
        __syncthreads();

        // ---- exp, write P fp16 to smem, rescale out acc, row sums ----
#pragma unroll
        for (int mt = 0; mt < 2; mt++)
#pragma unroll
            for (int half = 0; half < 2; half++) {
                int row = m0w + mt * 16 + (lane >> 2) + half * 8;
                float mrow = fm[row], sc = fsc[row];
                float ps = 0.0f;
#pragma unroll
                for (int nt = 0; nt < 4; nt++) {
                    float p0 = __expf(sacc[mt][nt][half * 2]     - mrow);
                    float p1 = __expf(sacc[mt][nt][half * 2 + 1] - mrow);
                    ps += p0 + p1;
                    oacc[mt][nt][half * 2]     *= sc;
                    oacc[mt][nt][half * 2 + 1] *= sc;
                    int gc = n0w + nt * 8 + (lane & 3) * 2;
                    char* tp = (gc >= 64) ? tP1 : tP0;
                    *reinterpret_cast<__half2*>(
                        tp + swz((uint32_t)row * 128u + (uint32_t)(gc & 63) * 2u)) =
                        __floats2half2_rn(p0, p1);
                }
                ps += __shfl_xor_sync(0xffffffffu, ps, 1);
                ps += __shfl_xor_sync(0xffffffffu, ps, 2);
                if ((lane & 3) == 0) fpsm[(wid & 3) * 128 + row] = ps;
            }
        __syncthreads();
        if (tid < 128)
            fl[tid] += fpsm[tid] + fpsm[128 + tid] + fpsm[256 + tid] + fpsm[384 + tid];
        __syncthreads();

        // ---- out += P @ V (2 chunks of K=64) ----
#pragma unroll
        for (int c = 0; c < 2; c++) {
            uint32_t aB = c ? sP1 : sP0;
            uint32_t bB = c ? sV1 : sV0;
#pragma unroll
            for (int ks = 0; ks < 4; ks++) {
                uint32_t kbyte = (uint32_t)ks * 32u;
                uint32_t af[2][4], bf[2][4];
#pragma unroll
                for (int mt = 0; mt < 2; mt++) {
                    uint32_t rr = (uint32_t)(m0w + mt * 16) + a_row;
                    ldm_x4(aB + swz(rr * 128u + kbyte + a_colb), af[mt]);
                }
#pragma unroll
                for (int bt = 0; bt < 2; bt++) {
                    uint32_t rr = (uint32_t)(n0w + bt * 16) + b_row;
                    ldm_x4(bB + swz(rr * 128u + kbyte + b_colb), bf[bt]);
                }
#pragma unroll
                for (int mt = 0; mt < 2; mt++)
#pragma unroll
                    for (int nt = 0; nt < 4; nt++)
                        mma16816(oacc[mt][nt], af[mt], &bf[nt >> 1][(nt & 1) * 2]);
            }
        }
        __syncthreads();   // fences buf reuse: kb+2's load targets this buf
    }

    // ---- epilogue: normalize and store to cat[:, 384 + ns*128 ..] ----
#pragma unroll
    for (int mt = 0; mt < 2; mt++)
#pragma unroll
        for (int half = 0; half < 2; half++) {
            int row = m0w + mt * 16 + (lane >> 2) + half * 8;
            float inv = 1.0f / fl[row];
            size_t t = (size_t)b * Sq + (size_t)qb * 128 + row;
#pragma unroll
            for (int nt = 0; nt < 4; nt++) {
                float o0 = oacc[mt][nt][half * 2]     * inv;
                float o1 = oacc[mt][nt][half * 2 + 1] * inv;
                int gc = 384 + ns * 128 + n0w + nt * 8 + (lane & 3) * 2;
                *reinterpret_cast<__half2*>(cat + t * Ed + gc) = __floats2half2_rn(o0, o1);
            }
        }
}

// ---------------- reductions ----------------
__device__ __forceinline__ float warp_sum(float v) {
#pragma unroll
    for (int o = 16; o; o >>= 1) v += __shfl_xor_sync(0xffffffffu, v, o);
    return v;
}

// ---------------- permute + fp16-round expand weights ----------------
__global__ void permute_round_ew(const float* __restrict__ exp_w,
                                 __half* __restrict__ wout) {
    int rid = blockIdx.x;
    int blk = rid / HPERM, fp = rid % HPERM;
    int f = 0; bool valid; float scale = 1.0f;
    if (fp < 1536) {
        int j = fp >> 1;
        f = (fp & 1) ? (2 * QKd + Ed + j) : (2 * QKd + j);
        valid = true;
    } else if (fp < 1600) {
        int d = fp - 1536;
        valid = (d < QKd); f = d;
        scale = 0.14433756729740643f;
    } else {
        int d = fp - 1600;
        valid = (d < QKd); f = QKd + d;
    }
    int tx = threadIdx.x;
    float4 x = make_float4(0.f, 0.f, 0.f, 0.f);
    if (valid)
        x = reinterpret_cast<const float4*>(exp_w + ((size_t)blk * Hd + f) * Dd)[tx];
    size_t o = ((size_t)blk * HPERM + fp) * Dd + tx * 4;
    *reinterpret_cast<__half2*>(wout + o)     = __floats2half2_rn(x.x * scale, x.y * scale);
    *reinterpret_cast<__half2*>(wout + o + 2) = __floats2half2_rn(x.z * scale, x.w * scale);
}

// ---------------- proj weights: fp32 -> fp16 round ----------------
__global__ void round_w_kernel(const float4* __restrict__ src,
                               __half2* __restrict__ dst, int n4) {
    int i = blockIdx.x * 256 + threadIdx.x;
    if (i >= n4) return;
    float4 x = src[i];
    dst[2 * i]     = __floats2half2_rn(x.x, x.y);
    dst[2 * i + 1] = __floats2half2_rn(x.z, x.w);
}

// ---------------- embed (sin/cos) + LayerNorm (fp32 out) ----------------
__global__ void embed_ln_kernel(const int* __restrict__ q,
                                const float* __restrict__ freqs,
                                const float* __restrict__ g,
                                const float* __restrict__ b,
                                float* __restrict__ y) {
    int t = blockIdx.x;
    int tid = threadIdx.x;
    float qv = (float)q[t];
    float v[3];
#pragma unroll
    for (int k = 0; k < 3; k++) {
        int d = tid + k * 128;
        if (d < Dd / 2) v[k] = sinf(qv * freqs[d]);
        else            v[k] = cosf(qv * freqs[d - Dd / 2]);
    }
    float s = v[0] + v[1] + v[2];
    float sq = v[0]*v[0] + v[1]*v[1] + v[2]*v[2];
    s = warp_sum(s); sq = warp_sum(sq);
    __shared__ float shs[4], shq[4], mr[2];
    if ((tid & 31) == 0) { shs[tid >> 5] = s; shq[tid >> 5] = sq; }
    __syncthreads();
    if (tid == 0) {
        float ts = shs[0]+shs[1]+shs[2]+shs[3], tq = shq[0]+shq[1]+shq[2]+shq[3];
        float mean = ts * (1.0f / Dd);
        float var  = tq * (1.0f / Dd) - mean * mean;
        mr[0] = mean; mr[1] = rsqrtf(var + 1e-5f);
    }
    __syncthreads();
    float mean = mr[0], rstd = mr[1];
    float* yr = y + (size_t)t * Dd;
#pragma unroll
    for (int k = 0; k < 3; k++) {
        int d = tid + k * 128;
        yr[d] = (v[k] - mean) * rstd * g[d] + b[d];
    }
}

// ---------------- LayerNorm, fp32 out (final LN) ----------------
__global__ void ln_kernel(const float* __restrict__ x, float* __restrict__ y,
                          const float* __restrict__ g, const float* __restrict__ b) {
    int t = blockIdx.x;
    int tid = threadIdx.x;
    const float* xr = x + (size_t)t * Dd;
    float v0 = xr[tid], v1 = xr[tid + 128], v2 = xr[tid + 256];
    float s  = v0 + v1 + v2;
    float sq = v0*v0 + v1*v1 + v2*v2;
    s = warp_sum(s); sq = warp_sum(sq);
    __shared__ float shs[4], shq[4], mr[2];
    if ((tid & 31) == 0) { shs[tid >> 5] = s; shq[tid >> 5] = sq; }
    __syncthreads();
    if (tid == 0) {
        float ts = shs[0]+shs[1]+shs[2]+shs[3], tq = shq[0]+shq[1]+shq[2]+shq[3];
        float mean = ts * (1.0f / Dd);
        float var  = tq * (1.0f / Dd) - mean * mean;
        mr[0] = mean; mr[1] = rsqrtf(var + 1e-5f);
    }
    __syncthreads();
    float mean = mr[0], rstd = mr[1];
    float* yr = y + (size_t)t * Dd;
    yr[tid]       = (v0 - mean) * rstd * g[tid]       + b[tid];
    yr[tid + 128] = (v1 - mean) * rstd * g[tid + 128] + b[tid + 128];
    yr[tid + 256] = (v2 - mean) * rstd * g[tid + 256] + b[tid + 256];
}

// ---------------- LayerNorm, fp16 out (per-block LN) ----------------
__global__ void ln_f16_kernel(const float* __restrict__ x,
                              __half* __restrict__ yh,
                              const float* __restrict__ g,
                              const float* __restrict__ b) {
    int t = blockIdx.x;
    int tid = threadIdx.x;
    const float* xr = x + (size_t)t * Dd;
    float v0 = xr[tid], v1 = xr[tid + 128], v2 = xr[tid + 256];
    float s  = v0 + v1 + v2;
    float sq = v0*v0 + v1*v1 + v2*v2;
    s = warp_sum(s); sq = warp_sum(sq);
    __shared__ float shs[4], shq[4], mr[2];
    if ((tid & 31) == 0) { shs[tid >> 5] = s; shq[tid >> 5] = sq; }
    __syncthreads();
    if (tid == 0) {
        float ts = shs[0]+shs[1]+shs[2]+shs[3], tq = shq[0]+shq[1]+shq[2]+shq[3];
        float mean = ts * (1.0f / Dd);
        float var  = tq * (1.0f / Dd) - mean * mean;
        mr[0] = mean; mr[1] = rsqrtf(var + 1e-5f);
    }
    __syncthreads();
    float mean = mr[0], rstd = mr[1];
    size_t rb = (size_t)t * Dd;
#pragma unroll
    for (int k = 0; k < 3; k++) {
        int d = tid + k * 128;
        float vv = (k == 0 ? v0 : (k == 1 ? v1 : v2));
        float y = (vv - mean) * rstd * g[d] + b[d];
        yh[rb + d] = __float2half_rn(y);
    }
}

// ---------------- SIMT SGEMM (logits only) ----------------
__global__ void __launch_bounds__(256, 2)
gemm_simt(const float* __restrict__ A, int lda,
          const float* __restrict__ B, int ldb,
          float* __restrict__ C, int ldc, int N, int K) {
    int bm = blockIdx.y * 128;
    int bn = blockIdx.x * 128;

    __shared__ float As[8][128];
    __shared__ float Bs[8][128];
    int tid = threadIdx.x;
    int tx = tid & 15, ty = tid >> 4;
    float acc[8][8] = {};

    int lrow = tid >> 1;
    int lkk  = (tid & 1) * 4;
    const float* Ap = A + (size_t)(bm + lrow) * lda + lkk;
    bool bvalid = (bn + lrow) < N;
    const float* Bp = B + (size_t)(bn + lrow) * ldb + lkk;

    for (int k0 = 0; k0 < K; k0 += 8) {
        float4 av = *reinterpret_cast<const float4*>(Ap + k0);
        float4 bv = bvalid ? *reinterpret_cast<const float4*>(Bp + k0)
                           : make_float4(0.f, 0.f, 0.f, 0.f);
        As[lkk+0][lrow]=av.x; As[lkk+1][lrow]=av.y; As[lkk+2][lrow]=av.z; As[lkk+3][lrow]=av.w;
        Bs[lkk+0][lrow]=bv.x; Bs[lkk+1][lrow]=bv.y; Bs[lkk+2][lrow]=bv.z; Bs[lkk+3][lrow]=bv.w;
        __syncthreads();
#pragma unroll
        for (int kk = 0; kk < 8; kk++) {
            float a[8], b[8];
            *reinterpret_cast<float4*>(&a[0]) = *reinterpret_cast<const float4*>(&As[kk][ty*8]);
            *reinterpret_cast<float4*>(&a[4]) = *reinterpret_cast<const float4*>(&As[kk][ty*8+4]);
            *reinterpret_cast<float4*>(&b[0]) = *reinterpret_cast<const float4*>(&Bs[kk][tx*8]);
            *reinterpret_cast<float4*>(&b[4]) = *reinterpret_cast<const float4*>(&Bs[kk][tx*8+4]);
#pragma unroll
            for (int i = 0; i < 8; i++)
#pragma unroll
                for (int j = 0; j < 8; j++)
                    acc[i][j] += a[i] * b[j];
        }
        __syncthreads();
    }
#pragma unroll
    for (int i = 0; i < 8; i++) {
        float* Crow = C + (size_t)(bm + ty * 8 + i) * ldc;
#pragma unroll
        for (int j = 0; j < 8; j++) {
            int n = bn + tx * 8 + j;
            if (n < N) Crow[n] = acc[i][j];
        }
    }
}

// ---------------- driver ----------------
extern "C" void kernel_launch(void* const* d_in, const int* in_sizes, int n_in,
                              void* d_out, int out_size) {
    const int*   q      = (const int*)  d_in[0];
    const float* freqs  = (const float*)d_in[1];
    const float* exp_w  = (const float*)d_in[2];
    const float* proj_w = (const float*)d_in[3];
    const float* blk_g  = (const float*)d_in[4];
    const float* blk_b  = (const float*)d_in[5];
    const float* ln_g   = (const float*)d_in[6];
    const float* ln_b   = (const float*)d_in[7];
    const float* out_w  = (const float*)d_in[8];
    float* out = (float*)d_out;

    float *x, *xn;
    __half *xnh, *cat, *vt, *qh, *kh, *ew, *pw;
    cudaGetSymbolAddress((void**)&x,   g_x);
    cudaGetSymbolAddress((void**)&xn,  g_xn);
    cudaGetSymbolAddress((void**)&xnh, g_xnh);
    cudaGetSymbolAddress((void**)&cat, g_cat);
    cudaGetSymbolAddress((void**)&vt,  g_vt);
    cudaGetSymbolAddress((void**)&qh,  g_qh);
    cudaGetSymbolAddress((void**)&kh,  g_kh);
    cudaGetSymbolAddress((void**)&ew,  g_ew);
    cudaGetSymbolAddress((void**)&pw,  g_pw);

    permute_round_ew<<<NBq * HPERM, 96>>>(exp_w, ew);
    {
        int n4p = NBq * Dd * Ed / 4;
        round_w_kernel<<<(n4p + 255) / 256, 256>>>(
            (const float4*)proj_w, (__half2*)pw, n4p);
    }

    embed_ln_kernel<<<Tq, 128>>>(q, freqs, ln_g, ln_b, x);

    cudaFuncSetAttribute(flash_kernel, cudaFuncAttributeMaxDynamicSharedMemorySize, FLASH_SHM);

    for (int blk = 0; blk < NBq; blk++) {
        ln_f16_kernel<<<Tq, 128>>>(x, xnh, blk_g + blk * Dd, blk_b + blk * Dd);

        // expand GEMM with fused geglu / qk-split / V^T epilogue
        gemm_bf_launch<3>(xnh, Dd, 0,
                          ew + (size_t)blk * HPERM * Dd, Dd, 0,
                          nullptr, nullptr, 0, 0,
                          Tq, HPERM, Dd, 1);

        // fused attention: scores + online softmax + P@V -> cat[:, 384:768]
        flash_kernel<<<dim3(3, Sq / 128, Bq), 512, FLASH_SHM>>>(qh, kh, vt, cat);

        // x += cat @ proj_w[blk]^T
        gemm_bf_launch<1>(cat, Ed, 0,
                          pw + (size_t)blk * Dd * Ed, Ed, 0,
                          x, nullptr, Dd, 0,
                          Tq, Dd, Ed, 1);
    }

    ln_kernel<<<Tq, 128>>>(x, xn, ln_g, ln_b);
    gemm_simt<<<dim3(1, Tq / 128), 256>>>(xn, Dd, out_w, Dd, out, VOCABq, VOCABq, Dd);
}